// round 6
// baseline (speedup 1.0000x reference)
#include <cuda_runtime.h>
#include <cstdint>

// Problem constants
#define BATCH 2
#define SEQ   2048
#define CDIM  2048
#define NHEAD 16
#define HDIM  128
#define C3    (3*CDIM)          // 6144
#define MROWS (BATCH*SEQ)       // 4096
static __device__ __constant__ float kScale = 0.08838834764831845f; // 1/sqrt(128)

// Scratch (device globals: allocation-free)
__device__ float g_qkv[(size_t)BATCH*SEQ*C3];    // [B,T,3C]
__device__ float g_y  [(size_t)BATCH*SEQ*CDIM];  // [B,T,C] (tf32-rounded by attn)
__device__ float g_xr [(size_t)BATCH*SEQ*CDIM];  // tf32-rounded copy of x
__device__ float g_vt [(size_t)BATCH*NHEAD*HDIM*SEQ]; // V transposed [b,h,d,t], tf32
__device__ float g_WtQkv[(size_t)C3*CDIM];       // [3C][C]  W_qkv^T, tf32-rounded
__device__ float g_WtProj[(size_t)CDIM*CDIM];    // [C][C]   W_proj^T, tf32-rounded

// ============================================================================
// helpers
// ============================================================================
__device__ __forceinline__ uint32_t smem_to_u32(const void* p) {
    uint32_t a;
    asm("{ .reg .u64 t; cvta.to.shared.u64 t, %1; cvt.u32.u64 %0, t; }" : "=r"(a) : "l"(p));
    return a;
}
__device__ __forceinline__ float to_tf32(float x) {
    float r;
    asm("cvt.rna.tf32.f32 %0, %1;" : "=f"(r) : "f"(x));
    return r;
}
__device__ __forceinline__ void cp_async16(uint32_t saddr, const void* g) {
    asm volatile("cp.async.cg.shared.global [%0], [%1], 16;" :: "r"(saddr), "l"(g));
}
#define CP_COMMIT() asm volatile("cp.async.commit_group;" ::: "memory")
#define CP_WAIT(n)  asm volatile("cp.async.wait_group %0;" :: "n"(n) : "memory")

__device__ __forceinline__ void mma_tf32(
    float& c0, float& c1, float& c2, float& c3,
    uint32_t a0, uint32_t a1, uint32_t a2, uint32_t a3,
    uint32_t b0, uint32_t b1)
{
    asm volatile(
        "mma.sync.aligned.m16n8k8.row.col.f32.tf32.tf32.f32 "
        "{%0,%1,%2,%3}, {%4,%5,%6,%7}, {%8,%9}, {%0,%1,%2,%3};"
        : "+f"(c0), "+f"(c1), "+f"(c2), "+f"(c3)
        : "r"(a0), "r"(a1), "r"(a2), "r"(a3), "r"(b0), "r"(b1));
}

// ============================================================================
// round fp32 -> tf32 (float4 vectorized)
// ============================================================================
__global__ __launch_bounds__(256) void round_tf32_kernel(
    const float* __restrict__ in, float* __restrict__ out, int n4)
{
    int i = blockIdx.x * blockDim.x + threadIdx.x;
    if (i < n4) {
        float4 v = ((const float4*)in)[i];
        v.x = to_tf32(v.x); v.y = to_tf32(v.y);
        v.z = to_tf32(v.z); v.w = to_tf32(v.w);
        ((float4*)out)[i] = v;
    }
}

// ============================================================================
// Transpose + tf32 round: out[C][R] = tf32(in[R][C])
// ============================================================================
__global__ __launch_bounds__(256) void transpose_k(
    const float* __restrict__ in, float* __restrict__ out, int R, int C)
{
    __shared__ float t[32][33];
    int bx = blockIdx.x * 32, by = blockIdx.y * 32;
    int tx = threadIdx.x, ty = threadIdx.y;
    #pragma unroll
    for (int j = ty; j < 32; j += 8)
        t[j][tx] = in[(size_t)(by + j) * C + bx + tx];
    __syncthreads();
    #pragma unroll
    for (int j = ty; j < 32; j += 8)
        out[(size_t)(bx + j) * R + by + tx] = to_tf32(t[tx][j]);
}

// ============================================================================
// Transpose V head slabs: g_vt[(b*H+h)*D + d][t] = tf32(qkv_v[b,t,h,d])
// grid (SEQ/32, HDIM/32, B*NHEAD), block (32,8)
// ============================================================================
__global__ __launch_bounds__(256) void transpose_vt(
    const float* __restrict__ qkv, float* __restrict__ vt)
{
    __shared__ float t[32][33];
    int bh = blockIdx.z;
    int b = bh >> 4, h = bh & 15;
    const float* src = qkv + (size_t)b * SEQ * C3 + 2 * CDIM + h * HDIM;
    float* dst = vt + (size_t)bh * HDIM * SEQ;
    int t0 = blockIdx.x * 32, d0 = blockIdx.y * 32;
    int tx = threadIdx.x, ty = threadIdx.y;
    #pragma unroll
    for (int j = ty; j < 32; j += 8)
        t[j][tx] = src[(size_t)(t0 + j) * C3 + d0 + tx];
    __syncthreads();
    #pragma unroll
    for (int j = ty; j < 32; j += 8)
        dst[(size_t)(d0 + j) * SEQ + t0 + tx] = to_tf32(t[tx][j]);
}

// ============================================================================
// TF32 mma.sync GEMM: C[M,N] = A[M,K] @ Bt[N,K]^T
// 128x128 CTA tile, K chunk 32, 3-stage cp.async pipeline (1 barrier/chunk).
// ============================================================================
#define GK   32
#define LDS_STRIDE 36
#define TILE_FLOATS (128 * LDS_STRIDE)          // 4608
#define BUF_FLOATS  (2 * TILE_FLOATS)           // 9216 (A+B per stage)
#define GSTAGES 3
#define GSMEM_BYTES (GSTAGES * BUF_FLOATS * 4)  // 110592

__global__ __launch_bounds__(256, 2) void gemm_tf32mma(
    const float* __restrict__ A, const float* __restrict__ Bt,
    float* __restrict__ C, int M, int N, int K)
{
    extern __shared__ float sm[];
    const int tid = threadIdx.x;
    const int wid = tid >> 5;
    const int lid = tid & 31;
    const int wm  = wid & 1;
    const int wn  = wid >> 1;
    const int m0  = blockIdx.y * 128;
    const int n0  = blockIdx.x * 128;

    const uint32_t smem_u32 = smem_to_u32(sm);

    float acc[4][4][4];
    #pragma unroll
    for (int i = 0; i < 4; i++)
        #pragma unroll
        for (int j = 0; j < 4; j++)
            #pragma unroll
            for (int u = 0; u < 4; u++) acc[i][j][u] = 0.f;

    const int nchunk = K / GK;

    auto issue = [&](int c) {
        const int s = c % GSTAGES;
        const float* Ag = A  + (size_t)m0 * K + c * GK;
        const float* Bg = Bt + (size_t)n0 * K + c * GK;
        uint32_t baseA = smem_u32 + (uint32_t)(s * BUF_FLOATS) * 4u;
        uint32_t baseB = baseA + (uint32_t)TILE_FLOATS * 4u;
        #pragma unroll
        for (int i = 0; i < 4; i++) {
            int f   = tid + i * 256;
            int row = f >> 3;
            int q   = f & 7;
            uint32_t soff = (uint32_t)(row * LDS_STRIDE + q * 4) * 4u;
            cp_async16(baseA + soff, Ag + (size_t)row * K + q * 4);
            cp_async16(baseB + soff, Bg + (size_t)row * K + q * 4);
        }
    };

    issue(0); CP_COMMIT();
    issue(1); CP_COMMIT();

    for (int c = 0; c < nchunk; c++) {
        if (c + 1 < nchunk) { CP_WAIT(1); } else { CP_WAIT(0); }
        __syncthreads();
        if (c + 2 < nchunk) { issue(c + 2); CP_COMMIT(); }

        const float* As = sm + (c % GSTAGES) * BUF_FLOATS;
        const float* Bs = As + TILE_FLOATS;
        const int r4 = lid >> 2;
        const int c4 = lid & 3;

        #pragma unroll
        for (int kk = 0; kk < 4; kk++) {
            uint32_t a[4][4], b[4][2];
            #pragma unroll
            for (int mt = 0; mt < 4; mt++) {
                int rb = wm * 64 + mt * 16;
                int kb = kk * 8;
                a[mt][0] = __float_as_uint(As[(rb + r4)     * LDS_STRIDE + kb + c4]);
                a[mt][1] = __float_as_uint(As[(rb + 8 + r4) * LDS_STRIDE + kb + c4]);
                a[mt][2] = __float_as_uint(As[(rb + r4)     * LDS_STRIDE + kb + 4 + c4]);
                a[mt][3] = __float_as_uint(As[(rb + 8 + r4) * LDS_STRIDE + kb + 4 + c4]);
            }
            #pragma unroll
            for (int nt = 0; nt < 4; nt++) {
                int nb = wn * 32 + nt * 8;
                int kb = kk * 8;
                b[nt][0] = __float_as_uint(Bs[(nb + r4) * LDS_STRIDE + kb + c4]);
                b[nt][1] = __float_as_uint(Bs[(nb + r4) * LDS_STRIDE + kb + 4 + c4]);
            }
            #pragma unroll
            for (int mt = 0; mt < 4; mt++)
                #pragma unroll
                for (int nt = 0; nt < 4; nt++)
                    mma_tf32(acc[mt][nt][0], acc[mt][nt][1], acc[mt][nt][2], acc[mt][nt][3],
                             a[mt][0], a[mt][1], a[mt][2], a[mt][3],
                             b[nt][0], b[nt][1]);
        }
    }

    const int r4 = lid >> 2;
    const int c2l = 2 * (lid & 3);
    #pragma unroll
    for (int mt = 0; mt < 4; mt++) {
        int row = m0 + wm * 64 + mt * 16 + r4;
        #pragma unroll
        for (int nt = 0; nt < 4; nt++) {
            int col = n0 + wn * 32 + nt * 8 + c2l;
            *(float2*)(C + (size_t)row * N + col) =
                make_float2(acc[mt][nt][0], acc[mt][nt][1]);
            *(float2*)(C + (size_t)(row + 8) * N + col) =
                make_float2(acc[mt][nt][2], acc[mt][nt][3]);
        }
    }
}

// ---------------------------------------------------------------------------
// RoPE (float4 vectorized, in-place on g_qkv q,k). Folds 1/sqrt(d) into q,
// rounds to tf32.  One thread per (b,t,qk,h, d4<16).
// ---------------------------------------------------------------------------
__global__ __launch_bounds__(256) void rope_kernel(
    float* __restrict__ qkv, const float* __restrict__ cosp,
    const float* __restrict__ sinp)
{
    int idx = blockIdx.x * blockDim.x + threadIdx.x;
    int d4 = idx & 15;               // float4 index in lower half (d = d4*4, <64)
    int h  = (idx >> 4) & (NHEAD - 1);
    int qk = (idx >> 8) & 1;
    int t  = (idx >> 9) & (SEQ - 1);
    int b  = idx >> 20;
    int d  = d4 * 4;

    float* base = qkv + ((size_t)(b * SEQ + t)) * C3 + qk * CDIM + h * HDIM;
    float4 x1 = *(float4*)(base + d);
    float4 x2 = *(float4*)(base + d + 64);
    float4 c1 = *(const float4*)(cosp + t * HDIM + d);
    float4 s1 = *(const float4*)(sinp + t * HDIM + d);
    float4 c2 = *(const float4*)(cosp + t * HDIM + d + 64);
    float4 s2 = *(const float4*)(sinp + t * HDIM + d + 64);

    float sc = (qk == 0) ? kScale : 1.f;
    float4 o1, o2;
    o1.x = to_tf32((x1.x * c1.x - x2.x * s1.x) * sc);
    o1.y = to_tf32((x1.y * c1.y - x2.y * s1.y) * sc);
    o1.z = to_tf32((x1.z * c1.z - x2.z * s1.z) * sc);
    o1.w = to_tf32((x1.w * c1.w - x2.w * s1.w) * sc);
    o2.x = to_tf32((x2.x * c2.x + x1.x * s2.x) * sc);
    o2.y = to_tf32((x2.y * c2.y + x1.y * s2.y) * sc);
    o2.z = to_tf32((x2.z * c2.z + x1.z * s2.z) * sc);
    o2.w = to_tf32((x2.w * c2.w + x1.w * s2.w) * sc);
    *(float4*)(base + d)      = o1;
    *(float4*)(base + d + 64) = o2;
}

// ---------------------------------------------------------------------------
// Flash attention v2: BM=128, BN=64, D=128, tf32 mma.sync.
// cp.async double-buffered K/Vt tiles; P kept in registers (shuffle to
// A-fragment layout, no smem staging).
// ---------------------------------------------------------------------------
#define ABM 128
#define ABN 64
#define QS_STRIDE 132
#define KS_STRIDE 132
#define VS_STRIDE 68
#define QS_FLOATS (128*QS_STRIDE)                 // 16896
#define KT_FLOATS (64*KS_STRIDE)                  // 8448
#define VT_FLOATS (128*VS_STRIDE)                 // 8704
#define STG_FLOATS (KT_FLOATS + VT_FLOATS)        // 17152
#define ATTN_SMEM_BYTES ((QS_FLOATS + 2*STG_FLOATS) * 4)   // 204800

__global__ __launch_bounds__(256, 1) void attn_mma_kernel(
    const float* __restrict__ qkv, const float* __restrict__ vt,
    float* __restrict__ y)
{
    extern __shared__ float sm[];
    float* Qs = sm;                               // [128][132]

    const int tid = threadIdx.x;
    const int wid = tid >> 5;
    const int lid = tid & 31;
    const int r4  = lid >> 2;       // 0..7
    const int c4  = lid & 3;        // 0..3
    const int h   = blockIdx.y;
    const int b   = blockIdx.z;
    const int t0  = blockIdx.x * ABM;
    const int mrow = wid * 16;

    const uint32_t smem_u32 = smem_to_u32(sm);

    const size_t base = ((size_t)b * SEQ) * C3 + (size_t)h * HDIM;
    const float* Qg  = qkv + base;                 // roped, scaled, tf32
    const float* Kg  = Qg + CDIM;                  // roped, tf32
    const float* Vtg = vt + (size_t)(b * NHEAD + h) * HDIM * SEQ; // tf32

    // prologue: Q tile via cp.async (group 0)
    #pragma unroll
    for (int i = 0; i < 16; i++) {
        int f = tid + i * 256;         // 0..4095
        int r = f >> 5, q = f & 31;
        cp_async16(smem_u32 + (uint32_t)(r * QS_STRIDE + q * 4) * 4u,
                   Qg + (size_t)(t0 + r) * C3 + q * 4);
    }
    CP_COMMIT();

    auto issue_tile = [&](int kt) {
        const int s = kt & 1;
        const int s0 = kt * ABN;
        uint32_t kbase = smem_u32 + (uint32_t)(QS_FLOATS + s * STG_FLOATS) * 4u;
        uint32_t vbase = kbase + (uint32_t)KT_FLOATS * 4u;
        #pragma unroll
        for (int i = 0; i < 8; i++) {
            int f = tid + i * 256;     // 0..2047
            int r = f >> 5, q = f & 31;
            cp_async16(kbase + (uint32_t)(r * KS_STRIDE + q * 4) * 4u,
                       Kg + (size_t)(s0 + r) * C3 + q * 4);
        }
        #pragma unroll
        for (int i = 0; i < 8; i++) {
            int f = tid + i * 256;     // 0..2047
            int d = f >> 4, q = f & 15;
            cp_async16(vbase + (uint32_t)(d * VS_STRIDE + q * 4) * 4u,
                       Vtg + (size_t)d * SEQ + s0 + q * 4);
        }
    };

    issue_tile(0); CP_COMMIT();

    float Oa[16][4];
    #pragma unroll
    for (int nt = 0; nt < 16; nt++)
        Oa[nt][0] = Oa[nt][1] = Oa[nt][2] = Oa[nt][3] = 0.f;
    float m0 = -1e30f, m1 = -1e30f, l0 = 0.f, l1 = 0.f;

    const int NT = SEQ / ABN;   // 32
    for (int kt = 0; kt < NT; kt++) {
        __syncthreads();                       // stage (kt+1)&1 free for reuse
        if (kt + 1 < NT) { issue_tile(kt + 1); CP_COMMIT(); }
        if (kt + 1 < NT) { CP_WAIT(1); } else { CP_WAIT(0); }
        __syncthreads();                       // tile kt (and Q on kt=0) visible

        const float* Ks  = sm + QS_FLOATS + (kt & 1) * STG_FLOATS;
        const float* Vts = Ks + KT_FLOATS;

        // ---- S = Q @ K^T ----
        float P[8][4];
        #pragma unroll
        for (int nt = 0; nt < 8; nt++)
            P[nt][0] = P[nt][1] = P[nt][2] = P[nt][3] = 0.f;

        #pragma unroll
        for (int kk = 0; kk < 16; kk++) {
            const int kb = kk * 8;
            uint32_t a0 = __float_as_uint(Qs[(mrow + r4)     * QS_STRIDE + kb + c4]);
            uint32_t a1 = __float_as_uint(Qs[(mrow + 8 + r4) * QS_STRIDE + kb + c4]);
            uint32_t a2 = __float_as_uint(Qs[(mrow + r4)     * QS_STRIDE + kb + 4 + c4]);
            uint32_t a3 = __float_as_uint(Qs[(mrow + 8 + r4) * QS_STRIDE + kb + 4 + c4]);
            #pragma unroll
            for (int nt = 0; nt < 8; nt++) {
                uint32_t b0 = __float_as_uint(Ks[(nt * 8 + r4) * KS_STRIDE + kb + c4]);
                uint32_t b1 = __float_as_uint(Ks[(nt * 8 + r4) * KS_STRIDE + kb + 4 + c4]);
                mma_tf32(P[nt][0], P[nt][1], P[nt][2], P[nt][3],
                         a0, a1, a2, a3, b0, b1);
            }
        }

        // ---- online softmax (row0 = mrow+r4, row1 = +8; 4 lanes per row) ----
        float mx0 = -1e30f, mx1 = -1e30f;
        #pragma unroll
        for (int nt = 0; nt < 8; nt++) {
            mx0 = fmaxf(mx0, fmaxf(P[nt][0], P[nt][1]));
            mx1 = fmaxf(mx1, fmaxf(P[nt][2], P[nt][3]));
        }
        mx0 = fmaxf(mx0, __shfl_xor_sync(0xffffffffu, mx0, 1));
        mx0 = fmaxf(mx0, __shfl_xor_sync(0xffffffffu, mx0, 2));
        mx1 = fmaxf(mx1, __shfl_xor_sync(0xffffffffu, mx1, 1));
        mx1 = fmaxf(mx1, __shfl_xor_sync(0xffffffffu, mx1, 2));

        float mn0 = fmaxf(m0, mx0), mn1 = fmaxf(m1, mx1);
        float cr0 = __expf(m0 - mn0), cr1 = __expf(m1 - mn1);
        m0 = mn0; m1 = mn1;

        float s0s = 0.f, s1s = 0.f;
        #pragma unroll
        for (int nt = 0; nt < 8; nt++) {
            P[nt][0] = to_tf32(__expf(P[nt][0] - mn0));
            P[nt][1] = to_tf32(__expf(P[nt][1] - mn0));
            P[nt][2] = to_tf32(__expf(P[nt][2] - mn1));
            P[nt][3] = to_tf32(__expf(P[nt][3] - mn1));
            s0s += P[nt][0] + P[nt][1];
            s1s += P[nt][2] + P[nt][3];
        }
        s0s += __shfl_xor_sync(0xffffffffu, s0s, 1);
        s0s += __shfl_xor_sync(0xffffffffu, s0s, 2);
        s1s += __shfl_xor_sync(0xffffffffu, s1s, 1);
        s1s += __shfl_xor_sync(0xffffffffu, s1s, 2);
        l0 = l0 * cr0 + s0s;
        l1 = l1 * cr1 + s1s;

        #pragma unroll
        for (int nt = 0; nt < 16; nt++) {
            Oa[nt][0] *= cr0; Oa[nt][1] *= cr0;
            Oa[nt][2] *= cr1; Oa[nt][3] *= cr1;
        }

        // ---- O += P @ V : convert P C-fragment -> A-fragment via shuffles ----
        const int src0 = (lid & ~3) | (c4 >> 1);
        const int src1 = src0 + 2;
        const bool odd = (c4 & 1);
        #pragma unroll
        for (int j = 0; j < 8; j++) {
            float v00 = __shfl_sync(0xffffffffu, P[j][0], src0);
            float v01 = __shfl_sync(0xffffffffu, P[j][1], src0);
            float v02 = __shfl_sync(0xffffffffu, P[j][2], src0);
            float v03 = __shfl_sync(0xffffffffu, P[j][3], src0);
            float v10 = __shfl_sync(0xffffffffu, P[j][0], src1);
            float v11 = __shfl_sync(0xffffffffu, P[j][1], src1);
            float v12 = __shfl_sync(0xffffffffu, P[j][2], src1);
            float v13 = __shfl_sync(0xffffffffu, P[j][3], src1);
            uint32_t a0 = __float_as_uint(odd ? v01 : v00);  // (r4,   c4)
            uint32_t a1 = __float_as_uint(odd ? v03 : v02);  // (r4+8, c4)
            uint32_t a2 = __float_as_uint(odd ? v11 : v10);  // (r4,   c4+4)
            uint32_t a3 = __float_as_uint(odd ? v13 : v12);  // (r4+8, c4+4)
            const int kb = j * 8;
            #pragma unroll
            for (int nt = 0; nt < 16; nt++) {
                uint32_t b0 = __float_as_uint(Vts[(nt * 8 + r4) * VS_STRIDE + kb + c4]);
                uint32_t b1 = __float_as_uint(Vts[(nt * 8 + r4) * VS_STRIDE + kb + 4 + c4]);
                mma_tf32(Oa[nt][0], Oa[nt][1], Oa[nt][2], Oa[nt][3],
                         a0, a1, a2, a3, b0, b1);
            }
        }
    }

    // epilogue: tf32(O/l) -> y
    float inv0 = 1.f / l0, inv1 = 1.f / l1;
    int row0 = t0 + mrow + r4;
    int row1 = row0 + 8;
    float* y0 = y + ((size_t)b * SEQ + row0) * CDIM + h * HDIM;
    float* y1 = y + ((size_t)b * SEQ + row1) * CDIM + h * HDIM;
    #pragma unroll
    for (int nt = 0; nt < 16; nt++) {
        int col = nt * 8 + 2 * c4;
        *(float2*)(y0 + col) = make_float2(to_tf32(Oa[nt][0] * inv0),
                                           to_tf32(Oa[nt][1] * inv0));
        *(float2*)(y1 + col) = make_float2(to_tf32(Oa[nt][2] * inv1),
                                           to_tf32(Oa[nt][3] * inv1));
    }
}

// ---------------------------------------------------------------------------
extern "C" void kernel_launch(void* const* d_in, const int* in_sizes, int n_in,
                              void* d_out, int out_size)
{
    const float* x     = (const float*)d_in[0];
    const float* cosp  = (const float*)d_in[1];
    const float* sinp  = (const float*)d_in[2];
    const float* Wqkv  = (const float*)d_in[3];
    const float* Wproj = (const float*)d_in[4];
    float* out = (float*)d_out;

    float *qkv = nullptr, *y = nullptr, *xr = nullptr, *vt = nullptr;
    float *WtQkv = nullptr, *WtProj = nullptr;
    cudaGetSymbolAddress((void**)&qkv,    g_qkv);
    cudaGetSymbolAddress((void**)&y,      g_y);
    cudaGetSymbolAddress((void**)&xr,     g_xr);
    cudaGetSymbolAddress((void**)&vt,     g_vt);
    cudaGetSymbolAddress((void**)&WtQkv,  g_WtQkv);
    cudaGetSymbolAddress((void**)&WtProj, g_WtProj);

    cudaFuncSetAttribute(attn_mma_kernel, cudaFuncAttributeMaxDynamicSharedMemorySize, ATTN_SMEM_BYTES);
    cudaFuncSetAttribute(gemm_tf32mma,    cudaFuncAttributeMaxDynamicSharedMemorySize, GSMEM_BYTES);

    // 0) weights: transpose + tf32 round; x: tf32 round into scratch
    transpose_k<<<dim3(C3 / 32,   CDIM / 32), dim3(32, 8)>>>(Wqkv,  WtQkv,  CDIM, C3);
    transpose_k<<<dim3(CDIM / 32, CDIM / 32), dim3(32, 8)>>>(Wproj, WtProj, CDIM, CDIM);
    {
        int n4 = MROWS * CDIM / 4;
        round_tf32_kernel<<<(n4 + 255) / 256, 256>>>(x, xr, n4);
    }

    // 1) qkv = x @ W_qkv   (tf32 mma.sync, 3-stage pipeline)
    gemm_tf32mma<<<dim3(C3 / 128, MROWS / 128), 256, GSMEM_BYTES>>>(
        xr, WtQkv, qkv, MROWS, C3, CDIM);

    // 2) RoPE in place on q,k (+ tf32 round); build transposed tf32 V
    {
        int total = BATCH * SEQ * 2 * NHEAD * 16;
        rope_kernel<<<total / 256, 256>>>(qkv, cosp, sinp);
        transpose_vt<<<dim3(SEQ / 32, HDIM / 32, BATCH * NHEAD), dim3(32, 8)>>>(qkv, vt);
    }

    // 3) flash attention (tf32 mma, cp.async double-buffered) -> y [B,T,C]
    {
        dim3 grid(SEQ / ABM, NHEAD, BATCH);
        attn_mma_kernel<<<grid, 256, ATTN_SMEM_BYTES>>>(qkv, vt, y);
    }

    // 4) out = y @ W_proj  (tf32 mma.sync)
    gemm_tf32mma<<<dim3(CDIM / 128, MROWS / 128), 256, GSMEM_BYTES>>>(
        y, WtProj, out, MROWS, CDIM, CDIM);
}

// round 7
// speedup vs baseline: 1.4748x; 1.4748x over previous
#include <cuda_runtime.h>
#include <cstdint>

// Problem constants
#define BATCH 2
#define SEQ   2048
#define CDIM  2048
#define NHEAD 16
#define HDIM  128
#define C3    (3*CDIM)          // 6144
#define MROWS (BATCH*SEQ)       // 4096
static __device__ __constant__ float kScale = 0.08838834764831845f; // 1/sqrt(128)

// Scratch (device globals: allocation-free)
__device__ float g_qkv[(size_t)BATCH*SEQ*C3];    // [B,T,3C]
__device__ float g_y  [(size_t)BATCH*SEQ*CDIM];  // [B,T,C] (tf32-rounded by attn)
__device__ float g_xr [(size_t)BATCH*SEQ*CDIM];  // tf32-rounded copy of x
__device__ float g_vt [(size_t)BATCH*NHEAD*HDIM*SEQ]; // V transposed [b,h,d,t], tf32
__device__ float g_WtQkv[(size_t)C3*CDIM];       // [3C][C]  W_qkv^T, tf32-rounded
__device__ float g_WtProj[(size_t)CDIM*CDIM];    // [C][C]   W_proj^T, tf32-rounded

// ============================================================================
// helpers
// ============================================================================
__device__ __forceinline__ uint32_t smem_to_u32(const void* p) {
    uint32_t a;
    asm("{ .reg .u64 t; cvta.to.shared.u64 t, %1; cvt.u32.u64 %0, t; }" : "=r"(a) : "l"(p));
    return a;
}
__device__ __forceinline__ float to_tf32(float x) {
    float r;
    asm("cvt.rna.tf32.f32 %0, %1;" : "=f"(r) : "f"(x));
    return r;
}
__device__ __forceinline__ void cp_async16(uint32_t saddr, const void* g) {
    asm volatile("cp.async.cg.shared.global [%0], [%1], 16;" :: "r"(saddr), "l"(g));
}
#define CP_COMMIT() asm volatile("cp.async.commit_group;" ::: "memory")
#define CP_WAIT(n)  asm volatile("cp.async.wait_group %0;" :: "n"(n) : "memory")

__device__ __forceinline__ void mma_tf32(
    float& c0, float& c1, float& c2, float& c3,
    uint32_t a0, uint32_t a1, uint32_t a2, uint32_t a3,
    uint32_t b0, uint32_t b1)
{
    asm volatile(
        "mma.sync.aligned.m16n8k8.row.col.f32.tf32.tf32.f32 "
        "{%0,%1,%2,%3}, {%4,%5,%6,%7}, {%8,%9}, {%0,%1,%2,%3};"
        : "+f"(c0), "+f"(c1), "+f"(c2), "+f"(c3)
        : "r"(a0), "r"(a1), "r"(a2), "r"(a3), "r"(b0), "r"(b1));
}

// ============================================================================
// round fp32 -> tf32 (float4 vectorized)
// ============================================================================
__global__ __launch_bounds__(256) void round_tf32_kernel(
    const float* __restrict__ in, float* __restrict__ out, int n4)
{
    int i = blockIdx.x * blockDim.x + threadIdx.x;
    if (i < n4) {
        float4 v = ((const float4*)in)[i];
        v.x = to_tf32(v.x); v.y = to_tf32(v.y);
        v.z = to_tf32(v.z); v.w = to_tf32(v.w);
        ((float4*)out)[i] = v;
    }
}

// ============================================================================
// Transpose + tf32 round: out[C][R] = tf32(in[R][C])
// ============================================================================
__global__ __launch_bounds__(256) void transpose_k(
    const float* __restrict__ in, float* __restrict__ out, int R, int C)
{
    __shared__ float t[32][33];
    int bx = blockIdx.x * 32, by = blockIdx.y * 32;
    int tx = threadIdx.x, ty = threadIdx.y;
    #pragma unroll
    for (int j = ty; j < 32; j += 8)
        t[j][tx] = in[(size_t)(by + j) * C + bx + tx];
    __syncthreads();
    #pragma unroll
    for (int j = ty; j < 32; j += 8)
        out[(size_t)(bx + j) * R + by + tx] = to_tf32(t[tx][j]);
}

// ============================================================================
// Transpose V head slabs: g_vt[(b*H+h)*D + d][t] = tf32(qkv_v[b,t,h,d])
// ============================================================================
__global__ __launch_bounds__(256) void transpose_vt(
    const float* __restrict__ qkv, float* __restrict__ vt)
{
    __shared__ float t[32][33];
    int bh = blockIdx.z;
    int b = bh >> 4, h = bh & 15;
    const float* src = qkv + (size_t)b * SEQ * C3 + 2 * CDIM + h * HDIM;
    float* dst = vt + (size_t)bh * HDIM * SEQ;
    int t0 = blockIdx.x * 32, d0 = blockIdx.y * 32;
    int tx = threadIdx.x, ty = threadIdx.y;
    #pragma unroll
    for (int j = ty; j < 32; j += 8)
        t[j][tx] = src[(size_t)(t0 + j) * C3 + d0 + tx];
    __syncthreads();
    #pragma unroll
    for (int j = ty; j < 32; j += 8)
        dst[(size_t)(d0 + j) * SEQ + t0 + tx] = to_tf32(t[tx][j]);
}

// ============================================================================
// TF32 mma.sync GEMM: C[M,N] = A[M,K] @ Bt[N,K]^T
// 128x256 CTA tile, warp tile 64x64 (2Mx4N warps), K chunk 32,
// 2-stage cp.async double buffer (R5-proven ordering), 256 threads.
// ============================================================================
#define GK   32
#define GSTRIDE 36
#define A_TILE_FLOATS (128 * GSTRIDE)             // 4608
#define B_TILE_FLOATS (256 * GSTRIDE)             // 9216
#define STAGE_FLOATS  (A_TILE_FLOATS + B_TILE_FLOATS) // 13824
#define GSMEM_BYTES   (2 * STAGE_FLOATS * 4)      // 110592

__global__ __launch_bounds__(256, 1) void gemm_tf32mma(
    const float* __restrict__ A, const float* __restrict__ Bt,
    float* __restrict__ C, int M, int N, int K)
{
    extern __shared__ float sm[];
    const int tid = threadIdx.x;
    const int wid = tid >> 5;
    const int lid = tid & 31;
    const int wm  = wid & 1;        // 0..1  (64 M-rows each)
    const int wn  = wid >> 1;       // 0..3  (64 N-cols each)
    const int m0  = blockIdx.y * 128;
    const int n0  = blockIdx.x * 256;

    const uint32_t smem_u32 = smem_to_u32(sm);

    float acc[4][8][4];
    #pragma unroll
    for (int i = 0; i < 4; i++)
        #pragma unroll
        for (int j = 0; j < 8; j++)
            #pragma unroll
            for (int u = 0; u < 4; u++) acc[i][j][u] = 0.f;

    const int nchunk = K / GK;

    auto issue = [&](int c, int s) {
        const float* Ag = A  + (size_t)m0 * K + c * GK;
        const float* Bg = Bt + (size_t)n0 * K + c * GK;
        uint32_t baseA = smem_u32 + (uint32_t)(s * STAGE_FLOATS) * 4u;
        uint32_t baseB = baseA + (uint32_t)A_TILE_FLOATS * 4u;
        // A: 128 rows x 8 float4 = 1024 lines (4 per thread)
        #pragma unroll
        for (int i = 0; i < 4; i++) {
            int f   = tid + i * 256;
            int row = f >> 3;
            int q   = f & 7;
            uint32_t soff = (uint32_t)(row * GSTRIDE + q * 4) * 4u;
            cp_async16(baseA + soff, Ag + (size_t)row * K + q * 4);
        }
        // B: 256 rows x 8 float4 = 2048 lines (8 per thread)
        #pragma unroll
        for (int i = 0; i < 8; i++) {
            int f   = tid + i * 256;
            int row = f >> 3;
            int q   = f & 7;
            uint32_t soff = (uint32_t)(row * GSTRIDE + q * 4) * 4u;
            cp_async16(baseB + soff, Bg + (size_t)row * K + q * 4);
        }
    };

    issue(0, 0);
    CP_COMMIT();

    const int r4 = lid >> 2;
    const int c4 = lid & 3;

    for (int c = 0; c < nchunk; c++) {
        const int s = c & 1;
        if (c + 1 < nchunk) {
            issue(c + 1, s ^ 1);
            CP_COMMIT();
            CP_WAIT(1);
        } else {
            CP_WAIT(0);
        }
        __syncthreads();

        const float* As = sm + s * STAGE_FLOATS;
        const float* Bs = As + A_TILE_FLOATS;

        #pragma unroll
        for (int kk = 0; kk < 4; kk++) {
            const int kb = kk * 8;
            uint32_t a[4][4], b[8][2];
            #pragma unroll
            for (int mt = 0; mt < 4; mt++) {
                int rb = wm * 64 + mt * 16;
                a[mt][0] = __float_as_uint(As[(rb + r4)     * GSTRIDE + kb + c4]);
                a[mt][1] = __float_as_uint(As[(rb + 8 + r4) * GSTRIDE + kb + c4]);
                a[mt][2] = __float_as_uint(As[(rb + r4)     * GSTRIDE + kb + 4 + c4]);
                a[mt][3] = __float_as_uint(As[(rb + 8 + r4) * GSTRIDE + kb + 4 + c4]);
            }
            #pragma unroll
            for (int nt = 0; nt < 8; nt++) {
                int nb = wn * 64 + nt * 8;
                b[nt][0] = __float_as_uint(Bs[(nb + r4) * GSTRIDE + kb + c4]);
                b[nt][1] = __float_as_uint(Bs[(nb + r4) * GSTRIDE + kb + 4 + c4]);
            }
            #pragma unroll
            for (int mt = 0; mt < 4; mt++)
                #pragma unroll
                for (int nt = 0; nt < 8; nt++)
                    mma_tf32(acc[mt][nt][0], acc[mt][nt][1], acc[mt][nt][2], acc[mt][nt][3],
                             a[mt][0], a[mt][1], a[mt][2], a[mt][3],
                             b[nt][0], b[nt][1]);
        }
        __syncthreads();
    }

    const int c2l = 2 * c4;
    #pragma unroll
    for (int mt = 0; mt < 4; mt++) {
        int row = m0 + wm * 64 + mt * 16 + r4;
        #pragma unroll
        for (int nt = 0; nt < 8; nt++) {
            int col = n0 + wn * 64 + nt * 8 + c2l;
            *(float2*)(C + (size_t)row * N + col) =
                make_float2(acc[mt][nt][0], acc[mt][nt][1]);
            *(float2*)(C + (size_t)(row + 8) * N + col) =
                make_float2(acc[mt][nt][2], acc[mt][nt][3]);
        }
    }
}

// ---------------------------------------------------------------------------
// RoPE (float4 vectorized, in-place on g_qkv q,k). Folds 1/sqrt(d) into q,
// rounds to tf32.
// ---------------------------------------------------------------------------
__global__ __launch_bounds__(256) void rope_kernel(
    float* __restrict__ qkv, const float* __restrict__ cosp,
    const float* __restrict__ sinp)
{
    int idx = blockIdx.x * blockDim.x + threadIdx.x;
    int d4 = idx & 15;
    int h  = (idx >> 4) & (NHEAD - 1);
    int qk = (idx >> 8) & 1;
    int t  = (idx >> 9) & (SEQ - 1);
    int b  = idx >> 20;
    int d  = d4 * 4;

    float* base = qkv + ((size_t)(b * SEQ + t)) * C3 + qk * CDIM + h * HDIM;
    float4 x1 = *(float4*)(base + d);
    float4 x2 = *(float4*)(base + d + 64);
    float4 c1 = *(const float4*)(cosp + t * HDIM + d);
    float4 s1 = *(const float4*)(sinp + t * HDIM + d);
    float4 c2 = *(const float4*)(cosp + t * HDIM + d + 64);
    float4 s2 = *(const float4*)(sinp + t * HDIM + d + 64);

    float sc = (qk == 0) ? kScale : 1.f;
    float4 o1, o2;
    o1.x = to_tf32((x1.x * c1.x - x2.x * s1.x) * sc);
    o1.y = to_tf32((x1.y * c1.y - x2.y * s1.y) * sc);
    o1.z = to_tf32((x1.z * c1.z - x2.z * s1.z) * sc);
    o1.w = to_tf32((x1.w * c1.w - x2.w * s1.w) * sc);
    o2.x = to_tf32((x2.x * c2.x + x1.x * s2.x) * sc);
    o2.y = to_tf32((x2.y * c2.y + x1.y * s2.y) * sc);
    o2.z = to_tf32((x2.z * c2.z + x1.z * s2.z) * sc);
    o2.w = to_tf32((x2.w * c2.w + x1.w * s2.w) * sc);
    *(float4*)(base + d)      = o1;
    *(float4*)(base + d + 64) = o2;
}

// ---------------------------------------------------------------------------
// Flash attention: BM=128, BN=64, D=128, tf32 mma.sync.
// cp.async double-buffered K/Vt tiles; P kept in registers (shuffle to
// A-fragment layout, no smem staging).  (Unchanged from R6 — measured neutral.)
// ---------------------------------------------------------------------------
#define ABM 128
#define ABN 64
#define QS_STRIDE 132
#define KS_STRIDE 132
#define VS_STRIDE 68
#define QS_FLOATS (128*QS_STRIDE)                 // 16896
#define KT_FLOATS (64*KS_STRIDE)                  // 8448
#define VT_FLOATS (128*VS_STRIDE)                 // 8704
#define STG_FLOATS (KT_FLOATS + VT_FLOATS)        // 17152
#define ATTN_SMEM_BYTES ((QS_FLOATS + 2*STG_FLOATS) * 4)   // 204800

__global__ __launch_bounds__(256, 1) void attn_mma_kernel(
    const float* __restrict__ qkv, const float* __restrict__ vt,
    float* __restrict__ y)
{
    extern __shared__ float sm[];
    float* Qs = sm;                               // [128][132]

    const int tid = threadIdx.x;
    const int wid = tid >> 5;
    const int lid = tid & 31;
    const int r4  = lid >> 2;       // 0..7
    const int c4  = lid & 3;        // 0..3
    const int h   = blockIdx.y;
    const int b   = blockIdx.z;
    const int t0  = blockIdx.x * ABM;
    const int mrow = wid * 16;

    const uint32_t smem_u32 = smem_to_u32(sm);

    const size_t base = ((size_t)b * SEQ) * C3 + (size_t)h * HDIM;
    const float* Qg  = qkv + base;
    const float* Kg  = Qg + CDIM;
    const float* Vtg = vt + (size_t)(b * NHEAD + h) * HDIM * SEQ;

    #pragma unroll
    for (int i = 0; i < 16; i++) {
        int f = tid + i * 256;
        int r = f >> 5, q = f & 31;
        cp_async16(smem_u32 + (uint32_t)(r * QS_STRIDE + q * 4) * 4u,
                   Qg + (size_t)(t0 + r) * C3 + q * 4);
    }
    CP_COMMIT();

    auto issue_tile = [&](int kt) {
        const int s = kt & 1;
        const int s0 = kt * ABN;
        uint32_t kbase = smem_u32 + (uint32_t)(QS_FLOATS + s * STG_FLOATS) * 4u;
        uint32_t vbase = kbase + (uint32_t)KT_FLOATS * 4u;
        #pragma unroll
        for (int i = 0; i < 8; i++) {
            int f = tid + i * 256;
            int r = f >> 5, q = f & 31;
            cp_async16(kbase + (uint32_t)(r * KS_STRIDE + q * 4) * 4u,
                       Kg + (size_t)(s0 + r) * C3 + q * 4);
        }
        #pragma unroll
        for (int i = 0; i < 8; i++) {
            int f = tid + i * 256;
            int d = f >> 4, q = f & 15;
            cp_async16(vbase + (uint32_t)(d * VS_STRIDE + q * 4) * 4u,
                       Vtg + (size_t)d * SEQ + s0 + q * 4);
        }
    };

    issue_tile(0); CP_COMMIT();

    float Oa[16][4];
    #pragma unroll
    for (int nt = 0; nt < 16; nt++)
        Oa[nt][0] = Oa[nt][1] = Oa[nt][2] = Oa[nt][3] = 0.f;
    float m0 = -1e30f, m1 = -1e30f, l0 = 0.f, l1 = 0.f;

    const int NT = SEQ / ABN;   // 32
    for (int kt = 0; kt < NT; kt++) {
        __syncthreads();
        if (kt + 1 < NT) { issue_tile(kt + 1); CP_COMMIT(); }
        if (kt + 1 < NT) { CP_WAIT(1); } else { CP_WAIT(0); }
        __syncthreads();

        const float* Ks  = sm + QS_FLOATS + (kt & 1) * STG_FLOATS;
        const float* Vts = Ks + KT_FLOATS;

        // ---- S = Q @ K^T ----
        float P[8][4];
        #pragma unroll
        for (int nt = 0; nt < 8; nt++)
            P[nt][0] = P[nt][1] = P[nt][2] = P[nt][3] = 0.f;

        #pragma unroll
        for (int kk = 0; kk < 16; kk++) {
            const int kb = kk * 8;
            uint32_t a0 = __float_as_uint(Qs[(mrow + r4)     * QS_STRIDE + kb + c4]);
            uint32_t a1 = __float_as_uint(Qs[(mrow + 8 + r4) * QS_STRIDE + kb + c4]);
            uint32_t a2 = __float_as_uint(Qs[(mrow + r4)     * QS_STRIDE + kb + 4 + c4]);
            uint32_t a3 = __float_as_uint(Qs[(mrow + 8 + r4) * QS_STRIDE + kb + 4 + c4]);
            #pragma unroll
            for (int nt = 0; nt < 8; nt++) {
                uint32_t b0 = __float_as_uint(Ks[(nt * 8 + r4) * KS_STRIDE + kb + c4]);
                uint32_t b1 = __float_as_uint(Ks[(nt * 8 + r4) * KS_STRIDE + kb + 4 + c4]);
                mma_tf32(P[nt][0], P[nt][1], P[nt][2], P[nt][3],
                         a0, a1, a2, a3, b0, b1);
            }
        }

        // ---- online softmax ----
        float mx0 = -1e30f, mx1 = -1e30f;
        #pragma unroll
        for (int nt = 0; nt < 8; nt++) {
            mx0 = fmaxf(mx0, fmaxf(P[nt][0], P[nt][1]));
            mx1 = fmaxf(mx1, fmaxf(P[nt][2], P[nt][3]));
        }
        mx0 = fmaxf(mx0, __shfl_xor_sync(0xffffffffu, mx0, 1));
        mx0 = fmaxf(mx0, __shfl_xor_sync(0xffffffffu, mx0, 2));
        mx1 = fmaxf(mx1, __shfl_xor_sync(0xffffffffu, mx1, 1));
        mx1 = fmaxf(mx1, __shfl_xor_sync(0xffffffffu, mx1, 2));

        float mn0 = fmaxf(m0, mx0), mn1 = fmaxf(m1, mx1);
        float cr0 = __expf(m0 - mn0), cr1 = __expf(m1 - mn1);
        m0 = mn0; m1 = mn1;

        float s0s = 0.f, s1s = 0.f;
        #pragma unroll
        for (int nt = 0; nt < 8; nt++) {
            P[nt][0] = to_tf32(__expf(P[nt][0] - mn0));
            P[nt][1] = to_tf32(__expf(P[nt][1] - mn0));
            P[nt][2] = to_tf32(__expf(P[nt][2] - mn1));
            P[nt][3] = to_tf32(__expf(P[nt][3] - mn1));
            s0s += P[nt][0] + P[nt][1];
            s1s += P[nt][2] + P[nt][3];
        }
        s0s += __shfl_xor_sync(0xffffffffu, s0s, 1);
        s0s += __shfl_xor_sync(0xffffffffu, s0s, 2);
        s1s += __shfl_xor_sync(0xffffffffu, s1s, 1);
        s1s += __shfl_xor_sync(0xffffffffu, s1s, 2);
        l0 = l0 * cr0 + s0s;
        l1 = l1 * cr1 + s1s;

        #pragma unroll
        for (int nt = 0; nt < 16; nt++) {
            Oa[nt][0] *= cr0; Oa[nt][1] *= cr0;
            Oa[nt][2] *= cr1; Oa[nt][3] *= cr1;
        }

        // ---- O += P @ V : P C-fragment -> A-fragment via shuffles ----
        const int src0 = (lid & ~3) | (c4 >> 1);
        const int src1 = src0 + 2;
        const bool odd = (c4 & 1);
        #pragma unroll
        for (int j = 0; j < 8; j++) {
            float v00 = __shfl_sync(0xffffffffu, P[j][0], src0);
            float v01 = __shfl_sync(0xffffffffu, P[j][1], src0);
            float v02 = __shfl_sync(0xffffffffu, P[j][2], src0);
            float v03 = __shfl_sync(0xffffffffu, P[j][3], src0);
            float v10 = __shfl_sync(0xffffffffu, P[j][0], src1);
            float v11 = __shfl_sync(0xffffffffu, P[j][1], src1);
            float v12 = __shfl_sync(0xffffffffu, P[j][2], src1);
            float v13 = __shfl_sync(0xffffffffu, P[j][3], src1);
            uint32_t a0 = __float_as_uint(odd ? v01 : v00);
            uint32_t a1 = __float_as_uint(odd ? v03 : v02);
            uint32_t a2 = __float_as_uint(odd ? v11 : v10);
            uint32_t a3 = __float_as_uint(odd ? v13 : v12);
            const int kb = j * 8;
            #pragma unroll
            for (int nt = 0; nt < 16; nt++) {
                uint32_t b0 = __float_as_uint(Vts[(nt * 8 + r4) * VS_STRIDE + kb + c4]);
                uint32_t b1 = __float_as_uint(Vts[(nt * 8 + r4) * VS_STRIDE + kb + 4 + c4]);
                mma_tf32(Oa[nt][0], Oa[nt][1], Oa[nt][2], Oa[nt][3],
                         a0, a1, a2, a3, b0, b1);
            }
        }
    }

    // epilogue
    float inv0 = 1.f / l0, inv1 = 1.f / l1;
    int row0 = t0 + mrow + r4;
    int row1 = row0 + 8;
    float* y0 = y + ((size_t)b * SEQ + row0) * CDIM + h * HDIM;
    float* y1 = y + ((size_t)b * SEQ + row1) * CDIM + h * HDIM;
    #pragma unroll
    for (int nt = 0; nt < 16; nt++) {
        int col = nt * 8 + 2 * c4;
        *(float2*)(y0 + col) = make_float2(to_tf32(Oa[nt][0] * inv0),
                                           to_tf32(Oa[nt][1] * inv0));
        *(float2*)(y1 + col) = make_float2(to_tf32(Oa[nt][2] * inv1),
                                           to_tf32(Oa[nt][3] * inv1));
    }
}

// ---------------------------------------------------------------------------
extern "C" void kernel_launch(void* const* d_in, const int* in_sizes, int n_in,
                              void* d_out, int out_size)
{
    const float* x     = (const float*)d_in[0];
    const float* cosp  = (const float*)d_in[1];
    const float* sinp  = (const float*)d_in[2];
    const float* Wqkv  = (const float*)d_in[3];
    const float* Wproj = (const float*)d_in[4];
    float* out = (float*)d_out;

    float *qkv = nullptr, *y = nullptr, *xr = nullptr, *vt = nullptr;
    float *WtQkv = nullptr, *WtProj = nullptr;
    cudaGetSymbolAddress((void**)&qkv,    g_qkv);
    cudaGetSymbolAddress((void**)&y,      g_y);
    cudaGetSymbolAddress((void**)&xr,     g_xr);
    cudaGetSymbolAddress((void**)&vt,     g_vt);
    cudaGetSymbolAddress((void**)&WtQkv,  g_WtQkv);
    cudaGetSymbolAddress((void**)&WtProj, g_WtProj);

    cudaFuncSetAttribute(attn_mma_kernel, cudaFuncAttributeMaxDynamicSharedMemorySize, ATTN_SMEM_BYTES);
    cudaFuncSetAttribute(gemm_tf32mma,    cudaFuncAttributeMaxDynamicSharedMemorySize, GSMEM_BYTES);

    // 0) weights: transpose + tf32 round; x: tf32 round into scratch
    transpose_k<<<dim3(C3 / 32,   CDIM / 32), dim3(32, 8)>>>(Wqkv,  WtQkv,  CDIM, C3);
    transpose_k<<<dim3(CDIM / 32, CDIM / 32), dim3(32, 8)>>>(Wproj, WtProj, CDIM, CDIM);
    {
        int n4 = MROWS * CDIM / 4;
        round_tf32_kernel<<<(n4 + 255) / 256, 256>>>(x, xr, n4);
    }

    // 1) qkv = x @ W_qkv   (tf32 mma.sync, 128x256 tile, 2-stage)
    gemm_tf32mma<<<dim3(C3 / 256, MROWS / 128), 256, GSMEM_BYTES>>>(
        xr, WtQkv, qkv, MROWS, C3, CDIM);

    // 2) RoPE in place on q,k (+ tf32 round); build transposed tf32 V
    {
        int total = BATCH * SEQ * 2 * NHEAD * 16;
        rope_kernel<<<total / 256, 256>>>(qkv, cosp, sinp);
        transpose_vt<<<dim3(SEQ / 32, HDIM / 32, BATCH * NHEAD), dim3(32, 8)>>>(qkv, vt);
    }

    // 3) flash attention (tf32 mma) -> y [B,T,C]
    {
        dim3 grid(SEQ / ABM, NHEAD, BATCH);
        attn_mma_kernel<<<grid, 256, ATTN_SMEM_BYTES>>>(qkv, vt, y);
    }

    // 4) out = y @ W_proj  (tf32 mma.sync)
    gemm_tf32mma<<<dim3(CDIM / 256, MROWS / 128), 256, GSMEM_BYTES>>>(
        y, WtProj, out, MROWS, CDIM, CDIM);
}

// round 9
// speedup vs baseline: 2.7557x; 1.8685x over previous
#include <cuda_runtime.h>
#include <cuda_fp16.h>
#include <cstdint>

// Problem constants
#define BATCH 2
#define SEQ   2048
#define CDIM  2048
#define NHEAD 16
#define HDIM  128
#define C3    (3*CDIM)          // 6144
#define MROWS (BATCH*SEQ)       // 4096
static __device__ __constant__ float kScale = 0.08838834764831845f; // 1/sqrt(128)

// Scratch (device globals: allocation-free)
__device__ float  g_qkv[(size_t)BATCH*SEQ*C3];     // [B,T,3C] fp32 (GEMM1 out)
__device__ __half g_xh [(size_t)BATCH*SEQ*CDIM];   // half(x)
__device__ __half g_qh [(size_t)BATCH*SEQ*CDIM];   // roped+scaled q, half
__device__ __half g_kh [(size_t)BATCH*SEQ*CDIM];   // roped k, half
__device__ __half g_vth[(size_t)BATCH*NHEAD*HDIM*SEQ]; // V^T [b,h,d,t], half
__device__ __half g_yh [(size_t)BATCH*SEQ*CDIM];   // attention out, half
__device__ __half g_WhQkv[(size_t)C3*CDIM];        // W_qkv^T half
__device__ __half g_WhProj[(size_t)CDIM*CDIM];     // W_proj^T half

// ============================================================================
// helpers
// ============================================================================
__device__ __forceinline__ uint32_t smem_to_u32(const void* p) {
    uint32_t a;
    asm("{ .reg .u64 t; cvta.to.shared.u64 t, %1; cvt.u32.u64 %0, t; }" : "=r"(a) : "l"(p));
    return a;
}
__device__ __forceinline__ void cp_async16(uint32_t saddr, const void* g) {
    asm volatile("cp.async.cg.shared.global [%0], [%1], 16;" :: "r"(saddr), "l"(g));
}
#define CP_COMMIT() asm volatile("cp.async.commit_group;" ::: "memory")
#define CP_WAIT(n)  asm volatile("cp.async.wait_group %0;" :: "n"(n) : "memory")

__device__ __forceinline__ uint32_t pack_h2(float a, float b) {
    __half2 h = __floats2half2_rn(a, b);
    return *reinterpret_cast<uint32_t*>(&h);
}
__device__ __forceinline__ float2 unpack_h2(uint32_t u) {
    __half2 h = *reinterpret_cast<__half2*>(&u);
    return __half22float2(h);
}

// m16n8k16 fp16 mma, fp32 accumulate
__device__ __forceinline__ void mma_f16(
    float& c0, float& c1, float& c2, float& c3,
    uint32_t a0, uint32_t a1, uint32_t a2, uint32_t a3,
    uint32_t b0, uint32_t b1)
{
    asm volatile(
        "mma.sync.aligned.m16n8k16.row.col.f32.f16.f16.f32 "
        "{%0,%1,%2,%3}, {%4,%5,%6,%7}, {%8,%9}, {%0,%1,%2,%3};"
        : "+f"(c0), "+f"(c1), "+f"(c2), "+f"(c3)
        : "r"(a0), "r"(a1), "r"(a2), "r"(a3), "r"(b0), "r"(b1));
}

// ============================================================================
// convert fp32 -> fp16 (float4 -> 4 halfs)
// ============================================================================
__global__ __launch_bounds__(256) void convert_h_kernel(
    const float* __restrict__ in, __half* __restrict__ out, int n4)
{
    int i = blockIdx.x * blockDim.x + threadIdx.x;
    if (i < n4) {
        float4 v = ((const float4*)in)[i];
        uint2 o;
        o.x = pack_h2(v.x, v.y);
        o.y = pack_h2(v.z, v.w);
        ((uint2*)out)[i] = o;
    }
}

// ============================================================================
// Transpose + half convert: out[C][R] = half(in[R][C])
// ============================================================================
__global__ __launch_bounds__(256) void transpose_kh(
    const float* __restrict__ in, __half* __restrict__ out, int R, int C)
{
    __shared__ float t[32][33];
    int bx = blockIdx.x * 32, by = blockIdx.y * 32;
    int tx = threadIdx.x, ty = threadIdx.y;
    #pragma unroll
    for (int j = ty; j < 32; j += 8)
        t[j][tx] = in[(size_t)(by + j) * C + bx + tx];
    __syncthreads();
    #pragma unroll
    for (int j = ty; j < 32; j += 8)
        out[(size_t)(bx + j) * R + by + tx] = __float2half_rn(t[tx][j]);
}

// ============================================================================
// Transpose V head slabs: g_vth[(b*H+h)*D + d][t] = half(qkv_v[b,t,h,d])
// ============================================================================
__global__ __launch_bounds__(256) void transpose_vth(
    const float* __restrict__ qkv, __half* __restrict__ vt)
{
    __shared__ float t[32][33];
    int bh = blockIdx.z;
    int b = bh >> 4, h = bh & 15;
    const float* src = qkv + (size_t)b * SEQ * C3 + 2 * CDIM + h * HDIM;
    __half* dst = vt + (size_t)bh * HDIM * SEQ;
    int t0 = blockIdx.x * 32, d0 = blockIdx.y * 32;
    int tx = threadIdx.x, ty = threadIdx.y;
    #pragma unroll
    for (int j = ty; j < 32; j += 8)
        t[j][tx] = src[(size_t)(t0 + j) * C3 + d0 + tx];
    __syncthreads();
    #pragma unroll
    for (int j = ty; j < 32; j += 8)
        dst[(size_t)(d0 + j) * SEQ + t0 + tx] = __float2half_rn(t[tx][j]);
}

// ============================================================================
// FP16 mma.sync GEMM: C[M,N](fp32) = A[M,K] @ Bt[N,K]^T  (A, Bt half)
// 128x128 CTA tile, warp tile 64x32 (2Mx4N warps), K chunk 64 halves,
// 2-stage cp.async double buffer, 256 threads, 2 CTAs/SM.
// ============================================================================
#define GKH 64
#define GSTRH 72                                  // halves per smem row
#define TILE_H (128 * GSTRH)                      // 9216 halves per tile
#define STAGE_H (2 * TILE_H)                      // A + B
#define GSMEM_BYTES (2 * STAGE_H * 2)             // 73728 B

__global__ __launch_bounds__(256, 2) void gemm_f16mma(
    const __half* __restrict__ A, const __half* __restrict__ Bt,
    float* __restrict__ C, int M, int N, int K)
{
    extern __shared__ __half smh[];
    const int tid = threadIdx.x;
    const int wid = tid >> 5;
    const int lid = tid & 31;
    const int wm  = wid & 1;        // 0..1  (64 M-rows)
    const int wn  = wid >> 1;       // 0..3  (32 N-cols)
    const int m0  = blockIdx.y * 128;
    const int n0  = blockIdx.x * 128;

    const uint32_t smem_u32 = smem_to_u32(smh);

    float acc[4][4][4];
    #pragma unroll
    for (int i = 0; i < 4; i++)
        #pragma unroll
        for (int j = 0; j < 4; j++)
            #pragma unroll
            for (int u = 0; u < 4; u++) acc[i][j][u] = 0.f;

    const int nchunk = K / GKH;   // 32

    auto issue = [&](int c, int s) {
        const __half* Ag = A  + (size_t)m0 * K + c * GKH;
        const __half* Bg = Bt + (size_t)n0 * K + c * GKH;
        uint32_t baseA = smem_u32 + (uint32_t)(s * STAGE_H) * 2u;
        uint32_t baseB = baseA + (uint32_t)TILE_H * 2u;
        // each tile: 128 rows x (64 halves = 128B = 8 x 16B lines) = 1024 lines
        #pragma unroll
        for (int i = 0; i < 4; i++) {
            int f   = tid + i * 256;
            int row = f >> 3;
            int q   = f & 7;
            uint32_t soff = (uint32_t)(row * GSTRH + q * 8) * 2u;
            cp_async16(baseA + soff, Ag + (size_t)row * K + q * 8);
            cp_async16(baseB + soff, Bg + (size_t)row * K + q * 8);
        }
    };

    issue(0, 0);
    CP_COMMIT();

    const int r4 = lid >> 2;
    const int c4 = lid & 3;

    for (int c = 0; c < nchunk; c++) {
        const int s = c & 1;
        if (c + 1 < nchunk) {
            issue(c + 1, s ^ 1);
            CP_COMMIT();
            CP_WAIT(1);
        } else {
            CP_WAIT(0);
        }
        __syncthreads();

        const __half* As = smh + s * STAGE_H;
        const __half* Bs = As + TILE_H;

        #pragma unroll
        for (int kk = 0; kk < 4; kk++) {             // K16 steps
            const int kb = kk * 16;
            uint32_t a[4][4], b[4][2];
            #pragma unroll
            for (int mt = 0; mt < 4; mt++) {
                int rb = wm * 64 + mt * 16;
                a[mt][0] = *(const uint32_t*)(As + (rb + r4)     * GSTRH + kb + 2 * c4);
                a[mt][1] = *(const uint32_t*)(As + (rb + 8 + r4) * GSTRH + kb + 2 * c4);
                a[mt][2] = *(const uint32_t*)(As + (rb + r4)     * GSTRH + kb + 8 + 2 * c4);
                a[mt][3] = *(const uint32_t*)(As + (rb + 8 + r4) * GSTRH + kb + 8 + 2 * c4);
            }
            #pragma unroll
            for (int nt = 0; nt < 4; nt++) {
                int nb = wn * 32 + nt * 8;
                b[nt][0] = *(const uint32_t*)(Bs + (nb + r4) * GSTRH + kb + 2 * c4);
                b[nt][1] = *(const uint32_t*)(Bs + (nb + r4) * GSTRH + kb + 8 + 2 * c4);
            }
            #pragma unroll
            for (int mt = 0; mt < 4; mt++)
                #pragma unroll
                for (int nt = 0; nt < 4; nt++)
                    mma_f16(acc[mt][nt][0], acc[mt][nt][1], acc[mt][nt][2], acc[mt][nt][3],
                            a[mt][0], a[mt][1], a[mt][2], a[mt][3],
                            b[nt][0], b[nt][1]);
        }
        __syncthreads();
    }

    const int c2l = 2 * c4;
    #pragma unroll
    for (int mt = 0; mt < 4; mt++) {
        int row = m0 + wm * 64 + mt * 16 + r4;
        #pragma unroll
        for (int nt = 0; nt < 4; nt++) {
            int col = n0 + wn * 32 + nt * 8 + c2l;
            *(float2*)(C + (size_t)row * N + col) =
                make_float2(acc[mt][nt][0], acc[mt][nt][1]);
            *(float2*)(C + (size_t)(row + 8) * N + col) =
                make_float2(acc[mt][nt][2], acc[mt][nt][3]);
        }
    }
}

// ---------------------------------------------------------------------------
// RoPE: read qkv fp32, write half q (scaled by 1/sqrt(d)) and half k.
// ---------------------------------------------------------------------------
__global__ __launch_bounds__(256) void rope_h_kernel(
    const float* __restrict__ qkv, const float* __restrict__ cosp,
    const float* __restrict__ sinp, __half* __restrict__ qh,
    __half* __restrict__ kh)
{
    int idx = blockIdx.x * blockDim.x + threadIdx.x;
    int d4 = idx & 15;
    int h  = (idx >> 4) & (NHEAD - 1);
    int qk = (idx >> 8) & 1;
    int t  = (idx >> 9) & (SEQ - 1);
    int b  = idx >> 20;
    int d  = d4 * 4;

    const float* base = qkv + ((size_t)(b * SEQ + t)) * C3 + qk * CDIM + h * HDIM;
    float4 x1 = *(const float4*)(base + d);
    float4 x2 = *(const float4*)(base + d + 64);
    float4 c1 = *(const float4*)(cosp + t * HDIM + d);
    float4 s1 = *(const float4*)(sinp + t * HDIM + d);
    float4 c2 = *(const float4*)(cosp + t * HDIM + d + 64);
    float4 s2 = *(const float4*)(sinp + t * HDIM + d + 64);

    float sc = (qk == 0) ? kScale : 1.f;
    __half* outp = (qk == 0 ? qh : kh) + ((size_t)(b * SEQ + t)) * CDIM + h * HDIM;
    uint2 o1, o2;
    o1.x = pack_h2((x1.x * c1.x - x2.x * s1.x) * sc, (x1.y * c1.y - x2.y * s1.y) * sc);
    o1.y = pack_h2((x1.z * c1.z - x2.z * s1.z) * sc, (x1.w * c1.w - x2.w * s1.w) * sc);
    o2.x = pack_h2((x2.x * c2.x + x1.x * s2.x) * sc, (x2.y * c2.y + x1.y * s2.y) * sc);
    o2.y = pack_h2((x2.z * c2.z + x1.z * s2.z) * sc, (x2.w * c2.w + x1.w * s2.w) * sc);
    *(uint2*)(outp + d)      = o1;
    *(uint2*)(outp + d + 64) = o2;
}

// ---------------------------------------------------------------------------
// Flash attention fp16: BM=128, BN=64, D=128, m16n8k16 mma.
// cp.async double-buffered K/Vt; P stays in registers (C frag == A frag).
// ---------------------------------------------------------------------------
#define ABM 128
#define ABN 64
#define QSH 136                 // Q/K smem stride (halves)
#define VSH 72                  // Vt smem stride (halves)
#define Q_HALVES (128 * QSH)    // 17408
#define K_HALVES (64 * QSH)     // 8704
#define V_HALVES (128 * VSH)    // 9216
#define STG_HALVES (K_HALVES + V_HALVES)          // 17920
#define ATTN_SMEM_BYTES ((Q_HALVES + 2 * STG_HALVES) * 2)  // 106496

__global__ __launch_bounds__(256, 1) void attn_f16_kernel(
    const __half* __restrict__ qh, const __half* __restrict__ kh,
    const __half* __restrict__ vt, __half* __restrict__ y)
{
    extern __shared__ __half smh[];
    __half* Qs = smh;                              // [128][136]

    const int tid = threadIdx.x;
    const int wid = tid >> 5;
    const int lid = tid & 31;
    const int r4  = lid >> 2;       // 0..7
    const int c4  = lid & 3;        // 0..3
    const int h   = blockIdx.y;
    const int b   = blockIdx.z;
    const int t0  = blockIdx.x * ABM;
    const int mrow = wid * 16;

    const uint32_t smem_u32 = smem_to_u32(smh);

    const __half* Qg  = qh + ((size_t)b * SEQ) * CDIM + h * HDIM;  // row stride CDIM
    const __half* Kg  = kh + ((size_t)b * SEQ) * CDIM + h * HDIM;
    const __half* Vtg = vt + (size_t)(b * NHEAD + h) * HDIM * SEQ; // row stride SEQ

    // Q tile: 128 rows x 128 halves = 16 lines/row -> 2048 lines, 8/thread
    #pragma unroll
    for (int i = 0; i < 8; i++) {
        int f = tid + i * 256;
        int r = f >> 4, q = f & 15;
        cp_async16(smem_u32 + (uint32_t)(r * QSH + q * 8) * 2u,
                   Qg + (size_t)(t0 + r) * CDIM + q * 8);
    }
    CP_COMMIT();

    auto issue_tile = [&](int kt) {
        const int s = kt & 1;
        const int s0 = kt * ABN;
        uint32_t kbase = smem_u32 + (uint32_t)(Q_HALVES + s * STG_HALVES) * 2u;
        uint32_t vbase = kbase + (uint32_t)K_HALVES * 2u;
        // K: 64 rows x 16 lines = 1024 lines, 4/thread
        #pragma unroll
        for (int i = 0; i < 4; i++) {
            int f = tid + i * 256;
            int r = f >> 4, q = f & 15;
            cp_async16(kbase + (uint32_t)(r * QSH + q * 8) * 2u,
                       Kg + (size_t)(s0 + r) * CDIM + q * 8);
        }
        // Vt: 128 d-rows x (64 halves = 8 lines) = 1024 lines, 4/thread
        #pragma unroll
        for (int i = 0; i < 4; i++) {
            int f = tid + i * 256;
            int d = f >> 3, q = f & 7;
            cp_async16(vbase + (uint32_t)(d * VSH + q * 8) * 2u,
                       Vtg + (size_t)d * SEQ + s0 + q * 8);
        }
    };

    issue_tile(0); CP_COMMIT();

    float Oa[16][4];
    #pragma unroll
    for (int nt = 0; nt < 16; nt++)
        Oa[nt][0] = Oa[nt][1] = Oa[nt][2] = Oa[nt][3] = 0.f;
    float m0 = -1e30f, m1 = -1e30f, l0 = 0.f, l1 = 0.f;

    const int NT = SEQ / ABN;   // 32
    for (int kt = 0; kt < NT; kt++) {
        __syncthreads();
        if (kt + 1 < NT) { issue_tile(kt + 1); CP_COMMIT(); }
        if (kt + 1 < NT) { CP_WAIT(1); } else { CP_WAIT(0); }
        __syncthreads();

        const __half* Ks  = smh + Q_HALVES + (kt & 1) * STG_HALVES;
        const __half* Vts = Ks + K_HALVES;

        // ---- S = Q @ K^T : 8 K16-steps, 8 n-tiles ----
        float P[8][4];
        #pragma unroll
        for (int nt = 0; nt < 8; nt++)
            P[nt][0] = P[nt][1] = P[nt][2] = P[nt][3] = 0.f;

        #pragma unroll
        for (int kk = 0; kk < 8; kk++) {
            const int kb = kk * 16;
            uint32_t a0 = *(const uint32_t*)(Qs + (mrow + r4)     * QSH + kb + 2 * c4);
            uint32_t a1 = *(const uint32_t*)(Qs + (mrow + 8 + r4) * QSH + kb + 2 * c4);
            uint32_t a2 = *(const uint32_t*)(Qs + (mrow + r4)     * QSH + kb + 8 + 2 * c4);
            uint32_t a3 = *(const uint32_t*)(Qs + (mrow + 8 + r4) * QSH + kb + 8 + 2 * c4);
            #pragma unroll
            for (int nt = 0; nt < 8; nt++) {
                uint32_t b0 = *(const uint32_t*)(Ks + (nt * 8 + r4) * QSH + kb + 2 * c4);
                uint32_t b1 = *(const uint32_t*)(Ks + (nt * 8 + r4) * QSH + kb + 8 + 2 * c4);
                mma_f16(P[nt][0], P[nt][1], P[nt][2], P[nt][3],
                        a0, a1, a2, a3, b0, b1);
            }
        }

        // ---- online softmax (rows mrow+r4 / +8; lanes c4 share a row) ----
        float mx0 = -1e30f, mx1 = -1e30f;
        #pragma unroll
        for (int nt = 0; nt < 8; nt++) {
            mx0 = fmaxf(mx0, fmaxf(P[nt][0], P[nt][1]));
            mx1 = fmaxf(mx1, fmaxf(P[nt][2], P[nt][3]));
        }
        mx0 = fmaxf(mx0, __shfl_xor_sync(0xffffffffu, mx0, 1));
        mx0 = fmaxf(mx0, __shfl_xor_sync(0xffffffffu, mx0, 2));
        mx1 = fmaxf(mx1, __shfl_xor_sync(0xffffffffu, mx1, 1));
        mx1 = fmaxf(mx1, __shfl_xor_sync(0xffffffffu, mx1, 2));

        float mn0 = fmaxf(m0, mx0), mn1 = fmaxf(m1, mx1);
        float cr0 = __expf(m0 - mn0), cr1 = __expf(m1 - mn1);
        m0 = mn0; m1 = mn1;

        // exp, round to half (P numerator == l denominator), pack A-frags
        uint32_t ph[8][2];
        float s0s = 0.f, s1s = 0.f;
        #pragma unroll
        for (int nt = 0; nt < 8; nt++) {
            float p0 = __expf(P[nt][0] - mn0);
            float p1 = __expf(P[nt][1] - mn0);
            float p2 = __expf(P[nt][2] - mn1);
            float p3 = __expf(P[nt][3] - mn1);
            ph[nt][0] = pack_h2(p0, p1);
            ph[nt][1] = pack_h2(p2, p3);
            float2 r01 = unpack_h2(ph[nt][0]);
            float2 r23 = unpack_h2(ph[nt][1]);
            s0s += r01.x + r01.y;
            s1s += r23.x + r23.y;
        }
        s0s += __shfl_xor_sync(0xffffffffu, s0s, 1);
        s0s += __shfl_xor_sync(0xffffffffu, s0s, 2);
        s1s += __shfl_xor_sync(0xffffffffu, s1s, 1);
        s1s += __shfl_xor_sync(0xffffffffu, s1s, 2);
        l0 = l0 * cr0 + s0s;
        l1 = l1 * cr1 + s1s;

        #pragma unroll
        for (int nt = 0; nt < 16; nt++) {
            Oa[nt][0] *= cr0; Oa[nt][1] *= cr0;
            Oa[nt][2] *= cr1; Oa[nt][3] *= cr1;
        }

        // ---- O += P @ V : A frag direct from ph (C->A identity), 4 K16 steps ----
        #pragma unroll
        for (int kk = 0; kk < 4; kk++) {
            const int kb = kk * 16;
            uint32_t a0 = ph[2 * kk][0];
            uint32_t a1 = ph[2 * kk][1];
            uint32_t a2 = ph[2 * kk + 1][0];
            uint32_t a3 = ph[2 * kk + 1][1];
            #pragma unroll
            for (int nt = 0; nt < 16; nt++) {
                uint32_t b0 = *(const uint32_t*)(Vts + (nt * 8 + r4) * VSH + kb + 2 * c4);
                uint32_t b1 = *(const uint32_t*)(Vts + (nt * 8 + r4) * VSH + kb + 8 + 2 * c4);
                mma_f16(Oa[nt][0], Oa[nt][1], Oa[nt][2], Oa[nt][3],
                        a0, a1, a2, a3, b0, b1);
            }
        }
    }

    // epilogue: half(O/l) -> y
    float inv0 = 1.f / l0, inv1 = 1.f / l1;
    int row0 = t0 + mrow + r4;
    int row1 = row0 + 8;
    __half* y0 = y + ((size_t)b * SEQ + row0) * CDIM + h * HDIM;
    __half* y1 = y + ((size_t)b * SEQ + row1) * CDIM + h * HDIM;
    #pragma unroll
    for (int nt = 0; nt < 16; nt++) {
        int col = nt * 8 + 2 * c4;
        *(uint32_t*)(y0 + col) = pack_h2(Oa[nt][0] * inv0, Oa[nt][1] * inv0);
        *(uint32_t*)(y1 + col) = pack_h2(Oa[nt][2] * inv1, Oa[nt][3] * inv1);
    }
}

// ---------------------------------------------------------------------------
extern "C" void kernel_launch(void* const* d_in, const int* in_sizes, int n_in,
                              void* d_out, int out_size)
{
    const float* x     = (const float*)d_in[0];
    const float* cosp  = (const float*)d_in[1];
    const float* sinp  = (const float*)d_in[2];
    const float* Wqkv  = (const float*)d_in[3];
    const float* Wproj = (const float*)d_in[4];
    float* out = (float*)d_out;

    float *qkv = nullptr;
    __half *xh = nullptr, *qh = nullptr, *kh = nullptr, *vth = nullptr, *yh = nullptr;
    __half *WhQkv = nullptr, *WhProj = nullptr;
    cudaGetSymbolAddress((void**)&qkv,    g_qkv);
    cudaGetSymbolAddress((void**)&xh,     g_xh);
    cudaGetSymbolAddress((void**)&qh,     g_qh);
    cudaGetSymbolAddress((void**)&kh,     g_kh);
    cudaGetSymbolAddress((void**)&vth,    g_vth);
    cudaGetSymbolAddress((void**)&yh,     g_yh);
    cudaGetSymbolAddress((void**)&WhQkv,  g_WhQkv);
    cudaGetSymbolAddress((void**)&WhProj, g_WhProj);

    cudaFuncSetAttribute(attn_f16_kernel, cudaFuncAttributeMaxDynamicSharedMemorySize, ATTN_SMEM_BYTES);
    cudaFuncSetAttribute(gemm_f16mma,     cudaFuncAttributeMaxDynamicSharedMemorySize, GSMEM_BYTES);

    // 0) weights: transpose + half; x: half
    transpose_kh<<<dim3(C3 / 32,   CDIM / 32), dim3(32, 8)>>>(Wqkv,  WhQkv,  CDIM, C3);
    transpose_kh<<<dim3(CDIM / 32, CDIM / 32), dim3(32, 8)>>>(Wproj, WhProj, CDIM, CDIM);
    {
        int n4 = MROWS * CDIM / 4;
        convert_h_kernel<<<(n4 + 255) / 256, 256>>>(x, xh, n4);
    }

    // 1) qkv = x @ W_qkv   (fp16 mma, fp32 out)
    gemm_f16mma<<<dim3(C3 / 128, MROWS / 128), 256, GSMEM_BYTES>>>(
        xh, WhQkv, qkv, MROWS, C3, CDIM);

    // 2) RoPE -> qh, kh (half); V -> vth (half, transposed)
    {
        int total = BATCH * SEQ * 2 * NHEAD * 16;
        rope_h_kernel<<<total / 256, 256>>>(qkv, cosp, sinp, qh, kh);
        transpose_vth<<<dim3(SEQ / 32, HDIM / 32, BATCH * NHEAD), dim3(32, 8)>>>(qkv, vth);
    }

    // 3) flash attention (fp16 mma) -> yh
    {
        dim3 grid(SEQ / ABM, NHEAD, BATCH);
        attn_f16_kernel<<<grid, 256, ATTN_SMEM_BYTES>>>(qh, kh, vth, yh);
    }

    // 4) out = y @ W_proj  (fp16 mma, fp32 out)
    gemm_f16mma<<<dim3(CDIM / 128, MROWS / 128), 256, GSMEM_BYTES>>>(
        yh, WhProj, out, MROWS, CDIM, CDIM);
}

// round 10
// speedup vs baseline: 2.9657x; 1.0762x over previous
#include <cuda_runtime.h>
#include <cuda_fp16.h>
#include <cstdint>

// Problem constants
#define BATCH 2
#define SEQ   2048
#define CDIM  2048
#define NHEAD 16
#define HDIM  128
#define C3    (3*CDIM)          // 6144
#define MROWS (BATCH*SEQ)       // 4096
static __device__ __constant__ float kScale = 0.08838834764831845f; // 1/sqrt(128)

// Scratch (device globals: allocation-free)
__device__ float  g_qkv[(size_t)BATCH*SEQ*C3];     // [B,T,3C] fp32 (GEMM1 out)
__device__ __half g_xh [(size_t)BATCH*SEQ*CDIM];   // half(x)
__device__ __half g_qh [(size_t)BATCH*SEQ*CDIM];   // roped+scaled q, half
__device__ __half g_kh [(size_t)BATCH*SEQ*CDIM];   // roped k, half
__device__ __half g_vth[(size_t)BATCH*NHEAD*HDIM*SEQ]; // V^T [b,h,d,t], half
__device__ __half g_yh [(size_t)BATCH*SEQ*CDIM];   // attention out, half
__device__ __half g_WhQkv[(size_t)C3*CDIM];        // W_qkv^T half
__device__ __half g_WhProj[(size_t)CDIM*CDIM];     // W_proj^T half

// ============================================================================
// helpers
// ============================================================================
__device__ __forceinline__ uint32_t smem_to_u32(const void* p) {
    uint32_t a;
    asm("{ .reg .u64 t; cvta.to.shared.u64 t, %1; cvt.u32.u64 %0, t; }" : "=r"(a) : "l"(p));
    return a;
}
__device__ __forceinline__ void cp_async16(uint32_t saddr, const void* g) {
    asm volatile("cp.async.cg.shared.global [%0], [%1], 16;" :: "r"(saddr), "l"(g));
}
#define CP_COMMIT() asm volatile("cp.async.commit_group;" ::: "memory")
#define CP_WAIT(n)  asm volatile("cp.async.wait_group %0;" :: "n"(n) : "memory")

__device__ __forceinline__ uint32_t pack_h2(float a, float b) {
    __half2 h = __floats2half2_rn(a, b);
    return *reinterpret_cast<uint32_t*>(&h);
}
__device__ __forceinline__ float2 unpack_h2(uint32_t u) {
    __half2 h = *reinterpret_cast<__half2*>(&u);
    return __half22float2(h);
}

// m16n8k16 fp16 mma, fp32 accumulate
__device__ __forceinline__ void mma_f16(
    float& c0, float& c1, float& c2, float& c3,
    uint32_t a0, uint32_t a1, uint32_t a2, uint32_t a3,
    uint32_t b0, uint32_t b1)
{
    asm volatile(
        "mma.sync.aligned.m16n8k16.row.col.f32.f16.f16.f32 "
        "{%0,%1,%2,%3}, {%4,%5,%6,%7}, {%8,%9}, {%0,%1,%2,%3};"
        : "+f"(c0), "+f"(c1), "+f"(c2), "+f"(c3)
        : "r"(a0), "r"(a1), "r"(a2), "r"(a3), "r"(b0), "r"(b1));
}

// ============================================================================
// convert fp32 -> fp16
// ============================================================================
__global__ __launch_bounds__(256) void convert_h_kernel(
    const float* __restrict__ in, __half* __restrict__ out, int n4)
{
    int i = blockIdx.x * blockDim.x + threadIdx.x;
    if (i < n4) {
        float4 v = ((const float4*)in)[i];
        uint2 o;
        o.x = pack_h2(v.x, v.y);
        o.y = pack_h2(v.z, v.w);
        ((uint2*)out)[i] = o;
    }
}

// ============================================================================
// Transpose + half convert: out[C][R] = half(in[R][C])
// ============================================================================
__global__ __launch_bounds__(256) void transpose_kh(
    const float* __restrict__ in, __half* __restrict__ out, int R, int C)
{
    __shared__ float t[32][33];
    int bx = blockIdx.x * 32, by = blockIdx.y * 32;
    int tx = threadIdx.x, ty = threadIdx.y;
    #pragma unroll
    for (int j = ty; j < 32; j += 8)
        t[j][tx] = in[(size_t)(by + j) * C + bx + tx];
    __syncthreads();
    #pragma unroll
    for (int j = ty; j < 32; j += 8)
        out[(size_t)(bx + j) * R + by + tx] = __float2half_rn(t[tx][j]);
}

// ============================================================================
// Transpose V head slabs: g_vth[(b*H+h)*D + d][t] = half(qkv_v[b,t,h,d])
// ============================================================================
__global__ __launch_bounds__(256) void transpose_vth(
    const float* __restrict__ qkv, __half* __restrict__ vt)
{
    __shared__ float t[32][33];
    int bh = blockIdx.z;
    int b = bh >> 4, h = bh & 15;
    const float* src = qkv + (size_t)b * SEQ * C3 + 2 * CDIM + h * HDIM;
    __half* dst = vt + (size_t)bh * HDIM * SEQ;
    int t0 = blockIdx.x * 32, d0 = blockIdx.y * 32;
    int tx = threadIdx.x, ty = threadIdx.y;
    #pragma unroll
    for (int j = ty; j < 32; j += 8)
        t[j][tx] = src[(size_t)(t0 + j) * C3 + d0 + tx];
    __syncthreads();
    #pragma unroll
    for (int j = ty; j < 32; j += 8)
        dst[(size_t)(d0 + j) * SEQ + t0 + tx] = __float2half_rn(t[tx][j]);
}

// ============================================================================
// FP16 mma.sync GEMM: C[M,N](fp32) = A[M,K] @ Bt[N,K]^T
// 128x128 CTA tile, 128 threads = 4 warps in 2x2 grid, warp tile 64x64.
// K chunk 64 halves, 2-stage cp.async double buffer, 2 CTAs/SM.
// ============================================================================
#define GKH 64
#define GSTRH 72                                  // halves per smem row
#define TILE_H (128 * GSTRH)                      // 9216 halves per tile
#define STAGE_H (2 * TILE_H)                      // A + B
#define GSMEM_BYTES (2 * STAGE_H * 2)             // 73728 B

__global__ __launch_bounds__(128, 2) void gemm_f16mma(
    const __half* __restrict__ A, const __half* __restrict__ Bt,
    float* __restrict__ C, int M, int N, int K)
{
    extern __shared__ __half smh[];
    const int tid = threadIdx.x;
    const int wid = tid >> 5;
    const int lid = tid & 31;
    const int wm  = wid & 1;        // 0..1  (64 M-rows)
    const int wn  = wid >> 1;       // 0..1  (64 N-cols)
    const int m0  = blockIdx.y * 128;
    const int n0  = blockIdx.x * 128;

    const uint32_t smem_u32 = smem_to_u32(smh);

    float acc[4][8][4];
    #pragma unroll
    for (int i = 0; i < 4; i++)
        #pragma unroll
        for (int j = 0; j < 8; j++)
            #pragma unroll
            for (int u = 0; u < 4; u++) acc[i][j][u] = 0.f;

    const int nchunk = K / GKH;   // 32

    auto issue = [&](int c, int s) {
        const __half* Ag = A  + (size_t)m0 * K + c * GKH;
        const __half* Bg = Bt + (size_t)n0 * K + c * GKH;
        uint32_t baseA = smem_u32 + (uint32_t)(s * STAGE_H) * 2u;
        uint32_t baseB = baseA + (uint32_t)TILE_H * 2u;
        // each tile: 128 rows x 8 lines = 1024 lines; 128 threads -> 8 iters
        #pragma unroll
        for (int i = 0; i < 8; i++) {
            int f   = tid + i * 128;
            int row = f >> 3;
            int q   = f & 7;
            uint32_t soff = (uint32_t)(row * GSTRH + q * 8) * 2u;
            cp_async16(baseA + soff, Ag + (size_t)row * K + q * 8);
            cp_async16(baseB + soff, Bg + (size_t)row * K + q * 8);
        }
    };

    issue(0, 0);
    CP_COMMIT();

    const int r4 = lid >> 2;
    const int c4 = lid & 3;

    for (int c = 0; c < nchunk; c++) {
        const int s = c & 1;
        if (c + 1 < nchunk) {
            issue(c + 1, s ^ 1);
            CP_COMMIT();
            CP_WAIT(1);
        } else {
            CP_WAIT(0);
        }
        __syncthreads();

        const __half* As = smh + s * STAGE_H;
        const __half* Bs = As + TILE_H;

        #pragma unroll
        for (int kk = 0; kk < 4; kk++) {             // K16 steps
            const int kb = kk * 16;
            uint32_t a[4][4], b[8][2];
            #pragma unroll
            for (int mt = 0; mt < 4; mt++) {
                int rb = wm * 64 + mt * 16;
                a[mt][0] = *(const uint32_t*)(As + (rb + r4)     * GSTRH + kb + 2 * c4);
                a[mt][1] = *(const uint32_t*)(As + (rb + 8 + r4) * GSTRH + kb + 2 * c4);
                a[mt][2] = *(const uint32_t*)(As + (rb + r4)     * GSTRH + kb + 8 + 2 * c4);
                a[mt][3] = *(const uint32_t*)(As + (rb + 8 + r4) * GSTRH + kb + 8 + 2 * c4);
            }
            #pragma unroll
            for (int nt = 0; nt < 8; nt++) {
                int nb = wn * 64 + nt * 8;
                b[nt][0] = *(const uint32_t*)(Bs + (nb + r4) * GSTRH + kb + 2 * c4);
                b[nt][1] = *(const uint32_t*)(Bs + (nb + r4) * GSTRH + kb + 8 + 2 * c4);
            }
            #pragma unroll
            for (int mt = 0; mt < 4; mt++)
                #pragma unroll
                for (int nt = 0; nt < 8; nt++)
                    mma_f16(acc[mt][nt][0], acc[mt][nt][1], acc[mt][nt][2], acc[mt][nt][3],
                            a[mt][0], a[mt][1], a[mt][2], a[mt][3],
                            b[nt][0], b[nt][1]);
        }
        __syncthreads();
    }

    const int c2l = 2 * c4;
    #pragma unroll
    for (int mt = 0; mt < 4; mt++) {
        int row = m0 + wm * 64 + mt * 16 + r4;
        #pragma unroll
        for (int nt = 0; nt < 8; nt++) {
            int col = n0 + wn * 64 + nt * 8 + c2l;
            *(float2*)(C + (size_t)row * N + col) =
                make_float2(acc[mt][nt][0], acc[mt][nt][1]);
            *(float2*)(C + (size_t)(row + 8) * N + col) =
                make_float2(acc[mt][nt][2], acc[mt][nt][3]);
        }
    }
}

// ---------------------------------------------------------------------------
// RoPE: read qkv fp32, write half q (scaled by 1/sqrt(d)) and half k.
// ---------------------------------------------------------------------------
__global__ __launch_bounds__(256) void rope_h_kernel(
    const float* __restrict__ qkv, const float* __restrict__ cosp,
    const float* __restrict__ sinp, __half* __restrict__ qh,
    __half* __restrict__ kh)
{
    int idx = blockIdx.x * blockDim.x + threadIdx.x;
    int d4 = idx & 15;
    int h  = (idx >> 4) & (NHEAD - 1);
    int qk = (idx >> 8) & 1;
    int t  = (idx >> 9) & (SEQ - 1);
    int b  = idx >> 20;
    int d  = d4 * 4;

    const float* base = qkv + ((size_t)(b * SEQ + t)) * C3 + qk * CDIM + h * HDIM;
    float4 x1 = *(const float4*)(base + d);
    float4 x2 = *(const float4*)(base + d + 64);
    float4 c1 = *(const float4*)(cosp + t * HDIM + d);
    float4 s1 = *(const float4*)(sinp + t * HDIM + d);
    float4 c2 = *(const float4*)(cosp + t * HDIM + d + 64);
    float4 s2 = *(const float4*)(sinp + t * HDIM + d + 64);

    float sc = (qk == 0) ? kScale : 1.f;
    __half* outp = (qk == 0 ? qh : kh) + ((size_t)(b * SEQ + t)) * CDIM + h * HDIM;
    uint2 o1, o2;
    o1.x = pack_h2((x1.x * c1.x - x2.x * s1.x) * sc, (x1.y * c1.y - x2.y * s1.y) * sc);
    o1.y = pack_h2((x1.z * c1.z - x2.z * s1.z) * sc, (x1.w * c1.w - x2.w * s1.w) * sc);
    o2.x = pack_h2((x2.x * c2.x + x1.x * s2.x) * sc, (x2.y * c2.y + x1.y * s2.y) * sc);
    o2.y = pack_h2((x2.z * c2.z + x1.z * s2.z) * sc, (x2.w * c2.w + x1.w * s2.w) * sc);
    *(uint2*)(outp + d)      = o1;
    *(uint2*)(outp + d + 64) = o2;
}

// ---------------------------------------------------------------------------
// Flash attention fp16: BM=128, BN=64, D=128, m16n8k16 mma.
// 128 threads = 4 warps; warp w owns 32 q-rows (2 x 16-row sub-tiles).
// cp.async double-buffered K/Vt; P stays in registers (C frag == A frag).
// ---------------------------------------------------------------------------
#define ABM 128
#define ABN 64
#define QSH 136                 // Q/K smem stride (halves)
#define VSH 72                  // Vt smem stride (halves)
#define Q_HALVES (128 * QSH)    // 17408
#define K_HALVES (64 * QSH)     // 8704
#define V_HALVES (128 * VSH)    // 9216
#define STG_HALVES (K_HALVES + V_HALVES)          // 17920
#define ATTN_SMEM_BYTES ((Q_HALVES + 2 * STG_HALVES) * 2)  // 106496

__global__ __launch_bounds__(128, 2) void attn_f16_kernel(
    const __half* __restrict__ qh, const __half* __restrict__ kh,
    const __half* __restrict__ vt, __half* __restrict__ y)
{
    extern __shared__ __half smh[];
    __half* Qs = smh;                              // [128][136]

    const int tid = threadIdx.x;
    const int wid = tid >> 5;
    const int lid = tid & 31;
    const int r4  = lid >> 2;       // 0..7
    const int c4  = lid & 3;        // 0..3
    const int h   = blockIdx.y;
    const int b   = blockIdx.z;
    const int t0  = blockIdx.x * ABM;
    const int mrow = wid * 32;      // warp owns rows [mrow, mrow+32)

    const uint32_t smem_u32 = smem_to_u32(smh);

    const __half* Qg  = qh + ((size_t)b * SEQ) * CDIM + h * HDIM;
    const __half* Kg  = kh + ((size_t)b * SEQ) * CDIM + h * HDIM;
    const __half* Vtg = vt + (size_t)(b * NHEAD + h) * HDIM * SEQ;

    // Q tile: 2048 lines; 128 threads -> 16 iters
    #pragma unroll
    for (int i = 0; i < 16; i++) {
        int f = tid + i * 128;
        int r = f >> 4, q = f & 15;
        cp_async16(smem_u32 + (uint32_t)(r * QSH + q * 8) * 2u,
                   Qg + (size_t)(t0 + r) * CDIM + q * 8);
    }
    CP_COMMIT();

    auto issue_tile = [&](int kt) {
        const int s = kt & 1;
        const int s0 = kt * ABN;
        uint32_t kbase = smem_u32 + (uint32_t)(Q_HALVES + s * STG_HALVES) * 2u;
        uint32_t vbase = kbase + (uint32_t)K_HALVES * 2u;
        // K: 1024 lines -> 8 iters
        #pragma unroll
        for (int i = 0; i < 8; i++) {
            int f = tid + i * 128;
            int r = f >> 4, q = f & 15;
            cp_async16(kbase + (uint32_t)(r * QSH + q * 8) * 2u,
                       Kg + (size_t)(s0 + r) * CDIM + q * 8);
        }
        // Vt: 1024 lines -> 8 iters
        #pragma unroll
        for (int i = 0; i < 8; i++) {
            int f = tid + i * 128;
            int d = f >> 3, q = f & 7;
            cp_async16(vbase + (uint32_t)(d * VSH + q * 8) * 2u,
                       Vtg + (size_t)d * SEQ + s0 + q * 8);
        }
    };

    issue_tile(0); CP_COMMIT();

    float Oa0[16][4], Oa1[16][4];
    #pragma unroll
    for (int nt = 0; nt < 16; nt++) {
        Oa0[nt][0] = Oa0[nt][1] = Oa0[nt][2] = Oa0[nt][3] = 0.f;
        Oa1[nt][0] = Oa1[nt][1] = Oa1[nt][2] = Oa1[nt][3] = 0.f;
    }
    float m_[2][2] = {{-1e30f, -1e30f}, {-1e30f, -1e30f}};
    float l_[2][2] = {{0.f, 0.f}, {0.f, 0.f}};

    const int NT = SEQ / ABN;   // 32
    for (int kt = 0; kt < NT; kt++) {
        __syncthreads();
        if (kt + 1 < NT) { issue_tile(kt + 1); CP_COMMIT(); }
        if (kt + 1 < NT) { CP_WAIT(1); } else { CP_WAIT(0); }
        __syncthreads();

        const __half* Ks  = smh + Q_HALVES + (kt & 1) * STG_HALVES;
        const __half* Vts = Ks + K_HALVES;

        uint32_t ph[2][8][2];   // packed P A-frags for both 16-row sub-tiles
        float cr[2][2];

        // ---- per 16-row sub-tile: S = Q@K^T, online softmax, pack P ----
        #pragma unroll
        for (int mt = 0; mt < 2; mt++) {
            const int rb = mrow + mt * 16;
            float P[8][4];
            #pragma unroll
            for (int nt = 0; nt < 8; nt++)
                P[nt][0] = P[nt][1] = P[nt][2] = P[nt][3] = 0.f;

            #pragma unroll
            for (int kk = 0; kk < 8; kk++) {
                const int kb = kk * 16;
                uint32_t a0 = *(const uint32_t*)(Qs + (rb + r4)     * QSH + kb + 2 * c4);
                uint32_t a1 = *(const uint32_t*)(Qs + (rb + 8 + r4) * QSH + kb + 2 * c4);
                uint32_t a2 = *(const uint32_t*)(Qs + (rb + r4)     * QSH + kb + 8 + 2 * c4);
                uint32_t a3 = *(const uint32_t*)(Qs + (rb + 8 + r4) * QSH + kb + 8 + 2 * c4);
                #pragma unroll
                for (int nt = 0; nt < 8; nt++) {
                    uint32_t b0 = *(const uint32_t*)(Ks + (nt * 8 + r4) * QSH + kb + 2 * c4);
                    uint32_t b1 = *(const uint32_t*)(Ks + (nt * 8 + r4) * QSH + kb + 8 + 2 * c4);
                    mma_f16(P[nt][0], P[nt][1], P[nt][2], P[nt][3],
                            a0, a1, a2, a3, b0, b1);
                }
            }

            float mx0 = -1e30f, mx1 = -1e30f;
            #pragma unroll
            for (int nt = 0; nt < 8; nt++) {
                mx0 = fmaxf(mx0, fmaxf(P[nt][0], P[nt][1]));
                mx1 = fmaxf(mx1, fmaxf(P[nt][2], P[nt][3]));
            }
            mx0 = fmaxf(mx0, __shfl_xor_sync(0xffffffffu, mx0, 1));
            mx0 = fmaxf(mx0, __shfl_xor_sync(0xffffffffu, mx0, 2));
            mx1 = fmaxf(mx1, __shfl_xor_sync(0xffffffffu, mx1, 1));
            mx1 = fmaxf(mx1, __shfl_xor_sync(0xffffffffu, mx1, 2));

            float mn0 = fmaxf(m_[mt][0], mx0), mn1 = fmaxf(m_[mt][1], mx1);
            cr[mt][0] = __expf(m_[mt][0] - mn0);
            cr[mt][1] = __expf(m_[mt][1] - mn1);
            m_[mt][0] = mn0; m_[mt][1] = mn1;

            float s0s = 0.f, s1s = 0.f;
            #pragma unroll
            for (int nt = 0; nt < 8; nt++) {
                float p0 = __expf(P[nt][0] - mn0);
                float p1 = __expf(P[nt][1] - mn0);
                float p2 = __expf(P[nt][2] - mn1);
                float p3 = __expf(P[nt][3] - mn1);
                ph[mt][nt][0] = pack_h2(p0, p1);
                ph[mt][nt][1] = pack_h2(p2, p3);
                float2 r01 = unpack_h2(ph[mt][nt][0]);
                float2 r23 = unpack_h2(ph[mt][nt][1]);
                s0s += r01.x + r01.y;
                s1s += r23.x + r23.y;
            }
            s0s += __shfl_xor_sync(0xffffffffu, s0s, 1);
            s0s += __shfl_xor_sync(0xffffffffu, s0s, 2);
            s1s += __shfl_xor_sync(0xffffffffu, s1s, 1);
            s1s += __shfl_xor_sync(0xffffffffu, s1s, 2);
            l_[mt][0] = l_[mt][0] * cr[mt][0] + s0s;
            l_[mt][1] = l_[mt][1] * cr[mt][1] + s1s;
        }

        // rescale O accumulators
        #pragma unroll
        for (int nt = 0; nt < 16; nt++) {
            Oa0[nt][0] *= cr[0][0]; Oa0[nt][1] *= cr[0][0];
            Oa0[nt][2] *= cr[0][1]; Oa0[nt][3] *= cr[0][1];
            Oa1[nt][0] *= cr[1][0]; Oa1[nt][1] *= cr[1][0];
            Oa1[nt][2] *= cr[1][1]; Oa1[nt][3] *= cr[1][1];
        }

        // ---- O += P @ V : shared V-fragments for both sub-tiles ----
        #pragma unroll
        for (int kk = 0; kk < 4; kk++) {
            const int kb = kk * 16;
            #pragma unroll
            for (int nt = 0; nt < 16; nt++) {
                uint32_t b0 = *(const uint32_t*)(Vts + (nt * 8 + r4) * VSH + kb + 2 * c4);
                uint32_t b1 = *(const uint32_t*)(Vts + (nt * 8 + r4) * VSH + kb + 8 + 2 * c4);
                mma_f16(Oa0[nt][0], Oa0[nt][1], Oa0[nt][2], Oa0[nt][3],
                        ph[0][2*kk][0], ph[0][2*kk][1], ph[0][2*kk+1][0], ph[0][2*kk+1][1],
                        b0, b1);
                mma_f16(Oa1[nt][0], Oa1[nt][1], Oa1[nt][2], Oa1[nt][3],
                        ph[1][2*kk][0], ph[1][2*kk][1], ph[1][2*kk+1][0], ph[1][2*kk+1][1],
                        b0, b1);
            }
        }
    }

    // epilogue: half(O/l) -> y, both sub-tiles
    #pragma unroll
    for (int mt = 0; mt < 2; mt++) {
        float inv0 = 1.f / l_[mt][0], inv1 = 1.f / l_[mt][1];
        int row0 = t0 + mrow + mt * 16 + r4;
        int row1 = row0 + 8;
        __half* y0 = y + ((size_t)b * SEQ + row0) * CDIM + h * HDIM;
        __half* y1 = y + ((size_t)b * SEQ + row1) * CDIM + h * HDIM;
        #pragma unroll
        for (int nt = 0; nt < 16; nt++) {
            int col = nt * 8 + 2 * c4;
            if (mt == 0) {
                *(uint32_t*)(y0 + col) = pack_h2(Oa0[nt][0] * inv0, Oa0[nt][1] * inv0);
                *(uint32_t*)(y1 + col) = pack_h2(Oa0[nt][2] * inv1, Oa0[nt][3] * inv1);
            } else {
                *(uint32_t*)(y0 + col) = pack_h2(Oa1[nt][0] * inv0, Oa1[nt][1] * inv0);
                *(uint32_t*)(y1 + col) = pack_h2(Oa1[nt][2] * inv1, Oa1[nt][3] * inv1);
            }
        }
    }
}

// ---------------------------------------------------------------------------
extern "C" void kernel_launch(void* const* d_in, const int* in_sizes, int n_in,
                              void* d_out, int out_size)
{
    const float* x     = (const float*)d_in[0];
    const float* cosp  = (const float*)d_in[1];
    const float* sinp  = (const float*)d_in[2];
    const float* Wqkv  = (const float*)d_in[3];
    const float* Wproj = (const float*)d_in[4];
    float* out = (float*)d_out;

    float *qkv = nullptr;
    __half *xh = nullptr, *qh = nullptr, *kh = nullptr, *vth = nullptr, *yh = nullptr;
    __half *WhQkv = nullptr, *WhProj = nullptr;
    cudaGetSymbolAddress((void**)&qkv,    g_qkv);
    cudaGetSymbolAddress((void**)&xh,     g_xh);
    cudaGetSymbolAddress((void**)&qh,     g_qh);
    cudaGetSymbolAddress((void**)&kh,     g_kh);
    cudaGetSymbolAddress((void**)&vth,    g_vth);
    cudaGetSymbolAddress((void**)&yh,     g_yh);
    cudaGetSymbolAddress((void**)&WhQkv,  g_WhQkv);
    cudaGetSymbolAddress((void**)&WhProj, g_WhProj);

    cudaFuncSetAttribute(attn_f16_kernel, cudaFuncAttributeMaxDynamicSharedMemorySize, ATTN_SMEM_BYTES);
    cudaFuncSetAttribute(gemm_f16mma,     cudaFuncAttributeMaxDynamicSharedMemorySize, GSMEM_BYTES);

    // 0) weights: transpose + half; x: half
    transpose_kh<<<dim3(C3 / 32,   CDIM / 32), dim3(32, 8)>>>(Wqkv,  WhQkv,  CDIM, C3);
    transpose_kh<<<dim3(CDIM / 32, CDIM / 32), dim3(32, 8)>>>(Wproj, WhProj, CDIM, CDIM);
    {
        int n4 = MROWS * CDIM / 4;
        convert_h_kernel<<<(n4 + 255) / 256, 256>>>(x, xh, n4);
    }

    // 1) qkv = x @ W_qkv   (fp16 mma, fp32 out; 4-warp CTA)
    gemm_f16mma<<<dim3(C3 / 128, MROWS / 128), 128, GSMEM_BYTES>>>(
        xh, WhQkv, qkv, MROWS, C3, CDIM);

    // 2) RoPE -> qh, kh (half); V -> vth (half, transposed)
    {
        int total = BATCH * SEQ * 2 * NHEAD * 16;
        rope_h_kernel<<<total / 256, 256>>>(qkv, cosp, sinp, qh, kh);
        transpose_vth<<<dim3(SEQ / 32, HDIM / 32, BATCH * NHEAD), dim3(32, 8)>>>(qkv, vth);
    }

    // 3) flash attention (fp16 mma, 4-warp CTA) -> yh
    {
        dim3 grid(SEQ / ABM, NHEAD, BATCH);
        attn_f16_kernel<<<grid, 128, ATTN_SMEM_BYTES>>>(qh, kh, vth, yh);
    }

    // 4) out = y @ W_proj  (fp16 mma, fp32 out)
    gemm_f16mma<<<dim3(CDIM / 128, MROWS / 128), 128, GSMEM_BYTES>>>(
        yh, WhProj, out, MROWS, CDIM, CDIM);
}

// round 12
// speedup vs baseline: 3.1608x; 1.0658x over previous
#include <cuda_runtime.h>
#include <cuda_fp16.h>
#include <cstdint>

// Problem constants
#define BATCH 2
#define SEQ   2048
#define CDIM  2048
#define NHEAD 16
#define HDIM  128
#define C3    (3*CDIM)          // 6144
#define MROWS (BATCH*SEQ)       // 4096
static __device__ __constant__ float kScale = 0.08838834764831845f; // 1/sqrt(128)

// Scratch (device globals: allocation-free)
__device__ float  g_qkv[(size_t)BATCH*SEQ*C3];     // [B,T,3C] fp32 (GEMM1 out)
__device__ __half g_xh [(size_t)BATCH*SEQ*CDIM];   // half(x)
__device__ __half g_qh [(size_t)BATCH*SEQ*CDIM];   // roped+scaled q, half
__device__ __half g_kh [(size_t)BATCH*SEQ*CDIM];   // roped k, half
__device__ __half g_vth[(size_t)BATCH*NHEAD*HDIM*SEQ]; // V^T [b,h,d,t], half
__device__ __half g_yh [(size_t)BATCH*SEQ*CDIM];   // attention out, half
__device__ __half g_WhQkv[(size_t)C3*CDIM];        // W_qkv^T half
__device__ __half g_WhProj[(size_t)CDIM*CDIM];     // W_proj^T half

// ============================================================================
// helpers
// ============================================================================
__device__ __forceinline__ uint32_t smem_to_u32(const void* p) {
    uint32_t a;
    asm("{ .reg .u64 t; cvta.to.shared.u64 t, %1; cvt.u32.u64 %0, t; }" : "=r"(a) : "l"(p));
    return a;
}
__device__ __forceinline__ void cp_async16(uint32_t saddr, const void* g) {
    asm volatile("cp.async.cg.shared.global [%0], [%1], 16;" :: "r"(saddr), "l"(g));
}
#define CP_COMMIT() asm volatile("cp.async.commit_group;" ::: "memory")
#define CP_WAIT(n)  asm volatile("cp.async.wait_group %0;" :: "n"(n) : "memory")

__device__ __forceinline__ uint32_t pack_h2(float a, float b) {
    __half2 h = __floats2half2_rn(a, b);
    return *reinterpret_cast<uint32_t*>(&h);
}
__device__ __forceinline__ float2 unpack_h2(uint32_t u) {
    __half2 h = *reinterpret_cast<__half2*>(&u);
    return __half22float2(h);
}

// ldmatrix: 4 x (8x8 b16) tiles
__device__ __forceinline__ void ldsm_x4(
    uint32_t& r0, uint32_t& r1, uint32_t& r2, uint32_t& r3, uint32_t addr)
{
    asm volatile("ldmatrix.sync.aligned.m8n8.x4.shared.b16 {%0,%1,%2,%3}, [%4];"
                 : "=r"(r0), "=r"(r1), "=r"(r2), "=r"(r3) : "r"(addr));
}

// m16n8k16 fp16 mma, fp32 accumulate
__device__ __forceinline__ void mma_f16(
    float& c0, float& c1, float& c2, float& c3,
    uint32_t a0, uint32_t a1, uint32_t a2, uint32_t a3,
    uint32_t b0, uint32_t b1)
{
    asm volatile(
        "mma.sync.aligned.m16n8k16.row.col.f32.f16.f16.f32 "
        "{%0,%1,%2,%3}, {%4,%5,%6,%7}, {%8,%9}, {%0,%1,%2,%3};"
        : "+f"(c0), "+f"(c1), "+f"(c2), "+f"(c3)
        : "r"(a0), "r"(a1), "r"(a2), "r"(a3), "r"(b0), "r"(b1));
}

// ============================================================================
// convert fp32 -> fp16
// ============================================================================
__global__ __launch_bounds__(256) void convert_h_kernel(
    const float* __restrict__ in, __half* __restrict__ out, int n4)
{
    int i = blockIdx.x * blockDim.x + threadIdx.x;
    if (i < n4) {
        float4 v = ((const float4*)in)[i];
        uint2 o;
        o.x = pack_h2(v.x, v.y);
        o.y = pack_h2(v.z, v.w);
        ((uint2*)out)[i] = o;
    }
}

// ============================================================================
// Transpose + half convert: out[C][R] = half(in[R][C])
// ============================================================================
__global__ __launch_bounds__(256) void transpose_kh(
    const float* __restrict__ in, __half* __restrict__ out, int R, int C)
{
    __shared__ float t[32][33];
    int bx = blockIdx.x * 32, by = blockIdx.y * 32;
    int tx = threadIdx.x, ty = threadIdx.y;
    #pragma unroll
    for (int j = ty; j < 32; j += 8)
        t[j][tx] = in[(size_t)(by + j) * C + bx + tx];
    __syncthreads();
    #pragma unroll
    for (int j = ty; j < 32; j += 8)
        out[(size_t)(bx + j) * R + by + tx] = __float2half_rn(t[tx][j]);
}

// ============================================================================
// Transpose V head slabs: g_vth[(b*H+h)*D + d][t] = half(qkv_v[b,t,h,d])
// ============================================================================
__global__ __launch_bounds__(256) void transpose_vth(
    const float* __restrict__ qkv, __half* __restrict__ vt)
{
    __shared__ float t[32][33];
    int bh = blockIdx.z;
    int b = bh >> 4, h = bh & 15;
    const float* src = qkv + (size_t)b * SEQ * C3 + 2 * CDIM + h * HDIM;
    __half* dst = vt + (size_t)bh * HDIM * SEQ;
    int t0 = blockIdx.x * 32, d0 = blockIdx.y * 32;
    int tx = threadIdx.x, ty = threadIdx.y;
    #pragma unroll
    for (int j = ty; j < 32; j += 8)
        t[j][tx] = src[(size_t)(t0 + j) * C3 + d0 + tx];
    __syncthreads();
    #pragma unroll
    for (int j = ty; j < 32; j += 8)
        dst[(size_t)(d0 + j) * SEQ + t0 + tx] = __float2half_rn(t[tx][j]);
}

// ============================================================================
// FP16 mma.sync GEMM: C[M,N](fp32) = A[M,K] @ Bt[N,K]^T
// 128x128 CTA tile, 256 threads = 8 warps (2M x 4N), warp tile 64x32.
// All fragment loads via ldmatrix.x4. K chunk 64 halves, 2-stage cp.async.
// ============================================================================
#define GKH 64
#define GSTRH 72                                  // halves per smem row
#define TILE_H (128 * GSTRH)                      // 9216 halves per tile
#define STAGE_H (2 * TILE_H)                      // A + B
#define GSMEM_BYTES (2 * STAGE_H * 2)             // 73728 B

__global__ __launch_bounds__(256, 2) void gemm_f16mma(
    const __half* __restrict__ A, const __half* __restrict__ Bt,
    float* __restrict__ C, int M, int N, int K)
{
    extern __shared__ __half smh[];
    const int tid = threadIdx.x;
    const int wid = tid >> 5;
    const int lid = tid & 31;
    const int wm  = wid & 1;        // 0..1  (64 M-rows)
    const int wn  = wid >> 1;       // 0..3  (32 N-cols)
    const int m0  = blockIdx.y * 128;
    const int n0  = blockIdx.x * 128;

    const uint32_t smem_u32 = smem_to_u32(smh);

    // ldmatrix lane offsets (halves):
    // A x4: m0=(r,k) m1=(r+8,k) m2=(r,k+8) m3=(r+8,k+8)
    // B x4: m0=(n,k) m1=(n,k+8) m2=(n+8,k) m3=(n+8,k+8)  (two n-tiles)
    const int grp = lid >> 3, rowin = lid & 7;
    const int aoff_h = (rowin + 8 * (grp & 1)) * GSTRH + (grp >> 1) * 8;
    const int boff_h = (rowin + 8 * (grp >> 1)) * GSTRH + (grp & 1) * 8;
    const uint32_t aBase = smem_u32 + (uint32_t)(aoff_h + wm * 64 * GSTRH) * 2u;
    const uint32_t bBase = smem_u32 + (uint32_t)(TILE_H + boff_h + wn * 32 * GSTRH) * 2u;

    float acc[4][4][4];
    #pragma unroll
    for (int i = 0; i < 4; i++)
        #pragma unroll
        for (int j = 0; j < 4; j++)
            #pragma unroll
            for (int u = 0; u < 4; u++) acc[i][j][u] = 0.f;

    const int nchunk = K / GKH;   // 32

    auto issue = [&](int c, int s) {
        const __half* Ag = A  + (size_t)m0 * K + c * GKH;
        const __half* Bg = Bt + (size_t)n0 * K + c * GKH;
        uint32_t baseA = smem_u32 + (uint32_t)(s * STAGE_H) * 2u;
        uint32_t baseB = baseA + (uint32_t)TILE_H * 2u;
        // each tile: 128 rows x 8 lines = 1024 lines; 256 threads -> 4 iters
        #pragma unroll
        for (int i = 0; i < 4; i++) {
            int f   = tid + i * 256;
            int row = f >> 3;
            int q   = f & 7;
            uint32_t soff = (uint32_t)(row * GSTRH + q * 8) * 2u;
            cp_async16(baseA + soff, Ag + (size_t)row * K + q * 8);
            cp_async16(baseB + soff, Bg + (size_t)row * K + q * 8);
        }
    };

    issue(0, 0);
    CP_COMMIT();

    const int r4 = lid >> 2;
    const int c4 = lid & 3;

    for (int c = 0; c < nchunk; c++) {
        const int s = c & 1;
        if (c + 1 < nchunk) {
            issue(c + 1, s ^ 1);
            CP_COMMIT();
            CP_WAIT(1);
        } else {
            CP_WAIT(0);
        }
        __syncthreads();

        const uint32_t aA = aBase + (uint32_t)(s * STAGE_H) * 2u;
        const uint32_t bA = bBase + (uint32_t)(s * STAGE_H) * 2u;

        #pragma unroll
        for (int kk = 0; kk < 4; kk++) {             // K16 steps
            uint32_t a[4][4], b[4][2];
            #pragma unroll
            for (int mt = 0; mt < 4; mt++)
                ldsm_x4(a[mt][0], a[mt][1], a[mt][2], a[mt][3],
                        aA + (uint32_t)((mt * 16 * GSTRH + kk * 16) * 2));
            #pragma unroll
            for (int np = 0; np < 2; np++)
                ldsm_x4(b[2*np][0], b[2*np][1], b[2*np+1][0], b[2*np+1][1],
                        bA + (uint32_t)((np * 16 * GSTRH + kk * 16) * 2));
            #pragma unroll
            for (int mt = 0; mt < 4; mt++)
                #pragma unroll
                for (int nt = 0; nt < 4; nt++)
                    mma_f16(acc[mt][nt][0], acc[mt][nt][1], acc[mt][nt][2], acc[mt][nt][3],
                            a[mt][0], a[mt][1], a[mt][2], a[mt][3],
                            b[nt][0], b[nt][1]);
        }
        __syncthreads();
    }

    const int c2l = 2 * c4;
    #pragma unroll
    for (int mt = 0; mt < 4; mt++) {
        int row = m0 + wm * 64 + mt * 16 + r4;
        #pragma unroll
        for (int nt = 0; nt < 4; nt++) {
            int col = n0 + wn * 32 + nt * 8 + c2l;
            *(float2*)(C + (size_t)row * N + col) =
                make_float2(acc[mt][nt][0], acc[mt][nt][1]);
            *(float2*)(C + (size_t)(row + 8) * N + col) =
                make_float2(acc[mt][nt][2], acc[mt][nt][3]);
        }
    }
}

// ---------------------------------------------------------------------------
// RoPE: read qkv fp32, write half q (scaled by 1/sqrt(d)) and half k.
// ---------------------------------------------------------------------------
__global__ __launch_bounds__(256) void rope_h_kernel(
    const float* __restrict__ qkv, const float* __restrict__ cosp,
    const float* __restrict__ sinp, __half* __restrict__ qh,
    __half* __restrict__ kh)
{
    int idx = blockIdx.x * blockDim.x + threadIdx.x;
    int d4 = idx & 15;
    int h  = (idx >> 4) & (NHEAD - 1);
    int qk = (idx >> 8) & 1;
    int t  = (idx >> 9) & (SEQ - 1);
    int b  = idx >> 20;
    int d  = d4 * 4;

    const float* base = qkv + ((size_t)(b * SEQ + t)) * C3 + qk * CDIM + h * HDIM;
    float4 x1 = *(const float4*)(base + d);
    float4 x2 = *(const float4*)(base + d + 64);
    float4 c1 = *(const float4*)(cosp + t * HDIM + d);
    float4 s1 = *(const float4*)(sinp + t * HDIM + d);
    float4 c2 = *(const float4*)(cosp + t * HDIM + d + 64);
    float4 s2 = *(const float4*)(sinp + t * HDIM + d + 64);

    float sc = (qk == 0) ? kScale : 1.f;
    __half* outp = (qk == 0 ? qh : kh) + ((size_t)(b * SEQ + t)) * CDIM + h * HDIM;
    uint2 o1, o2;
    o1.x = pack_h2((x1.x * c1.x - x2.x * s1.x) * sc, (x1.y * c1.y - x2.y * s1.y) * sc);
    o1.y = pack_h2((x1.z * c1.z - x2.z * s1.z) * sc, (x1.w * c1.w - x2.w * s1.w) * sc);
    o2.x = pack_h2((x2.x * c2.x + x1.x * s2.x) * sc, (x2.y * c2.y + x1.y * s2.y) * sc);
    o2.y = pack_h2((x2.z * c2.z + x1.z * s2.z) * sc, (x2.w * c2.w + x1.w * s2.w) * sc);
    *(uint2*)(outp + d)      = o1;
    *(uint2*)(outp + d + 64) = o2;
}

// ---------------------------------------------------------------------------
// Flash attention fp16: BM=128, BN=64, D=128, m16n8k16 mma, ldmatrix frags.
// 128 threads = 4 warps; warp w owns 32 q-rows (2 x 16-row sub-tiles).
// cp.async double-buffered K/Vt; P stays in registers (C frag == A frag).
// ---------------------------------------------------------------------------
#define ABM 128
#define ABN 64
#define QSH 136                 // Q/K smem stride (halves)
#define VSH 72                  // Vt smem stride (halves)
#define Q_HALVES (128 * QSH)    // 17408
#define K_HALVES (64 * QSH)     // 8704
#define V_HALVES (128 * VSH)    // 9216
#define STG_HALVES (K_HALVES + V_HALVES)          // 17920
#define ATTN_SMEM_BYTES ((Q_HALVES + 2 * STG_HALVES) * 2)  // 106496

__global__ __launch_bounds__(128, 2) void attn_f16_kernel(
    const __half* __restrict__ qh, const __half* __restrict__ kh,
    const __half* __restrict__ vt, __half* __restrict__ y)
{
    extern __shared__ __half smh[];
    const int tid = threadIdx.x;
    const int wid = tid >> 5;
    const int lid = tid & 31;
    const int r4  = lid >> 2;       // 0..7
    const int c4  = lid & 3;        // 0..3
    const int h   = blockIdx.y;
    const int b   = blockIdx.z;
    const int t0  = blockIdx.x * ABM;
    const int mrow = wid * 32;      // warp owns rows [mrow, mrow+32)

    const uint32_t smem_u32 = smem_to_u32(smh);

    // ldmatrix lane offsets
    const int grp = lid >> 3, rowin = lid & 7;
    const int qoff_h = (rowin + 8 * (grp & 1)) * QSH + (grp >> 1) * 8;   // A pattern
    const int koff_h = (rowin + 8 * (grp >> 1)) * QSH + (grp & 1) * 8;   // B pattern
    const int voff_h = (rowin + 8 * (grp >> 1)) * VSH + (grp & 1) * 8;   // B pattern
    const uint32_t qBase = smem_u32 + (uint32_t)(qoff_h + mrow * QSH) * 2u;

    const __half* Qg  = qh + ((size_t)b * SEQ) * CDIM + h * HDIM;
    const __half* Kg  = kh + ((size_t)b * SEQ) * CDIM + h * HDIM;
    const __half* Vtg = vt + (size_t)(b * NHEAD + h) * HDIM * SEQ;

    // Q tile: 2048 lines; 128 threads -> 16 iters
    #pragma unroll
    for (int i = 0; i < 16; i++) {
        int f = tid + i * 128;
        int r = f >> 4, q = f & 15;
        cp_async16(smem_u32 + (uint32_t)(r * QSH + q * 8) * 2u,
                   Qg + (size_t)(t0 + r) * CDIM + q * 8);
    }
    CP_COMMIT();

    auto issue_tile = [&](int kt) {
        const int s = kt & 1;
        const int s0 = kt * ABN;
        uint32_t kbase = smem_u32 + (uint32_t)(Q_HALVES + s * STG_HALVES) * 2u;
        uint32_t vbase = kbase + (uint32_t)K_HALVES * 2u;
        #pragma unroll
        for (int i = 0; i < 8; i++) {
            int f = tid + i * 128;
            int r = f >> 4, q = f & 15;
            cp_async16(kbase + (uint32_t)(r * QSH + q * 8) * 2u,
                       Kg + (size_t)(s0 + r) * CDIM + q * 8);
        }
        #pragma unroll
        for (int i = 0; i < 8; i++) {
            int f = tid + i * 128;
            int d = f >> 3, q = f & 7;
            cp_async16(vbase + (uint32_t)(d * VSH + q * 8) * 2u,
                       Vtg + (size_t)d * SEQ + s0 + q * 8);
        }
    };

    issue_tile(0); CP_COMMIT();

    float Oa0[16][4], Oa1[16][4];
    #pragma unroll
    for (int nt = 0; nt < 16; nt++) {
        Oa0[nt][0] = Oa0[nt][1] = Oa0[nt][2] = Oa0[nt][3] = 0.f;
        Oa1[nt][0] = Oa1[nt][1] = Oa1[nt][2] = Oa1[nt][3] = 0.f;
    }
    float m_[2][2] = {{-1e30f, -1e30f}, {-1e30f, -1e30f}};
    float l_[2][2] = {{0.f, 0.f}, {0.f, 0.f}};

    const int NT = SEQ / ABN;   // 32
    for (int kt = 0; kt < NT; kt++) {
        __syncthreads();
        if (kt + 1 < NT) { issue_tile(kt + 1); CP_COMMIT(); }
        if (kt + 1 < NT) { CP_WAIT(1); } else { CP_WAIT(0); }
        __syncthreads();

        const uint32_t kA = smem_u32 +
            (uint32_t)(Q_HALVES + (kt & 1) * STG_HALVES + koff_h) * 2u;
        const uint32_t vA = smem_u32 +
            (uint32_t)(Q_HALVES + (kt & 1) * STG_HALVES + K_HALVES + voff_h) * 2u;

        uint32_t ph[2][8][2];   // packed P A-frags for both 16-row sub-tiles
        float cr[2][2];

        // ---- per 16-row sub-tile: S = Q@K^T, online softmax, pack P ----
        #pragma unroll
        for (int mt = 0; mt < 2; mt++) {
            float P[8][4];
            #pragma unroll
            for (int nt = 0; nt < 8; nt++)
                P[nt][0] = P[nt][1] = P[nt][2] = P[nt][3] = 0.f;

            #pragma unroll
            for (int kk = 0; kk < 8; kk++) {
                uint32_t a0, a1, a2, a3;
                ldsm_x4(a0, a1, a2, a3,
                        qBase + (uint32_t)((mt * 16 * QSH + kk * 16) * 2));
                uint32_t bb[8][2];
                #pragma unroll
                for (int np = 0; np < 4; np++)
                    ldsm_x4(bb[2*np][0], bb[2*np][1], bb[2*np+1][0], bb[2*np+1][1],
                            kA + (uint32_t)((np * 16 * QSH + kk * 16) * 2));
                #pragma unroll
                for (int nt = 0; nt < 8; nt++)
                    mma_f16(P[nt][0], P[nt][1], P[nt][2], P[nt][3],
                            a0, a1, a2, a3, bb[nt][0], bb[nt][1]);
            }

            float mx0 = -1e30f, mx1 = -1e30f;
            #pragma unroll
            for (int nt = 0; nt < 8; nt++) {
                mx0 = fmaxf(mx0, fmaxf(P[nt][0], P[nt][1]));
                mx1 = fmaxf(mx1, fmaxf(P[nt][2], P[nt][3]));
            }
            mx0 = fmaxf(mx0, __shfl_xor_sync(0xffffffffu, mx0, 1));
            mx0 = fmaxf(mx0, __shfl_xor_sync(0xffffffffu, mx0, 2));
            mx1 = fmaxf(mx1, __shfl_xor_sync(0xffffffffu, mx1, 1));
            mx1 = fmaxf(mx1, __shfl_xor_sync(0xffffffffu, mx1, 2));

            float mn0 = fmaxf(m_[mt][0], mx0), mn1 = fmaxf(m_[mt][1], mx1);
            cr[mt][0] = __expf(m_[mt][0] - mn0);
            cr[mt][1] = __expf(m_[mt][1] - mn1);
            m_[mt][0] = mn0; m_[mt][1] = mn1;

            float s0s = 0.f, s1s = 0.f;
            #pragma unroll
            for (int nt = 0; nt < 8; nt++) {
                float p0 = __expf(P[nt][0] - mn0);
                float p1 = __expf(P[nt][1] - mn0);
                float p2 = __expf(P[nt][2] - mn1);
                float p3 = __expf(P[nt][3] - mn1);
                ph[mt][nt][0] = pack_h2(p0, p1);
                ph[mt][nt][1] = pack_h2(p2, p3);
                float2 r01 = unpack_h2(ph[mt][nt][0]);
                float2 r23 = unpack_h2(ph[mt][nt][1]);
                s0s += r01.x + r01.y;
                s1s += r23.x + r23.y;
            }
            s0s += __shfl_xor_sync(0xffffffffu, s0s, 1);
            s0s += __shfl_xor_sync(0xffffffffu, s0s, 2);
            s1s += __shfl_xor_sync(0xffffffffu, s1s, 1);
            s1s += __shfl_xor_sync(0xffffffffu, s1s, 2);
            l_[mt][0] = l_[mt][0] * cr[mt][0] + s0s;
            l_[mt][1] = l_[mt][1] * cr[mt][1] + s1s;
        }

        // rescale O accumulators
        #pragma unroll
        for (int nt = 0; nt < 16; nt++) {
            Oa0[nt][0] *= cr[0][0]; Oa0[nt][1] *= cr[0][0];
            Oa0[nt][2] *= cr[0][1]; Oa0[nt][3] *= cr[0][1];
            Oa1[nt][0] *= cr[1][0]; Oa1[nt][1] *= cr[1][0];
            Oa1[nt][2] *= cr[1][1]; Oa1[nt][3] *= cr[1][1];
        }

        // ---- O += P @ V : V frags via ldmatrix, shared by both sub-tiles ----
        #pragma unroll
        for (int kk = 0; kk < 4; kk++) {
            #pragma unroll
            for (int np = 0; np < 8; np++) {
                uint32_t b00, b01, b10, b11;
                ldsm_x4(b00, b01, b10, b11,
                        vA + (uint32_t)((np * 16 * VSH + kk * 16) * 2));
                mma_f16(Oa0[2*np][0], Oa0[2*np][1], Oa0[2*np][2], Oa0[2*np][3],
                        ph[0][2*kk][0], ph[0][2*kk][1], ph[0][2*kk+1][0], ph[0][2*kk+1][1],
                        b00, b01);
                mma_f16(Oa1[2*np][0], Oa1[2*np][1], Oa1[2*np][2], Oa1[2*np][3],
                        ph[1][2*kk][0], ph[1][2*kk][1], ph[1][2*kk+1][0], ph[1][2*kk+1][1],
                        b00, b01);
                mma_f16(Oa0[2*np+1][0], Oa0[2*np+1][1], Oa0[2*np+1][2], Oa0[2*np+1][3],
                        ph[0][2*kk][0], ph[0][2*kk][1], ph[0][2*kk+1][0], ph[0][2*kk+1][1],
                        b10, b11);
                mma_f16(Oa1[2*np+1][0], Oa1[2*np+1][1], Oa1[2*np+1][2], Oa1[2*np+1][3],
                        ph[1][2*kk][0], ph[1][2*kk][1], ph[1][2*kk+1][0], ph[1][2*kk+1][1],
                        b10, b11);
            }
        }
    }

    // epilogue: half(O/l) -> y, both sub-tiles
    #pragma unroll
    for (int mt = 0; mt < 2; mt++) {
        float inv0 = 1.f / l_[mt][0], inv1 = 1.f / l_[mt][1];
        int row0 = t0 + mrow + mt * 16 + r4;
        int row1 = row0 + 8;
        __half* y0 = y + ((size_t)b * SEQ + row0) * CDIM + h * HDIM;
        __half* y1 = y + ((size_t)b * SEQ + row1) * CDIM + h * HDIM;
        #pragma unroll
        for (int nt = 0; nt < 16; nt++) {
            int col = nt * 8 + 2 * c4;
            if (mt == 0) {
                *(uint32_t*)(y0 + col) = pack_h2(Oa0[nt][0] * inv0, Oa0[nt][1] * inv0);
                *(uint32_t*)(y1 + col) = pack_h2(Oa0[nt][2] * inv1, Oa0[nt][3] * inv1);
            } else {
                *(uint32_t*)(y0 + col) = pack_h2(Oa1[nt][0] * inv0, Oa1[nt][1] * inv0);
                *(uint32_t*)(y1 + col) = pack_h2(Oa1[nt][2] * inv1, Oa1[nt][3] * inv1);
            }
        }
    }
}

// ---------------------------------------------------------------------------
extern "C" void kernel_launch(void* const* d_in, const int* in_sizes, int n_in,
                              void* d_out, int out_size)
{
    const float* x     = (const float*)d_in[0];
    const float* cosp  = (const float*)d_in[1];
    const float* sinp  = (const float*)d_in[2];
    const float* Wqkv  = (const float*)d_in[3];
    const float* Wproj = (const float*)d_in[4];
    float* out = (float*)d_out;

    float *qkv = nullptr;
    __half *xh = nullptr, *qh = nullptr, *kh = nullptr, *vth = nullptr, *yh = nullptr;
    __half *WhQkv = nullptr, *WhProj = nullptr;
    cudaGetSymbolAddress((void**)&qkv,    g_qkv);
    cudaGetSymbolAddress((void**)&xh,     g_xh);
    cudaGetSymbolAddress((void**)&qh,     g_qh);
    cudaGetSymbolAddress((void**)&kh,     g_kh);
    cudaGetSymbolAddress((void**)&vth,    g_vth);
    cudaGetSymbolAddress((void**)&yh,     g_yh);
    cudaGetSymbolAddress((void**)&WhQkv,  g_WhQkv);
    cudaGetSymbolAddress((void**)&WhProj, g_WhProj);

    cudaFuncSetAttribute(attn_f16_kernel, cudaFuncAttributeMaxDynamicSharedMemorySize, ATTN_SMEM_BYTES);
    cudaFuncSetAttribute(gemm_f16mma,     cudaFuncAttributeMaxDynamicSharedMemorySize, GSMEM_BYTES);

    // 0) weights: transpose + half; x: half
    transpose_kh<<<dim3(C3 / 32,   CDIM / 32), dim3(32, 8)>>>(Wqkv,  WhQkv,  CDIM, C3);
    transpose_kh<<<dim3(CDIM / 32, CDIM / 32), dim3(32, 8)>>>(Wproj, WhProj, CDIM, CDIM);
    {
        int n4 = MROWS * CDIM / 4;
        convert_h_kernel<<<(n4 + 255) / 256, 256>>>(x, xh, n4);
    }

    // 1) qkv = x @ W_qkv   (fp16 mma + ldmatrix, fp32 out)
    gemm_f16mma<<<dim3(C3 / 128, MROWS / 128), 256, GSMEM_BYTES>>>(
        xh, WhQkv, qkv, MROWS, C3, CDIM);

    // 2) RoPE -> qh, kh (half); V -> vth (half, transposed)
    {
        int total = BATCH * SEQ * 2 * NHEAD * 16;
        rope_h_kernel<<<total / 256, 256>>>(qkv, cosp, sinp, qh, kh);
        transpose_vth<<<dim3(SEQ / 32, HDIM / 32, BATCH * NHEAD), dim3(32, 8)>>>(qkv, vth);
    }

    // 3) flash attention (fp16 mma + ldmatrix) -> yh
    {
        dim3 grid(SEQ / ABM, NHEAD, BATCH);
        attn_f16_kernel<<<grid, 128, ATTN_SMEM_BYTES>>>(qh, kh, vth, yh);
    }

    // 4) out = y @ W_proj  (fp16 mma + ldmatrix, fp32 out)
    gemm_f16mma<<<dim3(CDIM / 128, MROWS / 128), 256, GSMEM_BYTES>>>(
        yh, WhProj, out, MROWS, CDIM, CDIM);
}

// round 13
// speedup vs baseline: 3.3035x; 1.0451x over previous
#include <cuda_runtime.h>
#include <cuda_fp16.h>
#include <cstdint>

// Problem constants
#define BATCH 2
#define SEQ   2048
#define CDIM  2048
#define NHEAD 16
#define HDIM  128
#define C3    (3*CDIM)          // 6144
#define MROWS (BATCH*SEQ)       // 4096
static __device__ __constant__ float kScale = 0.08838834764831845f; // 1/sqrt(128)

// Scratch (device globals: allocation-free)
__device__ __half g_xh [(size_t)BATCH*SEQ*CDIM];   // half(x)
__device__ __half g_qh [(size_t)BATCH*SEQ*CDIM];   // roped+scaled q, half
__device__ __half g_kh [(size_t)BATCH*SEQ*CDIM];   // roped k, half
__device__ __half g_vth[(size_t)BATCH*NHEAD*HDIM*SEQ]; // V^T [b,h,d,t], half
__device__ __half g_yh [(size_t)BATCH*SEQ*CDIM];   // attention out, half
__device__ __half g_WhQkv[(size_t)C3*CDIM];        // W_qkv^T half
__device__ __half g_WhProj[(size_t)CDIM*CDIM];     // W_proj^T half

// ============================================================================
// helpers
// ============================================================================
__device__ __forceinline__ uint32_t smem_to_u32(const void* p) {
    uint32_t a;
    asm("{ .reg .u64 t; cvta.to.shared.u64 t, %1; cvt.u32.u64 %0, t; }" : "=r"(a) : "l"(p));
    return a;
}
__device__ __forceinline__ void cp_async16(uint32_t saddr, const void* g) {
    asm volatile("cp.async.cg.shared.global [%0], [%1], 16;" :: "r"(saddr), "l"(g));
}
#define CP_COMMIT() asm volatile("cp.async.commit_group;" ::: "memory")
#define CP_WAIT(n)  asm volatile("cp.async.wait_group %0;" :: "n"(n) : "memory")

__device__ __forceinline__ uint32_t pack_h2(float a, float b) {
    __half2 h = __floats2half2_rn(a, b);
    return *reinterpret_cast<uint32_t*>(&h);
}
__device__ __forceinline__ float2 unpack_h2(uint32_t u) {
    __half2 h = *reinterpret_cast<__half2*>(&u);
    return __half22float2(h);
}

// ldmatrix: 4 x (8x8 b16) tiles
__device__ __forceinline__ void ldsm_x4(
    uint32_t& r0, uint32_t& r1, uint32_t& r2, uint32_t& r3, uint32_t addr)
{
    asm volatile("ldmatrix.sync.aligned.m8n8.x4.shared.b16 {%0,%1,%2,%3}, [%4];"
                 : "=r"(r0), "=r"(r1), "=r"(r2), "=r"(r3) : "r"(addr));
}

// m16n8k16 fp16 mma, fp32 accumulate
__device__ __forceinline__ void mma_f16(
    float& c0, float& c1, float& c2, float& c3,
    uint32_t a0, uint32_t a1, uint32_t a2, uint32_t a3,
    uint32_t b0, uint32_t b1)
{
    asm volatile(
        "mma.sync.aligned.m16n8k16.row.col.f32.f16.f16.f32 "
        "{%0,%1,%2,%3}, {%4,%5,%6,%7}, {%8,%9}, {%0,%1,%2,%3};"
        : "+f"(c0), "+f"(c1), "+f"(c2), "+f"(c3)
        : "r"(a0), "r"(a1), "r"(a2), "r"(a3), "r"(b0), "r"(b1));
}

// ============================================================================
// convert fp32 -> fp16
// ============================================================================
__global__ __launch_bounds__(256) void convert_h_kernel(
    const float* __restrict__ in, __half* __restrict__ out, int n4)
{
    int i = blockIdx.x * blockDim.x + threadIdx.x;
    if (i < n4) {
        float4 v = ((const float4*)in)[i];
        uint2 o;
        o.x = pack_h2(v.x, v.y);
        o.y = pack_h2(v.z, v.w);
        ((uint2*)out)[i] = o;
    }
}

// ============================================================================
// Transpose + half convert: out[C][R] = half(in[R][C])
// ============================================================================
__global__ __launch_bounds__(256) void transpose_kh(
    const float* __restrict__ in, __half* __restrict__ out, int R, int C)
{
    __shared__ float t[32][33];
    int bx = blockIdx.x * 32, by = blockIdx.y * 32;
    int tx = threadIdx.x, ty = threadIdx.y;
    #pragma unroll
    for (int j = ty; j < 32; j += 8)
        t[j][tx] = in[(size_t)(by + j) * C + bx + tx];
    __syncthreads();
    #pragma unroll
    for (int j = ty; j < 32; j += 8)
        out[(size_t)(bx + j) * R + by + tx] = __float2half_rn(t[tx][j]);
}

// ============================================================================
// Shared GEMM config
// ============================================================================
#define GKH 64
#define GSTRH 72                                  // halves per smem row
#define TILE_H (128 * GSTRH)                      // 9216 halves per tile
#define STAGE_H (2 * TILE_H)                      // A + B
#define GSMEM_BYTES (2 * STAGE_H * 2)             // 73728 B
#define EPI_STRIDE 132                            // fp32 epilogue smem stride

// Mainloop body shared by both GEMMs (as a macro to keep one source of truth)
// Produces acc[4][4][4] from A (row-major) and Bt (row-major), K halves.

// ============================================================================
// Fused GEMM1: qkv = x @ W_qkv^T with RoPE/scale/half epilogue.
// N-tile (128) == one (type, head) slab. type 0->q(+rope,scale), 1->k(+rope),
// 2->v (transpose into vth). Epilogue stages fp32 tile through smem.
// ============================================================================
__global__ __launch_bounds__(256, 2) void gemm_qkv_fused(
    const __half* __restrict__ A, const __half* __restrict__ Bt,
    const float* __restrict__ cosp, const float* __restrict__ sinp,
    __half* __restrict__ qh, __half* __restrict__ kh, __half* __restrict__ vth)
{
    extern __shared__ __half smh[];
    const int tid = threadIdx.x;
    const int wid = tid >> 5;
    const int lid = tid & 31;
    const int wm  = wid & 1;
    const int wn  = wid >> 1;
    const int m0  = blockIdx.y * 128;
    const int n0  = blockIdx.x * 128;
    const int K   = CDIM;

    const uint32_t smem_u32 = smem_to_u32(smh);
    const int grp = lid >> 3, rowin = lid & 7;
    const int aoff_h = (rowin + 8 * (grp & 1)) * GSTRH + (grp >> 1) * 8;
    const int boff_h = (rowin + 8 * (grp >> 1)) * GSTRH + (grp & 1) * 8;
    const uint32_t aBase = smem_u32 + (uint32_t)(aoff_h + wm * 64 * GSTRH) * 2u;
    const uint32_t bBase = smem_u32 + (uint32_t)(TILE_H + boff_h + wn * 32 * GSTRH) * 2u;

    float acc[4][4][4];
    #pragma unroll
    for (int i = 0; i < 4; i++)
        #pragma unroll
        for (int j = 0; j < 4; j++)
            #pragma unroll
            for (int u = 0; u < 4; u++) acc[i][j][u] = 0.f;

    const int nchunk = K / GKH;

    auto issue = [&](int c, int s) {
        const __half* Ag = A  + (size_t)m0 * K + c * GKH;
        const __half* Bg = Bt + (size_t)n0 * K + c * GKH;
        uint32_t baseA = smem_u32 + (uint32_t)(s * STAGE_H) * 2u;
        uint32_t baseB = baseA + (uint32_t)TILE_H * 2u;
        #pragma unroll
        for (int i = 0; i < 4; i++) {
            int f   = tid + i * 256;
            int row = f >> 3;
            int q   = f & 7;
            uint32_t soff = (uint32_t)(row * GSTRH + q * 8) * 2u;
            cp_async16(baseA + soff, Ag + (size_t)row * K + q * 8);
            cp_async16(baseB + soff, Bg + (size_t)row * K + q * 8);
        }
    };

    issue(0, 0);
    CP_COMMIT();

    const int r4 = lid >> 2;
    const int c4 = lid & 3;

    for (int c = 0; c < nchunk; c++) {
        const int s = c & 1;
        if (c + 1 < nchunk) { issue(c + 1, s ^ 1); CP_COMMIT(); CP_WAIT(1); }
        else                { CP_WAIT(0); }
        __syncthreads();

        const uint32_t aA = aBase + (uint32_t)(s * STAGE_H) * 2u;
        const uint32_t bA = bBase + (uint32_t)(s * STAGE_H) * 2u;

        #pragma unroll
        for (int kk = 0; kk < 4; kk++) {
            uint32_t a[4][4], b[4][2];
            #pragma unroll
            for (int mt = 0; mt < 4; mt++)
                ldsm_x4(a[mt][0], a[mt][1], a[mt][2], a[mt][3],
                        aA + (uint32_t)((mt * 16 * GSTRH + kk * 16) * 2));
            #pragma unroll
            for (int np = 0; np < 2; np++)
                ldsm_x4(b[2*np][0], b[2*np][1], b[2*np+1][0], b[2*np+1][1],
                        bA + (uint32_t)((np * 16 * GSTRH + kk * 16) * 2));
            #pragma unroll
            for (int mt = 0; mt < 4; mt++)
                #pragma unroll
                for (int nt = 0; nt < 4; nt++)
                    mma_f16(acc[mt][nt][0], acc[mt][nt][1], acc[mt][nt][2], acc[mt][nt][3],
                            a[mt][0], a[mt][1], a[mt][2], a[mt][3],
                            b[nt][0], b[nt][1]);
        }
        __syncthreads();
    }

    // ---- fused epilogue: stage fp32 tile in smem (stages are dead now) ----
    float* sf = reinterpret_cast<float*>(smh);   // [128][EPI_STRIDE]
    #pragma unroll
    for (int mt = 0; mt < 4; mt++) {
        int row = wm * 64 + mt * 16 + r4;
        #pragma unroll
        for (int nt = 0; nt < 4; nt++) {
            int col = wn * 32 + nt * 8 + 2 * c4;
            sf[row * EPI_STRIDE + col]           = acc[mt][nt][0];
            sf[row * EPI_STRIDE + col + 1]       = acc[mt][nt][1];
            sf[(row + 8) * EPI_STRIDE + col]     = acc[mt][nt][2];
            sf[(row + 8) * EPI_STRIDE + col + 1] = acc[mt][nt][3];
        }
    }
    __syncthreads();

    const int type = n0 >> 11;           // 0=q, 1=k, 2=v
    const int h    = (n0 & 2047) >> 7;   // head
    const int b    = m0 >> 11;           // batch
    const int tbase = m0 & 2047;         // seq offset

    if (type < 2) {
        // RoPE + half: pairs (d, d+64), 2 consecutive d per thread
        __half* outg = (type == 0) ? qh : kh;
        const float sc = (type == 0) ? kScale : 1.f;
        #pragma unroll
        for (int i = 0; i < 16; i++) {
            int idx = tid + i * 256;       // 0..4095
            int tl  = idx >> 5;            // 0..127
            int dp  = (idx & 31) * 2;      // 0,2,..,62
            float2 x1 = *(const float2*)&sf[tl * EPI_STRIDE + dp];
            float2 x2 = *(const float2*)&sf[tl * EPI_STRIDE + dp + 64];
            int t = tbase + tl;
            float2 c1 = *(const float2*)(cosp + t * HDIM + dp);
            float2 s1 = *(const float2*)(sinp + t * HDIM + dp);
            float2 c2 = *(const float2*)(cosp + t * HDIM + dp + 64);
            float2 s2 = *(const float2*)(sinp + t * HDIM + dp + 64);
            __half* o = outg + ((size_t)(b * SEQ + t)) * CDIM + h * HDIM;
            *(uint32_t*)(o + dp) = pack_h2((x1.x * c1.x - x2.x * s1.x) * sc,
                                           (x1.y * c1.y - x2.y * s1.y) * sc);
            *(uint32_t*)(o + dp + 64) = pack_h2((x2.x * c2.x + x1.x * s2.x) * sc,
                                                (x2.y * c2.y + x1.y * s2.y) * sc);
        }
    } else {
        // V transpose: thread owns d = tid>>1, t-half = (tid&1)*64
        int d  = tid >> 1;
        int th = (tid & 1) * 64;
        __half* dst = vth + ((size_t)(b * NHEAD + h) * HDIM + d) * SEQ + tbase + th;
        #pragma unroll
        for (int j = 0; j < 16; j++) {
            float v0 = sf[(th + 4 * j + 0) * EPI_STRIDE + d];
            float v1 = sf[(th + 4 * j + 1) * EPI_STRIDE + d];
            float v2 = sf[(th + 4 * j + 2) * EPI_STRIDE + d];
            float v3 = sf[(th + 4 * j + 3) * EPI_STRIDE + d];
            uint2 o;
            o.x = pack_h2(v0, v1);
            o.y = pack_h2(v2, v3);
            *(uint2*)(dst + 4 * j) = o;
        }
    }
}

// ============================================================================
// Plain FP16 GEMM (proj): C[M,N](fp32) = A[M,K] @ Bt[N,K]^T
// ============================================================================
__global__ __launch_bounds__(256, 2) void gemm_f16mma(
    const __half* __restrict__ A, const __half* __restrict__ Bt,
    float* __restrict__ C, int M, int N, int K)
{
    extern __shared__ __half smh[];
    const int tid = threadIdx.x;
    const int wid = tid >> 5;
    const int lid = tid & 31;
    const int wm  = wid & 1;
    const int wn  = wid >> 1;
    const int m0  = blockIdx.y * 128;
    const int n0  = blockIdx.x * 128;

    const uint32_t smem_u32 = smem_to_u32(smh);
    const int grp = lid >> 3, rowin = lid & 7;
    const int aoff_h = (rowin + 8 * (grp & 1)) * GSTRH + (grp >> 1) * 8;
    const int boff_h = (rowin + 8 * (grp >> 1)) * GSTRH + (grp & 1) * 8;
    const uint32_t aBase = smem_u32 + (uint32_t)(aoff_h + wm * 64 * GSTRH) * 2u;
    const uint32_t bBase = smem_u32 + (uint32_t)(TILE_H + boff_h + wn * 32 * GSTRH) * 2u;

    float acc[4][4][4];
    #pragma unroll
    for (int i = 0; i < 4; i++)
        #pragma unroll
        for (int j = 0; j < 4; j++)
            #pragma unroll
            for (int u = 0; u < 4; u++) acc[i][j][u] = 0.f;

    const int nchunk = K / GKH;

    auto issue = [&](int c, int s) {
        const __half* Ag = A  + (size_t)m0 * K + c * GKH;
        const __half* Bg = Bt + (size_t)n0 * K + c * GKH;
        uint32_t baseA = smem_u32 + (uint32_t)(s * STAGE_H) * 2u;
        uint32_t baseB = baseA + (uint32_t)TILE_H * 2u;
        #pragma unroll
        for (int i = 0; i < 4; i++) {
            int f   = tid + i * 256;
            int row = f >> 3;
            int q   = f & 7;
            uint32_t soff = (uint32_t)(row * GSTRH + q * 8) * 2u;
            cp_async16(baseA + soff, Ag + (size_t)row * K + q * 8);
            cp_async16(baseB + soff, Bg + (size_t)row * K + q * 8);
        }
    };

    issue(0, 0);
    CP_COMMIT();

    const int r4 = lid >> 2;
    const int c4 = lid & 3;

    for (int c = 0; c < nchunk; c++) {
        const int s = c & 1;
        if (c + 1 < nchunk) { issue(c + 1, s ^ 1); CP_COMMIT(); CP_WAIT(1); }
        else                { CP_WAIT(0); }
        __syncthreads();

        const uint32_t aA = aBase + (uint32_t)(s * STAGE_H) * 2u;
        const uint32_t bA = bBase + (uint32_t)(s * STAGE_H) * 2u;

        #pragma unroll
        for (int kk = 0; kk < 4; kk++) {
            uint32_t a[4][4], b[4][2];
            #pragma unroll
            for (int mt = 0; mt < 4; mt++)
                ldsm_x4(a[mt][0], a[mt][1], a[mt][2], a[mt][3],
                        aA + (uint32_t)((mt * 16 * GSTRH + kk * 16) * 2));
            #pragma unroll
            for (int np = 0; np < 2; np++)
                ldsm_x4(b[2*np][0], b[2*np][1], b[2*np+1][0], b[2*np+1][1],
                        bA + (uint32_t)((np * 16 * GSTRH + kk * 16) * 2));
            #pragma unroll
            for (int mt = 0; mt < 4; mt++)
                #pragma unroll
                for (int nt = 0; nt < 4; nt++)
                    mma_f16(acc[mt][nt][0], acc[mt][nt][1], acc[mt][nt][2], acc[mt][nt][3],
                            a[mt][0], a[mt][1], a[mt][2], a[mt][3],
                            b[nt][0], b[nt][1]);
        }
        __syncthreads();
    }

    const int c2l = 2 * c4;
    #pragma unroll
    for (int mt = 0; mt < 4; mt++) {
        int row = m0 + wm * 64 + mt * 16 + r4;
        #pragma unroll
        for (int nt = 0; nt < 4; nt++) {
            int col = n0 + wn * 32 + nt * 8 + c2l;
            *(float2*)(C + (size_t)row * N + col) =
                make_float2(acc[mt][nt][0], acc[mt][nt][1]);
            *(float2*)(C + (size_t)(row + 8) * N + col) =
                make_float2(acc[mt][nt][2], acc[mt][nt][3]);
        }
    }
}

// ---------------------------------------------------------------------------
// Flash attention fp16: BM=128, BN=64, D=128, m16n8k16 mma, ldmatrix frags.
// 128 threads = 4 warps; warp w owns 32 q-rows (2 x 16-row sub-tiles).
// ---------------------------------------------------------------------------
#define ABM 128
#define ABN 64
#define QSH 136
#define VSH 72
#define Q_HALVES (128*QSH)
#define K_HALVES (64*QSH)
#define V_HALVES (128*VSH)
#define STG_HALVES (K_HALVES + V_HALVES)
#define ATTN_SMEM_BYTES ((Q_HALVES + 2 * STG_HALVES) * 2)  // 106496

__global__ __launch_bounds__(128, 2) void attn_f16_kernel(
    const __half* __restrict__ qh, const __half* __restrict__ kh,
    const __half* __restrict__ vt, __half* __restrict__ y)
{
    extern __shared__ __half smh[];
    const int tid = threadIdx.x;
    const int wid = tid >> 5;
    const int lid = tid & 31;
    const int r4  = lid >> 2;
    const int c4  = lid & 3;
    const int h   = blockIdx.y;
    const int b   = blockIdx.z;
    const int t0  = blockIdx.x * ABM;
    const int mrow = wid * 32;

    const uint32_t smem_u32 = smem_to_u32(smh);

    const int grp = lid >> 3, rowin = lid & 7;
    const int qoff_h = (rowin + 8 * (grp & 1)) * QSH + (grp >> 1) * 8;
    const int koff_h = (rowin + 8 * (grp >> 1)) * QSH + (grp & 1) * 8;
    const int voff_h = (rowin + 8 * (grp >> 1)) * VSH + (grp & 1) * 8;
    const uint32_t qBase = smem_u32 + (uint32_t)(qoff_h + mrow * QSH) * 2u;

    const __half* Qg  = qh + ((size_t)b * SEQ) * CDIM + h * HDIM;
    const __half* Kg  = kh + ((size_t)b * SEQ) * CDIM + h * HDIM;
    const __half* Vtg = vt + (size_t)(b * NHEAD + h) * HDIM * SEQ;

    #pragma unroll
    for (int i = 0; i < 16; i++) {
        int f = tid + i * 128;
        int r = f >> 4, q = f & 15;
        cp_async16(smem_u32 + (uint32_t)(r * QSH + q * 8) * 2u,
                   Qg + (size_t)(t0 + r) * CDIM + q * 8);
    }
    CP_COMMIT();

    auto issue_tile = [&](int kt) {
        const int s = kt & 1;
        const int s0 = kt * ABN;
        uint32_t kbase = smem_u32 + (uint32_t)(Q_HALVES + s * STG_HALVES) * 2u;
        uint32_t vbase = kbase + (uint32_t)K_HALVES * 2u;
        #pragma unroll
        for (int i = 0; i < 8; i++) {
            int f = tid + i * 128;
            int r = f >> 4, q = f & 15;
            cp_async16(kbase + (uint32_t)(r * QSH + q * 8) * 2u,
                       Kg + (size_t)(s0 + r) * CDIM + q * 8);
        }
        #pragma unroll
        for (int i = 0; i < 8; i++) {
            int f = tid + i * 128;
            int d = f >> 3, q = f & 7;
            cp_async16(vbase + (uint32_t)(d * VSH + q * 8) * 2u,
                       Vtg + (size_t)d * SEQ + s0 + q * 8);
        }
    };

    issue_tile(0); CP_COMMIT();

    float Oa0[16][4], Oa1[16][4];
    #pragma unroll
    for (int nt = 0; nt < 16; nt++) {
        Oa0[nt][0] = Oa0[nt][1] = Oa0[nt][2] = Oa0[nt][3] = 0.f;
        Oa1[nt][0] = Oa1[nt][1] = Oa1[nt][2] = Oa1[nt][3] = 0.f;
    }
    float m_[2][2] = {{-1e30f, -1e30f}, {-1e30f, -1e30f}};
    float l_[2][2] = {{0.f, 0.f}, {0.f, 0.f}};

    const int NT = SEQ / ABN;   // 32
    for (int kt = 0; kt < NT; kt++) {
        __syncthreads();
        if (kt + 1 < NT) { issue_tile(kt + 1); CP_COMMIT(); }
        if (kt + 1 < NT) { CP_WAIT(1); } else { CP_WAIT(0); }
        __syncthreads();

        const uint32_t kA = smem_u32 +
            (uint32_t)(Q_HALVES + (kt & 1) * STG_HALVES + koff_h) * 2u;
        const uint32_t vA = smem_u32 +
            (uint32_t)(Q_HALVES + (kt & 1) * STG_HALVES + K_HALVES + voff_h) * 2u;

        uint32_t ph[2][8][2];
        float cr[2][2];

        #pragma unroll
        for (int mt = 0; mt < 2; mt++) {
            float P[8][4];
            #pragma unroll
            for (int nt = 0; nt < 8; nt++)
                P[nt][0] = P[nt][1] = P[nt][2] = P[nt][3] = 0.f;

            #pragma unroll
            for (int kk = 0; kk < 8; kk++) {
                uint32_t a0, a1, a2, a3;
                ldsm_x4(a0, a1, a2, a3,
                        qBase + (uint32_t)((mt * 16 * QSH + kk * 16) * 2));
                uint32_t bb[8][2];
                #pragma unroll
                for (int np = 0; np < 4; np++)
                    ldsm_x4(bb[2*np][0], bb[2*np][1], bb[2*np+1][0], bb[2*np+1][1],
                            kA + (uint32_t)((np * 16 * QSH + kk * 16) * 2));
                #pragma unroll
                for (int nt = 0; nt < 8; nt++)
                    mma_f16(P[nt][0], P[nt][1], P[nt][2], P[nt][3],
                            a0, a1, a2, a3, bb[nt][0], bb[nt][1]);
            }

            float mx0 = -1e30f, mx1 = -1e30f;
            #pragma unroll
            for (int nt = 0; nt < 8; nt++) {
                mx0 = fmaxf(mx0, fmaxf(P[nt][0], P[nt][1]));
                mx1 = fmaxf(mx1, fmaxf(P[nt][2], P[nt][3]));
            }
            mx0 = fmaxf(mx0, __shfl_xor_sync(0xffffffffu, mx0, 1));
            mx0 = fmaxf(mx0, __shfl_xor_sync(0xffffffffu, mx0, 2));
            mx1 = fmaxf(mx1, __shfl_xor_sync(0xffffffffu, mx1, 1));
            mx1 = fmaxf(mx1, __shfl_xor_sync(0xffffffffu, mx1, 2));

            float mn0 = fmaxf(m_[mt][0], mx0), mn1 = fmaxf(m_[mt][1], mx1);
            cr[mt][0] = __expf(m_[mt][0] - mn0);
            cr[mt][1] = __expf(m_[mt][1] - mn1);
            m_[mt][0] = mn0; m_[mt][1] = mn1;

            float s0s = 0.f, s1s = 0.f;
            #pragma unroll
            for (int nt = 0; nt < 8; nt++) {
                float p0 = __expf(P[nt][0] - mn0);
                float p1 = __expf(P[nt][1] - mn0);
                float p2 = __expf(P[nt][2] - mn1);
                float p3 = __expf(P[nt][3] - mn1);
                ph[mt][nt][0] = pack_h2(p0, p1);
                ph[mt][nt][1] = pack_h2(p2, p3);
                float2 r01 = unpack_h2(ph[mt][nt][0]);
                float2 r23 = unpack_h2(ph[mt][nt][1]);
                s0s += r01.x + r01.y;
                s1s += r23.x + r23.y;
            }
            s0s += __shfl_xor_sync(0xffffffffu, s0s, 1);
            s0s += __shfl_xor_sync(0xffffffffu, s0s, 2);
            s1s += __shfl_xor_sync(0xffffffffu, s1s, 1);
            s1s += __shfl_xor_sync(0xffffffffu, s1s, 2);
            l_[mt][0] = l_[mt][0] * cr[mt][0] + s0s;
            l_[mt][1] = l_[mt][1] * cr[mt][1] + s1s;
        }

        #pragma unroll
        for (int nt = 0; nt < 16; nt++) {
            Oa0[nt][0] *= cr[0][0]; Oa0[nt][1] *= cr[0][0];
            Oa0[nt][2] *= cr[0][1]; Oa0[nt][3] *= cr[0][1];
            Oa1[nt][0] *= cr[1][0]; Oa1[nt][1] *= cr[1][0];
            Oa1[nt][2] *= cr[1][1]; Oa1[nt][3] *= cr[1][1];
        }

        #pragma unroll
        for (int kk = 0; kk < 4; kk++) {
            #pragma unroll
            for (int np = 0; np < 8; np++) {
                uint32_t b00, b01, b10, b11;
                ldsm_x4(b00, b01, b10, b11,
                        vA + (uint32_t)((np * 16 * VSH + kk * 16) * 2));
                mma_f16(Oa0[2*np][0], Oa0[2*np][1], Oa0[2*np][2], Oa0[2*np][3],
                        ph[0][2*kk][0], ph[0][2*kk][1], ph[0][2*kk+1][0], ph[0][2*kk+1][1],
                        b00, b01);
                mma_f16(Oa1[2*np][0], Oa1[2*np][1], Oa1[2*np][2], Oa1[2*np][3],
                        ph[1][2*kk][0], ph[1][2*kk][1], ph[1][2*kk+1][0], ph[1][2*kk+1][1],
                        b00, b01);
                mma_f16(Oa0[2*np+1][0], Oa0[2*np+1][1], Oa0[2*np+1][2], Oa0[2*np+1][3],
                        ph[0][2*kk][0], ph[0][2*kk][1], ph[0][2*kk+1][0], ph[0][2*kk+1][1],
                        b10, b11);
                mma_f16(Oa1[2*np+1][0], Oa1[2*np+1][1], Oa1[2*np+1][2], Oa1[2*np+1][3],
                        ph[1][2*kk][0], ph[1][2*kk][1], ph[1][2*kk+1][0], ph[1][2*kk+1][1],
                        b10, b11);
            }
        }
    }

    #pragma unroll
    for (int mt = 0; mt < 2; mt++) {
        float inv0 = 1.f / l_[mt][0], inv1 = 1.f / l_[mt][1];
        int row0 = t0 + mrow + mt * 16 + r4;
        int row1 = row0 + 8;
        __half* y0 = y + ((size_t)b * SEQ + row0) * CDIM + h * HDIM;
        __half* y1 = y + ((size_t)b * SEQ + row1) * CDIM + h * HDIM;
        #pragma unroll
        for (int nt = 0; nt < 16; nt++) {
            int col = nt * 8 + 2 * c4;
            if (mt == 0) {
                *(uint32_t*)(y0 + col) = pack_h2(Oa0[nt][0] * inv0, Oa0[nt][1] * inv0);
                *(uint32_t*)(y1 + col) = pack_h2(Oa0[nt][2] * inv1, Oa0[nt][3] * inv1);
            } else {
                *(uint32_t*)(y0 + col) = pack_h2(Oa1[nt][0] * inv0, Oa1[nt][1] * inv0);
                *(uint32_t*)(y1 + col) = pack_h2(Oa1[nt][2] * inv1, Oa1[nt][3] * inv1);
            }
        }
    }
}

// ---------------------------------------------------------------------------
extern "C" void kernel_launch(void* const* d_in, const int* in_sizes, int n_in,
                              void* d_out, int out_size)
{
    const float* x     = (const float*)d_in[0];
    const float* cosp  = (const float*)d_in[1];
    const float* sinp  = (const float*)d_in[2];
    const float* Wqkv  = (const float*)d_in[3];
    const float* Wproj = (const float*)d_in[4];
    float* out = (float*)d_out;

    __half *xh = nullptr, *qh = nullptr, *kh = nullptr, *vth = nullptr, *yh = nullptr;
    __half *WhQkv = nullptr, *WhProj = nullptr;
    cudaGetSymbolAddress((void**)&xh,     g_xh);
    cudaGetSymbolAddress((void**)&qh,     g_qh);
    cudaGetSymbolAddress((void**)&kh,     g_kh);
    cudaGetSymbolAddress((void**)&vth,    g_vth);
    cudaGetSymbolAddress((void**)&yh,     g_yh);
    cudaGetSymbolAddress((void**)&WhQkv,  g_WhQkv);
    cudaGetSymbolAddress((void**)&WhProj, g_WhProj);

    cudaFuncSetAttribute(attn_f16_kernel, cudaFuncAttributeMaxDynamicSharedMemorySize, ATTN_SMEM_BYTES);
    cudaFuncSetAttribute(gemm_f16mma,     cudaFuncAttributeMaxDynamicSharedMemorySize, GSMEM_BYTES);
    cudaFuncSetAttribute(gemm_qkv_fused,  cudaFuncAttributeMaxDynamicSharedMemorySize, GSMEM_BYTES);

    // 0) weights: transpose + half; x: half
    transpose_kh<<<dim3(C3 / 32,   CDIM / 32), dim3(32, 8)>>>(Wqkv,  WhQkv,  CDIM, C3);
    transpose_kh<<<dim3(CDIM / 32, CDIM / 32), dim3(32, 8)>>>(Wproj, WhProj, CDIM, CDIM);
    {
        int n4 = MROWS * CDIM / 4;
        convert_h_kernel<<<(n4 + 255) / 256, 256>>>(x, xh, n4);
    }

    // 1) fused: qkv GEMM + RoPE + scale + V-transpose -> qh, kh, vth (half)
    gemm_qkv_fused<<<dim3(C3 / 128, MROWS / 128), 256, GSMEM_BYTES>>>(
        xh, WhQkv, cosp, sinp, qh, kh, vth);

    // 2) flash attention (fp16 mma + ldmatrix) -> yh
    {
        dim3 grid(SEQ / ABM, NHEAD, BATCH);
        attn_f16_kernel<<<grid, 128, ATTN_SMEM_BYTES>>>(qh, kh, vth, yh);
    }

    // 3) out = y @ W_proj  (fp16 mma + ldmatrix, fp32 out)
    gemm_f16mma<<<dim3(CDIM / 128, MROWS / 128), 256, GSMEM_BYTES>>>(
        yh, WhProj, out, MROWS, CDIM, CDIM);
}

// round 14
// speedup vs baseline: 3.3079x; 1.0013x over previous
#include <cuda_runtime.h>
#include <cuda_fp16.h>
#include <cstdint>

// Problem constants
#define BATCH 2
#define SEQ   2048
#define CDIM  2048
#define NHEAD 16
#define HDIM  128
#define C3    (3*CDIM)          // 6144
#define MROWS (BATCH*SEQ)       // 4096
static __device__ __constant__ float kScale = 0.08838834764831845f; // 1/sqrt(128)

// Scratch (device globals: allocation-free)
__device__ __half g_xh [(size_t)BATCH*SEQ*CDIM];   // half(x)
__device__ __half g_qh [(size_t)BATCH*SEQ*CDIM];   // roped+scaled q, half
__device__ __half g_kh [(size_t)BATCH*SEQ*CDIM];   // roped k, half
__device__ __half g_vth[(size_t)BATCH*NHEAD*HDIM*SEQ]; // V^T [b,h,d,t], half
__device__ __half g_yh [(size_t)BATCH*SEQ*CDIM];   // attention out, half
__device__ __half g_WhQkv[(size_t)C3*CDIM];        // W_qkv^T half
__device__ __half g_WhProj[(size_t)CDIM*CDIM];     // W_proj^T half

// ============================================================================
// helpers
// ============================================================================
__device__ __forceinline__ uint32_t smem_to_u32(const void* p) {
    uint32_t a;
    asm("{ .reg .u64 t; cvta.to.shared.u64 t, %1; cvt.u32.u64 %0, t; }" : "=r"(a) : "l"(p));
    return a;
}
__device__ __forceinline__ void cp_async16(uint32_t saddr, const void* g) {
    asm volatile("cp.async.cg.shared.global [%0], [%1], 16;" :: "r"(saddr), "l"(g));
}
#define CP_COMMIT() asm volatile("cp.async.commit_group;" ::: "memory")
#define CP_WAIT(n)  asm volatile("cp.async.wait_group %0;" :: "n"(n) : "memory")

__device__ __forceinline__ uint32_t pack_h2(float a, float b) {
    __half2 h = __floats2half2_rn(a, b);
    return *reinterpret_cast<uint32_t*>(&h);
}
__device__ __forceinline__ float2 unpack_h2(uint32_t u) {
    __half2 h = *reinterpret_cast<__half2*>(&u);
    return __half22float2(h);
}

// ldmatrix: 4 x (8x8 b16) tiles
__device__ __forceinline__ void ldsm_x4(
    uint32_t& r0, uint32_t& r1, uint32_t& r2, uint32_t& r3, uint32_t addr)
{
    asm volatile("ldmatrix.sync.aligned.m8n8.x4.shared.b16 {%0,%1,%2,%3}, [%4];"
                 : "=r"(r0), "=r"(r1), "=r"(r2), "=r"(r3) : "r"(addr));
}

// m16n8k16 fp16 mma, fp32 accumulate
__device__ __forceinline__ void mma_f16(
    float& c0, float& c1, float& c2, float& c3,
    uint32_t a0, uint32_t a1, uint32_t a2, uint32_t a3,
    uint32_t b0, uint32_t b1)
{
    asm volatile(
        "mma.sync.aligned.m16n8k16.row.col.f32.f16.f16.f32 "
        "{%0,%1,%2,%3}, {%4,%5,%6,%7}, {%8,%9}, {%0,%1,%2,%3};"
        : "+f"(c0), "+f"(c1), "+f"(c2), "+f"(c3)
        : "r"(a0), "r"(a1), "r"(a2), "r"(a3), "r"(b0), "r"(b1));
}

// ============================================================================
// convert fp32 -> fp16
// ============================================================================
__global__ __launch_bounds__(256) void convert_h_kernel(
    const float* __restrict__ in, __half* __restrict__ out, int n4)
{
    int i = blockIdx.x * blockDim.x + threadIdx.x;
    if (i < n4) {
        float4 v = ((const float4*)in)[i];
        uint2 o;
        o.x = pack_h2(v.x, v.y);
        o.y = pack_h2(v.z, v.w);
        ((uint2*)out)[i] = o;
    }
}

// ============================================================================
// Transpose + half convert: out[C][R] = half(in[R][C])
// ============================================================================
__global__ __launch_bounds__(256) void transpose_kh(
    const float* __restrict__ in, __half* __restrict__ out, int R, int C)
{
    __shared__ float t[32][33];
    int bx = blockIdx.x * 32, by = blockIdx.y * 32;
    int tx = threadIdx.x, ty = threadIdx.y;
    #pragma unroll
    for (int j = ty; j < 32; j += 8)
        t[j][tx] = in[(size_t)(by + j) * C + bx + tx];
    __syncthreads();
    #pragma unroll
    for (int j = ty; j < 32; j += 8)
        out[(size_t)(bx + j) * R + by + tx] = __float2half_rn(t[tx][j]);
}

// ============================================================================
// Shared GEMM config: 64x128 CTA tile, 128 threads = 4 warps (2M x 2N),
// warp tile 32x64, K chunk 64 halves, 2-stage cp.async, 3 CTAs/SM.
// ============================================================================
#define GKH 64
#define GSTRH 72                                  // halves per smem row
#define A_TILE_H (64 * GSTRH)                     // 4608 halves
#define B_TILE_H (128 * GSTRH)                    // 9216 halves
#define STAGE_H  (A_TILE_H + B_TILE_H)            // 13824
#define GSMEM_BYTES (2 * STAGE_H * 2)             // 55296 B
#define EPI_STRIDE 132                            // fp32 epilogue smem stride

// ============================================================================
// Fused GEMM1: qkv = x @ W_qkv^T with RoPE/scale/half epilogue.
// N-tile (128) == one (type, head) slab. type 0->q(+rope,scale), 1->k(+rope),
// 2->v (transpose into vth). Epilogue stages fp32 64x128 tile through smem.
// ============================================================================
__global__ __launch_bounds__(128, 3) void gemm_qkv_fused(
    const __half* __restrict__ A, const __half* __restrict__ Bt,
    const float* __restrict__ cosp, const float* __restrict__ sinp,
    __half* __restrict__ qh, __half* __restrict__ kh, __half* __restrict__ vth)
{
    extern __shared__ __half smh[];
    const int tid = threadIdx.x;
    const int wid = tid >> 5;
    const int lid = tid & 31;
    const int wm  = wid & 1;        // 0..1  (32 M-rows)
    const int wn  = wid >> 1;       // 0..1  (64 N-cols)
    const int m0  = blockIdx.y * 64;
    const int n0  = blockIdx.x * 128;
    const int K   = CDIM;

    const uint32_t smem_u32 = smem_to_u32(smh);
    const int grp = lid >> 3, rowin = lid & 7;
    const int aoff_h = (rowin + 8 * (grp & 1)) * GSTRH + (grp >> 1) * 8;
    const int boff_h = (rowin + 8 * (grp >> 1)) * GSTRH + (grp & 1) * 8;
    const uint32_t aBase = smem_u32 + (uint32_t)(aoff_h + wm * 32 * GSTRH) * 2u;
    const uint32_t bBase = smem_u32 + (uint32_t)(A_TILE_H + boff_h + wn * 64 * GSTRH) * 2u;

    float acc[2][8][4];
    #pragma unroll
    for (int i = 0; i < 2; i++)
        #pragma unroll
        for (int j = 0; j < 8; j++)
            #pragma unroll
            for (int u = 0; u < 4; u++) acc[i][j][u] = 0.f;

    const int nchunk = K / GKH;

    auto issue = [&](int c, int s) {
        const __half* Ag = A  + (size_t)m0 * K + c * GKH;
        const __half* Bg = Bt + (size_t)n0 * K + c * GKH;
        uint32_t baseA = smem_u32 + (uint32_t)(s * STAGE_H) * 2u;
        uint32_t baseB = baseA + (uint32_t)A_TILE_H * 2u;
        // A: 64 rows x 8 lines = 512 lines -> 4 iters
        #pragma unroll
        for (int i = 0; i < 4; i++) {
            int f   = tid + i * 128;
            int row = f >> 3;
            int q   = f & 7;
            cp_async16(baseA + (uint32_t)(row * GSTRH + q * 8) * 2u,
                       Ag + (size_t)row * K + q * 8);
        }
        // B: 128 rows x 8 lines = 1024 lines -> 8 iters
        #pragma unroll
        for (int i = 0; i < 8; i++) {
            int f   = tid + i * 128;
            int row = f >> 3;
            int q   = f & 7;
            cp_async16(baseB + (uint32_t)(row * GSTRH + q * 8) * 2u,
                       Bg + (size_t)row * K + q * 8);
        }
    };

    issue(0, 0);
    CP_COMMIT();

    const int r4 = lid >> 2;
    const int c4 = lid & 3;

    for (int c = 0; c < nchunk; c++) {
        const int s = c & 1;
        if (c + 1 < nchunk) { issue(c + 1, s ^ 1); CP_COMMIT(); CP_WAIT(1); }
        else                { CP_WAIT(0); }
        __syncthreads();

        const uint32_t aA = aBase + (uint32_t)(s * STAGE_H) * 2u;
        const uint32_t bA = bBase + (uint32_t)(s * STAGE_H) * 2u;

        #pragma unroll
        for (int kk = 0; kk < 4; kk++) {
            uint32_t a[2][4], b[8][2];
            #pragma unroll
            for (int mt = 0; mt < 2; mt++)
                ldsm_x4(a[mt][0], a[mt][1], a[mt][2], a[mt][3],
                        aA + (uint32_t)((mt * 16 * GSTRH + kk * 16) * 2));
            #pragma unroll
            for (int np = 0; np < 4; np++)
                ldsm_x4(b[2*np][0], b[2*np][1], b[2*np+1][0], b[2*np+1][1],
                        bA + (uint32_t)((np * 16 * GSTRH + kk * 16) * 2));
            #pragma unroll
            for (int mt = 0; mt < 2; mt++)
                #pragma unroll
                for (int nt = 0; nt < 8; nt++)
                    mma_f16(acc[mt][nt][0], acc[mt][nt][1], acc[mt][nt][2], acc[mt][nt][3],
                            a[mt][0], a[mt][1], a[mt][2], a[mt][3],
                            b[nt][0], b[nt][1]);
        }
        __syncthreads();
    }

    // ---- fused epilogue: stage fp32 64x128 tile in smem ----
    float* sf = reinterpret_cast<float*>(smh);   // [64][EPI_STRIDE]
    #pragma unroll
    for (int mt = 0; mt < 2; mt++) {
        int row = wm * 32 + mt * 16 + r4;
        #pragma unroll
        for (int nt = 0; nt < 8; nt++) {
            int col = wn * 64 + nt * 8 + 2 * c4;
            sf[row * EPI_STRIDE + col]           = acc[mt][nt][0];
            sf[row * EPI_STRIDE + col + 1]       = acc[mt][nt][1];
            sf[(row + 8) * EPI_STRIDE + col]     = acc[mt][nt][2];
            sf[(row + 8) * EPI_STRIDE + col + 1] = acc[mt][nt][3];
        }
    }
    __syncthreads();

    const int type = n0 >> 11;           // 0=q, 1=k, 2=v
    const int h    = (n0 & 2047) >> 7;   // head
    const int b    = m0 >> 11;           // batch
    const int tbase = m0 & 2047;         // seq offset

    if (type < 2) {
        // RoPE + half: pairs (d, d+64); 2048 items (64 rows x 32 dp) / 128 thr
        __half* outg = (type == 0) ? qh : kh;
        const float sc = (type == 0) ? kScale : 1.f;
        #pragma unroll
        for (int i = 0; i < 16; i++) {
            int idx = tid + i * 128;       // 0..2047
            int tl  = idx >> 5;            // 0..63
            int dp  = (idx & 31) * 2;      // 0,2,..,62
            float2 x1 = *(const float2*)&sf[tl * EPI_STRIDE + dp];
            float2 x2 = *(const float2*)&sf[tl * EPI_STRIDE + dp + 64];
            int t = tbase + tl;
            float2 c1 = *(const float2*)(cosp + t * HDIM + dp);
            float2 s1 = *(const float2*)(sinp + t * HDIM + dp);
            float2 c2 = *(const float2*)(cosp + t * HDIM + dp + 64);
            float2 s2 = *(const float2*)(sinp + t * HDIM + dp + 64);
            __half* o = outg + ((size_t)(b * SEQ + t)) * CDIM + h * HDIM;
            *(uint32_t*)(o + dp) = pack_h2((x1.x * c1.x - x2.x * s1.x) * sc,
                                           (x1.y * c1.y - x2.y * s1.y) * sc);
            *(uint32_t*)(o + dp + 64) = pack_h2((x2.x * c2.x + x1.x * s2.x) * sc,
                                                (x2.y * c2.y + x1.y * s2.y) * sc);
        }
    } else {
        // V transpose: thread owns d = tid (0..127); writes 64 t-contiguous halves
        int d = tid;
        __half* dst = vth + ((size_t)(b * NHEAD + h) * HDIM + d) * SEQ + tbase;
        #pragma unroll
        for (int j = 0; j < 16; j++) {
            float v0 = sf[(4 * j + 0) * EPI_STRIDE + d];
            float v1 = sf[(4 * j + 1) * EPI_STRIDE + d];
            float v2 = sf[(4 * j + 2) * EPI_STRIDE + d];
            float v3 = sf[(4 * j + 3) * EPI_STRIDE + d];
            uint2 o;
            o.x = pack_h2(v0, v1);
            o.y = pack_h2(v2, v3);
            *(uint2*)(dst + 4 * j) = o;
        }
    }
}

// ============================================================================
// Plain FP16 GEMM (proj): C[M,N](fp32) = A[M,K] @ Bt[N,K]^T, 64x128 tile
// ============================================================================
__global__ __launch_bounds__(128, 3) void gemm_f16mma(
    const __half* __restrict__ A, const __half* __restrict__ Bt,
    float* __restrict__ C, int M, int N, int K)
{
    extern __shared__ __half smh[];
    const int tid = threadIdx.x;
    const int wid = tid >> 5;
    const int lid = tid & 31;
    const int wm  = wid & 1;
    const int wn  = wid >> 1;
    const int m0  = blockIdx.y * 64;
    const int n0  = blockIdx.x * 128;

    const uint32_t smem_u32 = smem_to_u32(smh);
    const int grp = lid >> 3, rowin = lid & 7;
    const int aoff_h = (rowin + 8 * (grp & 1)) * GSTRH + (grp >> 1) * 8;
    const int boff_h = (rowin + 8 * (grp >> 1)) * GSTRH + (grp & 1) * 8;
    const uint32_t aBase = smem_u32 + (uint32_t)(aoff_h + wm * 32 * GSTRH) * 2u;
    const uint32_t bBase = smem_u32 + (uint32_t)(A_TILE_H + boff_h + wn * 64 * GSTRH) * 2u;

    float acc[2][8][4];
    #pragma unroll
    for (int i = 0; i < 2; i++)
        #pragma unroll
        for (int j = 0; j < 8; j++)
            #pragma unroll
            for (int u = 0; u < 4; u++) acc[i][j][u] = 0.f;

    const int nchunk = K / GKH;

    auto issue = [&](int c, int s) {
        const __half* Ag = A  + (size_t)m0 * K + c * GKH;
        const __half* Bg = Bt + (size_t)n0 * K + c * GKH;
        uint32_t baseA = smem_u32 + (uint32_t)(s * STAGE_H) * 2u;
        uint32_t baseB = baseA + (uint32_t)A_TILE_H * 2u;
        #pragma unroll
        for (int i = 0; i < 4; i++) {
            int f   = tid + i * 128;
            int row = f >> 3;
            int q   = f & 7;
            cp_async16(baseA + (uint32_t)(row * GSTRH + q * 8) * 2u,
                       Ag + (size_t)row * K + q * 8);
        }
        #pragma unroll
        for (int i = 0; i < 8; i++) {
            int f   = tid + i * 128;
            int row = f >> 3;
            int q   = f & 7;
            cp_async16(baseB + (uint32_t)(row * GSTRH + q * 8) * 2u,
                       Bg + (size_t)row * K + q * 8);
        }
    };

    issue(0, 0);
    CP_COMMIT();

    const int r4 = lid >> 2;
    const int c4 = lid & 3;

    for (int c = 0; c < nchunk; c++) {
        const int s = c & 1;
        if (c + 1 < nchunk) { issue(c + 1, s ^ 1); CP_COMMIT(); CP_WAIT(1); }
        else                { CP_WAIT(0); }
        __syncthreads();

        const uint32_t aA = aBase + (uint32_t)(s * STAGE_H) * 2u;
        const uint32_t bA = bBase + (uint32_t)(s * STAGE_H) * 2u;

        #pragma unroll
        for (int kk = 0; kk < 4; kk++) {
            uint32_t a[2][4], b[8][2];
            #pragma unroll
            for (int mt = 0; mt < 2; mt++)
                ldsm_x4(a[mt][0], a[mt][1], a[mt][2], a[mt][3],
                        aA + (uint32_t)((mt * 16 * GSTRH + kk * 16) * 2));
            #pragma unroll
            for (int np = 0; np < 4; np++)
                ldsm_x4(b[2*np][0], b[2*np][1], b[2*np+1][0], b[2*np+1][1],
                        bA + (uint32_t)((np * 16 * GSTRH + kk * 16) * 2));
            #pragma unroll
            for (int mt = 0; mt < 2; mt++)
                #pragma unroll
                for (int nt = 0; nt < 8; nt++)
                    mma_f16(acc[mt][nt][0], acc[mt][nt][1], acc[mt][nt][2], acc[mt][nt][3],
                            a[mt][0], a[mt][1], a[mt][2], a[mt][3],
                            b[nt][0], b[nt][1]);
        }
        __syncthreads();
    }

    const int c2l = 2 * c4;
    #pragma unroll
    for (int mt = 0; mt < 2; mt++) {
        int row = m0 + wm * 32 + mt * 16 + r4;
        #pragma unroll
        for (int nt = 0; nt < 8; nt++) {
            int col = n0 + wn * 64 + nt * 8 + c2l;
            *(float2*)(C + (size_t)row * N + col) =
                make_float2(acc[mt][nt][0], acc[mt][nt][1]);
            *(float2*)(C + (size_t)(row + 8) * N + col) =
                make_float2(acc[mt][nt][2], acc[mt][nt][3]);
        }
    }
}

// ---------------------------------------------------------------------------
// Flash attention fp16 (unchanged from R13): BM=128, BN=64, D=128.
// ---------------------------------------------------------------------------
#define ABM 128
#define ABN 64
#define QSH 136
#define VSH 72
#define Q_HALVES (128*QSH)
#define K_HALVES (64*QSH)
#define V_HALVES (128*VSH)
#define STG_HALVES (K_HALVES + V_HALVES)
#define ATTN_SMEM_BYTES ((Q_HALVES + 2 * STG_HALVES) * 2)  // 106496

__global__ __launch_bounds__(128, 2) void attn_f16_kernel(
    const __half* __restrict__ qh, const __half* __restrict__ kh,
    const __half* __restrict__ vt, __half* __restrict__ y)
{
    extern __shared__ __half smh[];
    const int tid = threadIdx.x;
    const int wid = tid >> 5;
    const int lid = tid & 31;
    const int r4  = lid >> 2;
    const int c4  = lid & 3;
    const int h   = blockIdx.y;
    const int b   = blockIdx.z;
    const int t0  = blockIdx.x * ABM;
    const int mrow = wid * 32;

    const uint32_t smem_u32 = smem_to_u32(smh);

    const int grp = lid >> 3, rowin = lid & 7;
    const int qoff_h = (rowin + 8 * (grp & 1)) * QSH + (grp >> 1) * 8;
    const int koff_h = (rowin + 8 * (grp >> 1)) * QSH + (grp & 1) * 8;
    const int voff_h = (rowin + 8 * (grp >> 1)) * VSH + (grp & 1) * 8;
    const uint32_t qBase = smem_u32 + (uint32_t)(qoff_h + mrow * QSH) * 2u;

    const __half* Qg  = qh + ((size_t)b * SEQ) * CDIM + h * HDIM;
    const __half* Kg  = kh + ((size_t)b * SEQ) * CDIM + h * HDIM;
    const __half* Vtg = vt + (size_t)(b * NHEAD + h) * HDIM * SEQ;

    #pragma unroll
    for (int i = 0; i < 16; i++) {
        int f = tid + i * 128;
        int r = f >> 4, q = f & 15;
        cp_async16(smem_u32 + (uint32_t)(r * QSH + q * 8) * 2u,
                   Qg + (size_t)(t0 + r) * CDIM + q * 8);
    }
    CP_COMMIT();

    auto issue_tile = [&](int kt) {
        const int s = kt & 1;
        const int s0 = kt * ABN;
        uint32_t kbase = smem_u32 + (uint32_t)(Q_HALVES + s * STG_HALVES) * 2u;
        uint32_t vbase = kbase + (uint32_t)K_HALVES * 2u;
        #pragma unroll
        for (int i = 0; i < 8; i++) {
            int f = tid + i * 128;
            int r = f >> 4, q = f & 15;
            cp_async16(kbase + (uint32_t)(r * QSH + q * 8) * 2u,
                       Kg + (size_t)(s0 + r) * CDIM + q * 8);
        }
        #pragma unroll
        for (int i = 0; i < 8; i++) {
            int f = tid + i * 128;
            int d = f >> 3, q = f & 7;
            cp_async16(vbase + (uint32_t)(d * VSH + q * 8) * 2u,
                       Vtg + (size_t)d * SEQ + s0 + q * 8);
        }
    };

    issue_tile(0); CP_COMMIT();

    float Oa0[16][4], Oa1[16][4];
    #pragma unroll
    for (int nt = 0; nt < 16; nt++) {
        Oa0[nt][0] = Oa0[nt][1] = Oa0[nt][2] = Oa0[nt][3] = 0.f;
        Oa1[nt][0] = Oa1[nt][1] = Oa1[nt][2] = Oa1[nt][3] = 0.f;
    }
    float m_[2][2] = {{-1e30f, -1e30f}, {-1e30f, -1e30f}};
    float l_[2][2] = {{0.f, 0.f}, {0.f, 0.f}};

    const int NT = SEQ / ABN;   // 32
    for (int kt = 0; kt < NT; kt++) {
        __syncthreads();
        if (kt + 1 < NT) { issue_tile(kt + 1); CP_COMMIT(); }
        if (kt + 1 < NT) { CP_WAIT(1); } else { CP_WAIT(0); }
        __syncthreads();

        const uint32_t kA = smem_u32 +
            (uint32_t)(Q_HALVES + (kt & 1) * STG_HALVES + koff_h) * 2u;
        const uint32_t vA = smem_u32 +
            (uint32_t)(Q_HALVES + (kt & 1) * STG_HALVES + K_HALVES + voff_h) * 2u;

        uint32_t ph[2][8][2];
        float cr[2][2];

        #pragma unroll
        for (int mt = 0; mt < 2; mt++) {
            float P[8][4];
            #pragma unroll
            for (int nt = 0; nt < 8; nt++)
                P[nt][0] = P[nt][1] = P[nt][2] = P[nt][3] = 0.f;

            #pragma unroll
            for (int kk = 0; kk < 8; kk++) {
                uint32_t a0, a1, a2, a3;
                ldsm_x4(a0, a1, a2, a3,
                        qBase + (uint32_t)((mt * 16 * QSH + kk * 16) * 2));
                uint32_t bb[8][2];
                #pragma unroll
                for (int np = 0; np < 4; np++)
                    ldsm_x4(bb[2*np][0], bb[2*np][1], bb[2*np+1][0], bb[2*np+1][1],
                            kA + (uint32_t)((np * 16 * QSH + kk * 16) * 2));
                #pragma unroll
                for (int nt = 0; nt < 8; nt++)
                    mma_f16(P[nt][0], P[nt][1], P[nt][2], P[nt][3],
                            a0, a1, a2, a3, bb[nt][0], bb[nt][1]);
            }

            float mx0 = -1e30f, mx1 = -1e30f;
            #pragma unroll
            for (int nt = 0; nt < 8; nt++) {
                mx0 = fmaxf(mx0, fmaxf(P[nt][0], P[nt][1]));
                mx1 = fmaxf(mx1, fmaxf(P[nt][2], P[nt][3]));
            }
            mx0 = fmaxf(mx0, __shfl_xor_sync(0xffffffffu, mx0, 1));
            mx0 = fmaxf(mx0, __shfl_xor_sync(0xffffffffu, mx0, 2));
            mx1 = fmaxf(mx1, __shfl_xor_sync(0xffffffffu, mx1, 1));
            mx1 = fmaxf(mx1, __shfl_xor_sync(0xffffffffu, mx1, 2));

            float mn0 = fmaxf(m_[mt][0], mx0), mn1 = fmaxf(m_[mt][1], mx1);
            cr[mt][0] = __expf(m_[mt][0] - mn0);
            cr[mt][1] = __expf(m_[mt][1] - mn1);
            m_[mt][0] = mn0; m_[mt][1] = mn1;

            float s0s = 0.f, s1s = 0.f;
            #pragma unroll
            for (int nt = 0; nt < 8; nt++) {
                float p0 = __expf(P[nt][0] - mn0);
                float p1 = __expf(P[nt][1] - mn0);
                float p2 = __expf(P[nt][2] - mn1);
                float p3 = __expf(P[nt][3] - mn1);
                ph[mt][nt][0] = pack_h2(p0, p1);
                ph[mt][nt][1] = pack_h2(p2, p3);
                float2 r01 = unpack_h2(ph[mt][nt][0]);
                float2 r23 = unpack_h2(ph[mt][nt][1]);
                s0s += r01.x + r01.y;
                s1s += r23.x + r23.y;
            }
            s0s += __shfl_xor_sync(0xffffffffu, s0s, 1);
            s0s += __shfl_xor_sync(0xffffffffu, s0s, 2);
            s1s += __shfl_xor_sync(0xffffffffu, s1s, 1);
            s1s += __shfl_xor_sync(0xffffffffu, s1s, 2);
            l_[mt][0] = l_[mt][0] * cr[mt][0] + s0s;
            l_[mt][1] = l_[mt][1] * cr[mt][1] + s1s;
        }

        #pragma unroll
        for (int nt = 0; nt < 16; nt++) {
            Oa0[nt][0] *= cr[0][0]; Oa0[nt][1] *= cr[0][0];
            Oa0[nt][2] *= cr[0][1]; Oa0[nt][3] *= cr[0][1];
            Oa1[nt][0] *= cr[1][0]; Oa1[nt][1] *= cr[1][0];
            Oa1[nt][2] *= cr[1][1]; Oa1[nt][3] *= cr[1][1];
        }

        #pragma unroll
        for (int kk = 0; kk < 4; kk++) {
            #pragma unroll
            for (int np = 0; np < 8; np++) {
                uint32_t b00, b01, b10, b11;
                ldsm_x4(b00, b01, b10, b11,
                        vA + (uint32_t)((np * 16 * VSH + kk * 16) * 2));
                mma_f16(Oa0[2*np][0], Oa0[2*np][1], Oa0[2*np][2], Oa0[2*np][3],
                        ph[0][2*kk][0], ph[0][2*kk][1], ph[0][2*kk+1][0], ph[0][2*kk+1][1],
                        b00, b01);
                mma_f16(Oa1[2*np][0], Oa1[2*np][1], Oa1[2*np][2], Oa1[2*np][3],
                        ph[1][2*kk][0], ph[1][2*kk][1], ph[1][2*kk+1][0], ph[1][2*kk+1][1],
                        b00, b01);
                mma_f16(Oa0[2*np+1][0], Oa0[2*np+1][1], Oa0[2*np+1][2], Oa0[2*np+1][3],
                        ph[0][2*kk][0], ph[0][2*kk][1], ph[0][2*kk+1][0], ph[0][2*kk+1][1],
                        b10, b11);
                mma_f16(Oa1[2*np+1][0], Oa1[2*np+1][1], Oa1[2*np+1][2], Oa1[2*np+1][3],
                        ph[1][2*kk][0], ph[1][2*kk][1], ph[1][2*kk+1][0], ph[1][2*kk+1][1],
                        b10, b11);
            }
        }
    }

    #pragma unroll
    for (int mt = 0; mt < 2; mt++) {
        float inv0 = 1.f / l_[mt][0], inv1 = 1.f / l_[mt][1];
        int row0 = t0 + mrow + mt * 16 + r4;
        int row1 = row0 + 8;
        __half* y0 = y + ((size_t)b * SEQ + row0) * CDIM + h * HDIM;
        __half* y1 = y + ((size_t)b * SEQ + row1) * CDIM + h * HDIM;
        #pragma unroll
        for (int nt = 0; nt < 16; nt++) {
            int col = nt * 8 + 2 * c4;
            if (mt == 0) {
                *(uint32_t*)(y0 + col) = pack_h2(Oa0[nt][0] * inv0, Oa0[nt][1] * inv0);
                *(uint32_t*)(y1 + col) = pack_h2(Oa0[nt][2] * inv1, Oa0[nt][3] * inv1);
            } else {
                *(uint32_t*)(y0 + col) = pack_h2(Oa1[nt][0] * inv0, Oa1[nt][1] * inv0);
                *(uint32_t*)(y1 + col) = pack_h2(Oa1[nt][2] * inv1, Oa1[nt][3] * inv1);
            }
        }
    }
}

// ---------------------------------------------------------------------------
extern "C" void kernel_launch(void* const* d_in, const int* in_sizes, int n_in,
                              void* d_out, int out_size)
{
    const float* x     = (const float*)d_in[0];
    const float* cosp  = (const float*)d_in[1];
    const float* sinp  = (const float*)d_in[2];
    const float* Wqkv  = (const float*)d_in[3];
    const float* Wproj = (const float*)d_in[4];
    float* out = (float*)d_out;

    __half *xh = nullptr, *qh = nullptr, *kh = nullptr, *vth = nullptr, *yh = nullptr;
    __half *WhQkv = nullptr, *WhProj = nullptr;
    cudaGetSymbolAddress((void**)&xh,     g_xh);
    cudaGetSymbolAddress((void**)&qh,     g_qh);
    cudaGetSymbolAddress((void**)&kh,     g_kh);
    cudaGetSymbolAddress((void**)&vth,    g_vth);
    cudaGetSymbolAddress((void**)&yh,     g_yh);
    cudaGetSymbolAddress((void**)&WhQkv,  g_WhQkv);
    cudaGetSymbolAddress((void**)&WhProj, g_WhProj);

    cudaFuncSetAttribute(attn_f16_kernel, cudaFuncAttributeMaxDynamicSharedMemorySize, ATTN_SMEM_BYTES);
    cudaFuncSetAttribute(gemm_f16mma,     cudaFuncAttributeMaxDynamicSharedMemorySize, GSMEM_BYTES);
    cudaFuncSetAttribute(gemm_qkv_fused,  cudaFuncAttributeMaxDynamicSharedMemorySize, GSMEM_BYTES);

    // 0) weights: transpose + half; x: half
    transpose_kh<<<dim3(C3 / 32,   CDIM / 32), dim3(32, 8)>>>(Wqkv,  WhQkv,  CDIM, C3);
    transpose_kh<<<dim3(CDIM / 32, CDIM / 32), dim3(32, 8)>>>(Wproj, WhProj, CDIM, CDIM);
    {
        int n4 = MROWS * CDIM / 4;
        convert_h_kernel<<<(n4 + 255) / 256, 256>>>(x, xh, n4);
    }

    // 1) fused: qkv GEMM + RoPE + scale + V-transpose -> qh, kh, vth (half)
    gemm_qkv_fused<<<dim3(C3 / 128, MROWS / 64), 128, GSMEM_BYTES>>>(
        xh, WhQkv, cosp, sinp, qh, kh, vth);

    // 2) flash attention (fp16 mma + ldmatrix) -> yh
    {
        dim3 grid(SEQ / ABM, NHEAD, BATCH);
        attn_f16_kernel<<<grid, 128, ATTN_SMEM_BYTES>>>(qh, kh, vth, yh);
    }

    // 3) out = y @ W_proj  (fp16 mma + ldmatrix, fp32 out)
    gemm_f16mma<<<dim3(CDIM / 128, MROWS / 64), 128, GSMEM_BYTES>>>(
        yh, WhProj, out, MROWS, CDIM, CDIM);
}

// round 16
// speedup vs baseline: 3.3180x; 1.0030x over previous
#include <cuda_runtime.h>
#include <cuda_fp16.h>
#include <cstdint>

// Problem constants
#define BATCH 2
#define SEQ   2048
#define CDIM  2048
#define NHEAD 16
#define HDIM  128
#define C3    (3*CDIM)          // 6144
#define MROWS (BATCH*SEQ)       // 4096
// q scale with log2(e) folded in: softmax runs in exp2 domain.
static __device__ __constant__ float kScale = 0.08838834764831845f;       // 1/sqrt(128)
#define LOG2E 1.4426950408889634f

// Scratch (device globals: allocation-free)
__device__ __half g_xh [(size_t)BATCH*SEQ*CDIM];   // half(x)
__device__ __half g_qh [(size_t)BATCH*SEQ*CDIM];   // roped, scaled*log2e q, half
__device__ __half g_kh [(size_t)BATCH*SEQ*CDIM];   // roped k, half
__device__ __half g_vth[(size_t)BATCH*NHEAD*HDIM*SEQ]; // V^T [b,h,d,t], half
__device__ __half g_yh [(size_t)BATCH*SEQ*CDIM];   // attention out, half
__device__ __half g_WhQkv[(size_t)C3*CDIM];        // W_qkv^T half
__device__ __half g_WhProj[(size_t)CDIM*CDIM];     // W_proj^T half

// ============================================================================
// helpers
// ============================================================================
__device__ __forceinline__ uint32_t smem_to_u32(const void* p) {
    uint32_t a;
    asm("{ .reg .u64 t; cvta.to.shared.u64 t, %1; cvt.u32.u64 %0, t; }" : "=r"(a) : "l"(p));
    return a;
}
__device__ __forceinline__ void cp_async16(uint32_t saddr, const void* g) {
    asm volatile("cp.async.cg.shared.global [%0], [%1], 16;" :: "r"(saddr), "l"(g));
}
#define CP_COMMIT() asm volatile("cp.async.commit_group;" ::: "memory")
#define CP_WAIT(n)  asm volatile("cp.async.wait_group %0;" :: "n"(n) : "memory")

__device__ __forceinline__ uint32_t pack_h2(float a, float b) {
    __half2 h = __floats2half2_rn(a, b);
    return *reinterpret_cast<uint32_t*>(&h);
}
__device__ __forceinline__ float2 unpack_h2(uint32_t u) {
    __half2 h = *reinterpret_cast<__half2*>(&u);
    return __half22float2(h);
}

// ldmatrix: 4 x (8x8 b16) tiles
__device__ __forceinline__ void ldsm_x4(
    uint32_t& r0, uint32_t& r1, uint32_t& r2, uint32_t& r3, uint32_t addr)
{
    asm volatile("ldmatrix.sync.aligned.m8n8.x4.shared.b16 {%0,%1,%2,%3}, [%4];"
                 : "=r"(r0), "=r"(r1), "=r"(r2), "=r"(r3) : "r"(addr));
}

// m16n8k16 fp16 mma, fp32 accumulate
__device__ __forceinline__ void mma_f16(
    float& c0, float& c1, float& c2, float& c3,
    uint32_t a0, uint32_t a1, uint32_t a2, uint32_t a3,
    uint32_t b0, uint32_t b1)
{
    asm volatile(
        "mma.sync.aligned.m16n8k16.row.col.f32.f16.f16.f32 "
        "{%0,%1,%2,%3}, {%4,%5,%6,%7}, {%8,%9}, {%0,%1,%2,%3};"
        : "+f"(c0), "+f"(c1), "+f"(c2), "+f"(c3)
        : "r"(a0), "r"(a1), "r"(a2), "r"(a3), "r"(b0), "r"(b1));
}

// ============================================================================
// convert fp32 -> fp16
// ============================================================================
__global__ __launch_bounds__(256) void convert_h_kernel(
    const float* __restrict__ in, __half* __restrict__ out, int n4)
{
    int i = blockIdx.x * blockDim.x + threadIdx.x;
    if (i < n4) {
        float4 v = ((const float4*)in)[i];
        uint2 o;
        o.x = pack_h2(v.x, v.y);
        o.y = pack_h2(v.z, v.w);
        ((uint2*)out)[i] = o;
    }
}

// ============================================================================
// Transpose + half convert: out[C][R] = half(in[R][C])
// ============================================================================
__global__ __launch_bounds__(256) void transpose_kh(
    const float* __restrict__ in, __half* __restrict__ out, int R, int C)
{
    __shared__ float t[32][33];
    int bx = blockIdx.x * 32, by = blockIdx.y * 32;
    int tx = threadIdx.x, ty = threadIdx.y;
    #pragma unroll
    for (int j = ty; j < 32; j += 8)
        t[j][tx] = in[(size_t)(by + j) * C + bx + tx];
    __syncthreads();
    #pragma unroll
    for (int j = ty; j < 32; j += 8)
        out[(size_t)(bx + j) * R + by + tx] = __float2half_rn(t[tx][j]);
}

// ============================================================================
// Shared GEMM config: 128x128 CTA tile, 256 threads = 8 warps (2M x 4N),
// warp tile 64x32, K chunk 64 halves, 2-stage cp.async, 2 CTAs/SM. (R13 best)
// ============================================================================
#define GKH 64
#define GSTRH 72                                  // halves per smem row
#define TILE_H (128 * GSTRH)                      // 9216 halves per tile
#define STAGE_H (2 * TILE_H)                      // A + B
#define GSMEM_BYTES (2 * STAGE_H * 2)             // 73728 B
#define EPI_STRIDE 132                            // fp32 epilogue smem stride

// ============================================================================
// Fused GEMM1: qkv = x @ W_qkv^T with RoPE/scale/half epilogue.
// N-tile (128) == one (type, head) slab. type 0->q(+rope, scale*log2e),
// 1->k(+rope), 2->v (transpose into vth). Epilogue stages fp32 tile via smem.
// ============================================================================
__global__ __launch_bounds__(256, 2) void gemm_qkv_fused(
    const __half* __restrict__ A, const __half* __restrict__ Bt,
    const float* __restrict__ cosp, const float* __restrict__ sinp,
    __half* __restrict__ qh, __half* __restrict__ kh, __half* __restrict__ vth)
{
    extern __shared__ __half smh[];
    const int tid = threadIdx.x;
    const int wid = tid >> 5;
    const int lid = tid & 31;
    const int wm  = wid & 1;
    const int wn  = wid >> 1;
    const int m0  = blockIdx.y * 128;
    const int n0  = blockIdx.x * 128;
    const int K   = CDIM;

    const uint32_t smem_u32 = smem_to_u32(smh);
    const int grp = lid >> 3, rowin = lid & 7;
    const int aoff_h = (rowin + 8 * (grp & 1)) * GSTRH + (grp >> 1) * 8;
    const int boff_h = (rowin + 8 * (grp >> 1)) * GSTRH + (grp & 1) * 8;
    const uint32_t aBase = smem_u32 + (uint32_t)(aoff_h + wm * 64 * GSTRH) * 2u;
    const uint32_t bBase = smem_u32 + (uint32_t)(TILE_H + boff_h + wn * 32 * GSTRH) * 2u;

    float acc[4][4][4];
    #pragma unroll
    for (int i = 0; i < 4; i++)
        #pragma unroll
        for (int j = 0; j < 4; j++)
            #pragma unroll
            for (int u = 0; u < 4; u++) acc[i][j][u] = 0.f;

    const int nchunk = K / GKH;

    auto issue = [&](int c, int s) {
        const __half* Ag = A  + (size_t)m0 * K + c * GKH;
        const __half* Bg = Bt + (size_t)n0 * K + c * GKH;
        uint32_t baseA = smem_u32 + (uint32_t)(s * STAGE_H) * 2u;
        uint32_t baseB = baseA + (uint32_t)TILE_H * 2u;
        #pragma unroll
        for (int i = 0; i < 4; i++) {
            int f   = tid + i * 256;
            int row = f >> 3;
            int q   = f & 7;
            uint32_t soff = (uint32_t)(row * GSTRH + q * 8) * 2u;
            cp_async16(baseA + soff, Ag + (size_t)row * K + q * 8);
            cp_async16(baseB + soff, Bg + (size_t)row * K + q * 8);
        }
    };

    issue(0, 0);
    CP_COMMIT();

    const int r4 = lid >> 2;
    const int c4 = lid & 3;

    for (int c = 0; c < nchunk; c++) {
        const int s = c & 1;
        if (c + 1 < nchunk) { issue(c + 1, s ^ 1); CP_COMMIT(); CP_WAIT(1); }
        else                { CP_WAIT(0); }
        __syncthreads();

        const uint32_t aA = aBase + (uint32_t)(s * STAGE_H) * 2u;
        const uint32_t bA = bBase + (uint32_t)(s * STAGE_H) * 2u;

        #pragma unroll
        for (int kk = 0; kk < 4; kk++) {
            uint32_t a[4][4], b[4][2];
            #pragma unroll
            for (int mt = 0; mt < 4; mt++)
                ldsm_x4(a[mt][0], a[mt][1], a[mt][2], a[mt][3],
                        aA + (uint32_t)((mt * 16 * GSTRH + kk * 16) * 2));
            #pragma unroll
            for (int np = 0; np < 2; np++)
                ldsm_x4(b[2*np][0], b[2*np][1], b[2*np+1][0], b[2*np+1][1],
                        bA + (uint32_t)((np * 16 * GSTRH + kk * 16) * 2));
            #pragma unroll
            for (int mt = 0; mt < 4; mt++)
                #pragma unroll
                for (int nt = 0; nt < 4; nt++)
                    mma_f16(acc[mt][nt][0], acc[mt][nt][1], acc[mt][nt][2], acc[mt][nt][3],
                            a[mt][0], a[mt][1], a[mt][2], a[mt][3],
                            b[nt][0], b[nt][1]);
        }
        __syncthreads();
    }

    // ---- fused epilogue: stage fp32 tile in smem (stages are dead now) ----
    float* sf = reinterpret_cast<float*>(smh);   // [128][EPI_STRIDE]
    #pragma unroll
    for (int mt = 0; mt < 4; mt++) {
        int row = wm * 64 + mt * 16 + r4;
        #pragma unroll
        for (int nt = 0; nt < 4; nt++) {
            int col = wn * 32 + nt * 8 + 2 * c4;
            sf[row * EPI_STRIDE + col]           = acc[mt][nt][0];
            sf[row * EPI_STRIDE + col + 1]       = acc[mt][nt][1];
            sf[(row + 8) * EPI_STRIDE + col]     = acc[mt][nt][2];
            sf[(row + 8) * EPI_STRIDE + col + 1] = acc[mt][nt][3];
        }
    }
    __syncthreads();

    const int type = n0 >> 11;           // 0=q, 1=k, 2=v
    const int h    = (n0 & 2047) >> 7;   // head
    const int b    = m0 >> 11;           // batch
    const int tbase = m0 & 2047;         // seq offset

    if (type < 2) {
        __half* outg = (type == 0) ? qh : kh;
        const float sc = (type == 0) ? (kScale * LOG2E) : 1.f;  // log2e folded into q
        #pragma unroll
        for (int i = 0; i < 16; i++) {
            int idx = tid + i * 256;       // 0..4095
            int tl  = idx >> 5;            // 0..127
            int dp  = (idx & 31) * 2;      // 0,2,..,62
            float2 x1 = *(const float2*)&sf[tl * EPI_STRIDE + dp];
            float2 x2 = *(const float2*)&sf[tl * EPI_STRIDE + dp + 64];
            int t = tbase + tl;
            float2 c1 = *(const float2*)(cosp + t * HDIM + dp);
            float2 s1 = *(const float2*)(sinp + t * HDIM + dp);
            float2 c2 = *(const float2*)(cosp + t * HDIM + dp + 64);
            float2 s2 = *(const float2*)(sinp + t * HDIM + dp + 64);
            __half* o = outg + ((size_t)(b * SEQ + t)) * CDIM + h * HDIM;
            *(uint32_t*)(o + dp) = pack_h2((x1.x * c1.x - x2.x * s1.x) * sc,
                                           (x1.y * c1.y - x2.y * s1.y) * sc);
            *(uint32_t*)(o + dp + 64) = pack_h2((x2.x * c2.x + x1.x * s2.x) * sc,
                                                (x2.y * c2.y + x1.y * s2.y) * sc);
        }
    } else {
        int d  = tid >> 1;
        int th = (tid & 1) * 64;
        __half* dst = vth + ((size_t)(b * NHEAD + h) * HDIM + d) * SEQ + tbase + th;
        #pragma unroll
        for (int j = 0; j < 16; j++) {
            float v0 = sf[(th + 4 * j + 0) * EPI_STRIDE + d];
            float v1 = sf[(th + 4 * j + 1) * EPI_STRIDE + d];
            float v2 = sf[(th + 4 * j + 2) * EPI_STRIDE + d];
            float v3 = sf[(th + 4 * j + 3) * EPI_STRIDE + d];
            uint2 o;
            o.x = pack_h2(v0, v1);
            o.y = pack_h2(v2, v3);
            *(uint2*)(dst + 4 * j) = o;
        }
    }
}

// ============================================================================
// Plain FP16 GEMM (proj): C[M,N](fp32) = A[M,K] @ Bt[N,K]^T
// ============================================================================
__global__ __launch_bounds__(256, 2) void gemm_f16mma(
    const __half* __restrict__ A, const __half* __restrict__ Bt,
    float* __restrict__ C, int M, int N, int K)
{
    extern __shared__ __half smh[];
    const int tid = threadIdx.x;
    const int wid = tid >> 5;
    const int lid = tid & 31;
    const int wm  = wid & 1;
    const int wn  = wid >> 1;
    const int m0  = blockIdx.y * 128;
    const int n0  = blockIdx.x * 128;

    const uint32_t smem_u32 = smem_to_u32(smh);
    const int grp = lid >> 3, rowin = lid & 7;
    const int aoff_h = (rowin + 8 * (grp & 1)) * GSTRH + (grp >> 1) * 8;
    const int boff_h = (rowin + 8 * (grp >> 1)) * GSTRH + (grp & 1) * 8;
    const uint32_t aBase = smem_u32 + (uint32_t)(aoff_h + wm * 64 * GSTRH) * 2u;
    const uint32_t bBase = smem_u32 + (uint32_t)(TILE_H + boff_h + wn * 32 * GSTRH) * 2u;

    float acc[4][4][4];
    #pragma unroll
    for (int i = 0; i < 4; i++)
        #pragma unroll
        for (int j = 0; j < 4; j++)
            #pragma unroll
            for (int u = 0; u < 4; u++) acc[i][j][u] = 0.f;

    const int nchunk = K / GKH;

    auto issue = [&](int c, int s) {
        const __half* Ag = A  + (size_t)m0 * K + c * GKH;
        const __half* Bg = Bt + (size_t)n0 * K + c * GKH;
        uint32_t baseA = smem_u32 + (uint32_t)(s * STAGE_H) * 2u;
        uint32_t baseB = baseA + (uint32_t)TILE_H * 2u;
        #pragma unroll
        for (int i = 0; i < 4; i++) {
            int f   = tid + i * 256;
            int row = f >> 3;
            int q   = f & 7;
            uint32_t soff = (uint32_t)(row * GSTRH + q * 8) * 2u;
            cp_async16(baseA + soff, Ag + (size_t)row * K + q * 8);
            cp_async16(baseB + soff, Bg + (size_t)row * K + q * 8);
        }
    };

    issue(0, 0);
    CP_COMMIT();

    const int r4 = lid >> 2;
    const int c4 = lid & 3;

    for (int c = 0; c < nchunk; c++) {
        const int s = c & 1;
        if (c + 1 < nchunk) { issue(c + 1, s ^ 1); CP_COMMIT(); CP_WAIT(1); }
        else                { CP_WAIT(0); }
        __syncthreads();

        const uint32_t aA = aBase + (uint32_t)(s * STAGE_H) * 2u;
        const uint32_t bA = bBase + (uint32_t)(s * STAGE_H) * 2u;

        #pragma unroll
        for (int kk = 0; kk < 4; kk++) {
            uint32_t a[4][4], b[4][2];
            #pragma unroll
            for (int mt = 0; mt < 4; mt++)
                ldsm_x4(a[mt][0], a[mt][1], a[mt][2], a[mt][3],
                        aA + (uint32_t)((mt * 16 * GSTRH + kk * 16) * 2));
            #pragma unroll
            for (int np = 0; np < 2; np++)
                ldsm_x4(b[2*np][0], b[2*np][1], b[2*np+1][0], b[2*np+1][1],
                        bA + (uint32_t)((np * 16 * GSTRH + kk * 16) * 2));
            #pragma unroll
            for (int mt = 0; mt < 4; mt++)
                #pragma unroll
                for (int nt = 0; nt < 4; nt++)
                    mma_f16(acc[mt][nt][0], acc[mt][nt][1], acc[mt][nt][2], acc[mt][nt][3],
                            a[mt][0], a[mt][1], a[mt][2], a[mt][3],
                            b[nt][0], b[nt][1]);
        }
        __syncthreads();
    }

    const int c2l = 2 * c4;
    #pragma unroll
    for (int mt = 0; mt < 4; mt++) {
        int row = m0 + wm * 64 + mt * 16 + r4;
        #pragma unroll
        for (int nt = 0; nt < 4; nt++) {
            int col = n0 + wn * 32 + nt * 8 + c2l;
            *(float2*)(C + (size_t)row * N + col) =
                make_float2(acc[mt][nt][0], acc[mt][nt][1]);
            *(float2*)(C + (size_t)(row + 8) * N + col) =
                make_float2(acc[mt][nt][2], acc[mt][nt][3]);
        }
    }
}

// ---------------------------------------------------------------------------
// Flash attention fp16: BM=128, BN=64, D=128, m16n8k16 mma, ldmatrix frags.
// 128 threads = 4 warps; warp w owns 32 q-rows (2 x 16-row sub-tiles).
// Softmax in exp2 domain (log2e pre-folded into q). K-frags hoisted: loaded
// once per kk and shared by both sub-tiles.
// ---------------------------------------------------------------------------
#define ABM 128
#define ABN 64
#define QSH 136
#define VSH 72
#define Q_HALVES (128*QSH)
#define K_HALVES (64*QSH)
#define V_HALVES (128*VSH)
#define STG_HALVES (K_HALVES + V_HALVES)
#define ATTN_SMEM_BYTES ((Q_HALVES + 2 * STG_HALVES) * 2)  // 106496

__global__ __launch_bounds__(128, 2) void attn_f16_kernel(
    const __half* __restrict__ qh, const __half* __restrict__ kh,
    const __half* __restrict__ vt, __half* __restrict__ y)
{
    extern __shared__ __half smh[];
    const int tid = threadIdx.x;
    const int wid = tid >> 5;
    const int lid = tid & 31;
    const int r4  = lid >> 2;
    const int c4  = lid & 3;
    const int h   = blockIdx.y;
    const int b   = blockIdx.z;
    const int t0  = blockIdx.x * ABM;
    const int mrow = wid * 32;

    const uint32_t smem_u32 = smem_to_u32(smh);

    const int grp = lid >> 3, rowin = lid & 7;
    const int qoff_h = (rowin + 8 * (grp & 1)) * QSH + (grp >> 1) * 8;
    const int koff_h = (rowin + 8 * (grp >> 1)) * QSH + (grp & 1) * 8;
    const int voff_h = (rowin + 8 * (grp >> 1)) * VSH + (grp & 1) * 8;
    const uint32_t qBase = smem_u32 + (uint32_t)(qoff_h + mrow * QSH) * 2u;

    const __half* Qg  = qh + ((size_t)b * SEQ) * CDIM + h * HDIM;
    const __half* Kg  = kh + ((size_t)b * SEQ) * CDIM + h * HDIM;
    const __half* Vtg = vt + (size_t)(b * NHEAD + h) * HDIM * SEQ;

    #pragma unroll
    for (int i = 0; i < 16; i++) {
        int f = tid + i * 128;
        int r = f >> 4, q = f & 15;
        cp_async16(smem_u32 + (uint32_t)(r * QSH + q * 8) * 2u,
                   Qg + (size_t)(t0 + r) * CDIM + q * 8);
    }
    CP_COMMIT();

    auto issue_tile = [&](int kt) {
        const int s = kt & 1;
        const int s0 = kt * ABN;
        uint32_t kbase = smem_u32 + (uint32_t)(Q_HALVES + s * STG_HALVES) * 2u;
        uint32_t vbase = kbase + (uint32_t)K_HALVES * 2u;
        #pragma unroll
        for (int i = 0; i < 8; i++) {
            int f = tid + i * 128;
            int r = f >> 4, q = f & 15;
            cp_async16(kbase + (uint32_t)(r * QSH + q * 8) * 2u,
                       Kg + (size_t)(s0 + r) * CDIM + q * 8);
        }
        #pragma unroll
        for (int i = 0; i < 8; i++) {
            int f = tid + i * 128;
            int d = f >> 3, q = f & 7;
            cp_async16(vbase + (uint32_t)(d * VSH + q * 8) * 2u,
                       Vtg + (size_t)d * SEQ + s0 + q * 8);
        }
    };

    issue_tile(0); CP_COMMIT();

    float Oa0[16][4], Oa1[16][4];
    #pragma unroll
    for (int nt = 0; nt < 16; nt++) {
        Oa0[nt][0] = Oa0[nt][1] = Oa0[nt][2] = Oa0[nt][3] = 0.f;
        Oa1[nt][0] = Oa1[nt][1] = Oa1[nt][2] = Oa1[nt][3] = 0.f;
    }
    float m_[2][2] = {{-1e30f, -1e30f}, {-1e30f, -1e30f}};
    float l_[2][2] = {{0.f, 0.f}, {0.f, 0.f}};

    const int NT = SEQ / ABN;   // 32
    for (int kt = 0; kt < NT; kt++) {
        __syncthreads();
        if (kt + 1 < NT) { issue_tile(kt + 1); CP_COMMIT(); }
        if (kt + 1 < NT) { CP_WAIT(1); } else { CP_WAIT(0); }
        __syncthreads();

        const uint32_t kA = smem_u32 +
            (uint32_t)(Q_HALVES + (kt & 1) * STG_HALVES + koff_h) * 2u;
        const uint32_t vA = smem_u32 +
            (uint32_t)(Q_HALVES + (kt & 1) * STG_HALVES + K_HALVES + voff_h) * 2u;

        // ---- S = Q @ K^T : K-frags hoisted, both sub-tiles per kk ----
        float P[2][8][4];
        #pragma unroll
        for (int mt = 0; mt < 2; mt++)
            #pragma unroll
            for (int nt = 0; nt < 8; nt++)
                P[mt][nt][0] = P[mt][nt][1] = P[mt][nt][2] = P[mt][nt][3] = 0.f;

        #pragma unroll
        for (int kk = 0; kk < 8; kk++) {
            uint32_t bb[8][2];
            #pragma unroll
            for (int np = 0; np < 4; np++)
                ldsm_x4(bb[2*np][0], bb[2*np][1], bb[2*np+1][0], bb[2*np+1][1],
                        kA + (uint32_t)((np * 16 * QSH + kk * 16) * 2));
            #pragma unroll
            for (int mt = 0; mt < 2; mt++) {
                uint32_t a0, a1, a2, a3;
                ldsm_x4(a0, a1, a2, a3,
                        qBase + (uint32_t)((mt * 16 * QSH + kk * 16) * 2));
                #pragma unroll
                for (int nt = 0; nt < 8; nt++)
                    mma_f16(P[mt][nt][0], P[mt][nt][1], P[mt][nt][2], P[mt][nt][3],
                            a0, a1, a2, a3, bb[nt][0], bb[nt][1]);
            }
        }

        // ---- online softmax in exp2 domain ----
        uint32_t ph[2][8][2];
        float cr[2][2];
        #pragma unroll
        for (int mt = 0; mt < 2; mt++) {
            float mx0 = -1e30f, mx1 = -1e30f;
            #pragma unroll
            for (int nt = 0; nt < 8; nt++) {
                mx0 = fmaxf(mx0, fmaxf(P[mt][nt][0], P[mt][nt][1]));
                mx1 = fmaxf(mx1, fmaxf(P[mt][nt][2], P[mt][nt][3]));
            }
            mx0 = fmaxf(mx0, __shfl_xor_sync(0xffffffffu, mx0, 1));
            mx0 = fmaxf(mx0, __shfl_xor_sync(0xffffffffu, mx0, 2));
            mx1 = fmaxf(mx1, __shfl_xor_sync(0xffffffffu, mx1, 1));
            mx1 = fmaxf(mx1, __shfl_xor_sync(0xffffffffu, mx1, 2));

            float mn0 = fmaxf(m_[mt][0], mx0), mn1 = fmaxf(m_[mt][1], mx1);
            cr[mt][0] = exp2f(m_[mt][0] - mn0);
            cr[mt][1] = exp2f(m_[mt][1] - mn1);
            m_[mt][0] = mn0; m_[mt][1] = mn1;

            float s0s = 0.f, s1s = 0.f;
            #pragma unroll
            for (int nt = 0; nt < 8; nt++) {
                float p0 = exp2f(P[mt][nt][0] - mn0);
                float p1 = exp2f(P[mt][nt][1] - mn0);
                float p2 = exp2f(P[mt][nt][2] - mn1);
                float p3 = exp2f(P[mt][nt][3] - mn1);
                ph[mt][nt][0] = pack_h2(p0, p1);
                ph[mt][nt][1] = pack_h2(p2, p3);
                float2 r01 = unpack_h2(ph[mt][nt][0]);
                float2 r23 = unpack_h2(ph[mt][nt][1]);
                s0s += r01.x + r01.y;
                s1s += r23.x + r23.y;
            }
            s0s += __shfl_xor_sync(0xffffffffu, s0s, 1);
            s0s += __shfl_xor_sync(0xffffffffu, s0s, 2);
            s1s += __shfl_xor_sync(0xffffffffu, s1s, 1);
            s1s += __shfl_xor_sync(0xffffffffu, s1s, 2);
            l_[mt][0] = l_[mt][0] * cr[mt][0] + s0s;
            l_[mt][1] = l_[mt][1] * cr[mt][1] + s1s;
        }

        #pragma unroll
        for (int nt = 0; nt < 16; nt++) {
            Oa0[nt][0] *= cr[0][0]; Oa0[nt][1] *= cr[0][0];
            Oa0[nt][2] *= cr[0][1]; Oa0[nt][3] *= cr[0][1];
            Oa1[nt][0] *= cr[1][0]; Oa1[nt][1] *= cr[1][0];
            Oa1[nt][2] *= cr[1][1]; Oa1[nt][3] *= cr[1][1];
        }

        // ---- O += P @ V : V frags shared by both sub-tiles ----
        #pragma unroll
        for (int kk = 0; kk < 4; kk++) {
            #pragma unroll
            for (int np = 0; np < 8; np++) {
                uint32_t b00, b01, b10, b11;
                ldsm_x4(b00, b01, b10, b11,
                        vA + (uint32_t)((np * 16 * VSH + kk * 16) * 2));
                mma_f16(Oa0[2*np][0], Oa0[2*np][1], Oa0[2*np][2], Oa0[2*np][3],
                        ph[0][2*kk][0], ph[0][2*kk][1], ph[0][2*kk+1][0], ph[0][2*kk+1][1],
                        b00, b01);
                mma_f16(Oa1[2*np][0], Oa1[2*np][1], Oa1[2*np][2], Oa1[2*np][3],
                        ph[1][2*kk][0], ph[1][2*kk][1], ph[1][2*kk+1][0], ph[1][2*kk+1][1],
                        b00, b01);
                mma_f16(Oa0[2*np+1][0], Oa0[2*np+1][1], Oa0[2*np+1][2], Oa0[2*np+1][3],
                        ph[0][2*kk][0], ph[0][2*kk][1], ph[0][2*kk+1][0], ph[0][2*kk+1][1],
                        b10, b11);
                mma_f16(Oa1[2*np+1][0], Oa1[2*np+1][1], Oa1[2*np+1][2], Oa1[2*np+1][3],
                        ph[1][2*kk][0], ph[1][2*kk][1], ph[1][2*kk+1][0], ph[1][2*kk+1][1],
                        b10, b11);
            }
        }
    }

    #pragma unroll
    for (int mt = 0; mt < 2; mt++) {
        float inv0 = 1.f / l_[mt][0], inv1 = 1.f / l_[mt][1];
        int row0 = t0 + mrow + mt * 16 + r4;
        int row1 = row0 + 8;
        __half* y0 = y + ((size_t)b * SEQ + row0) * CDIM + h * HDIM;
        __half* y1 = y + ((size_t)b * SEQ + row1) * CDIM + h * HDIM;
        #pragma unroll
        for (int nt = 0; nt < 16; nt++) {
            int col = nt * 8 + 2 * c4;
            if (mt == 0) {
                *(uint32_t*)(y0 + col) = pack_h2(Oa0[nt][0] * inv0, Oa0[nt][1] * inv0);
                *(uint32_t*)(y1 + col) = pack_h2(Oa0[nt][2] * inv1, Oa0[nt][3] * inv1);
            } else {
                *(uint32_t*)(y0 + col) = pack_h2(Oa1[nt][0] * inv0, Oa1[nt][1] * inv0);
                *(uint32_t*)(y1 + col) = pack_h2(Oa1[nt][2] * inv1, Oa1[nt][3] * inv1);
            }
        }
    }
}

// ---------------------------------------------------------------------------
extern "C" void kernel_launch(void* const* d_in, const int* in_sizes, int n_in,
                              void* d_out, int out_size)
{
    const float* x     = (const float*)d_in[0];
    const float* cosp  = (const float*)d_in[1];
    const float* sinp  = (const float*)d_in[2];
    const float* Wqkv  = (const float*)d_in[3];
    const float* Wproj = (const float*)d_in[4];
    float* out = (float*)d_out;

    __half *xh = nullptr, *qh = nullptr, *kh = nullptr, *vth = nullptr, *yh = nullptr;
    __half *WhQkv = nullptr, *WhProj = nullptr;
    cudaGetSymbolAddress((void**)&xh,     g_xh);
    cudaGetSymbolAddress((void**)&qh,     g_qh);
    cudaGetSymbolAddress((void**)&kh,     g_kh);
    cudaGetSymbolAddress((void**)&vth,    g_vth);
    cudaGetSymbolAddress((void**)&yh,     g_yh);
    cudaGetSymbolAddress((void**)&WhQkv,  g_WhQkv);
    cudaGetSymbolAddress((void**)&WhProj, g_WhProj);

    cudaFuncSetAttribute(attn_f16_kernel, cudaFuncAttributeMaxDynamicSharedMemorySize, ATTN_SMEM_BYTES);
    cudaFuncSetAttribute(gemm_f16mma,     cudaFuncAttributeMaxDynamicSharedMemorySize, GSMEM_BYTES);
    cudaFuncSetAttribute(gemm_qkv_fused,  cudaFuncAttributeMaxDynamicSharedMemorySize, GSMEM_BYTES);

    // 0) weights: transpose + half; x: half
    transpose_kh<<<dim3(C3 / 32,   CDIM / 32), dim3(32, 8)>>>(Wqkv,  WhQkv,  CDIM, C3);
    transpose_kh<<<dim3(CDIM / 32, CDIM / 32), dim3(32, 8)>>>(Wproj, WhProj, CDIM, CDIM);
    {
        int n4 = MROWS * CDIM / 4;
        convert_h_kernel<<<(n4 + 255) / 256, 256>>>(x, xh, n4);
    }

    // 1) fused: qkv GEMM + RoPE + scale*log2e + V-transpose -> qh, kh, vth
    gemm_qkv_fused<<<dim3(C3 / 128, MROWS / 128), 256, GSMEM_BYTES>>>(
        xh, WhQkv, cosp, sinp, qh, kh, vth);

    // 2) flash attention (fp16 mma + ldmatrix, exp2 softmax) -> yh
    {
        dim3 grid(SEQ / ABM, NHEAD, BATCH);
        attn_f16_kernel<<<grid, 128, ATTN_SMEM_BYTES>>>(qh, kh, vth, yh);
    }

    // 3) out = y @ W_proj  (fp16 mma + ldmatrix, fp32 out)
    gemm_f16mma<<<dim3(CDIM / 128, MROWS / 128), 256, GSMEM_BYTES>>>(
        yh, WhProj, out, MROWS, CDIM, CDIM);
}